// round 5
// baseline (speedup 1.0000x reference)
#include <cuda_runtime.h>
#include <math.h>

#define BB 2
#define SS 2048
#define EE 1024
#define HH 16
#define DD 64
#define MM (BB*SS)

// Scratch (static device globals; no runtime allocation)
__device__ float    g_q[BB*HH*SS*DD];      // raw fp32 q
__device__ float    g_k[BB*HH*SS*DD];      // tf32-valued fp32
__device__ float    g_v[BB*HH*SS*DD];      // tf32-valued fp32, pre-masked
__device__ float    g_vmean[BB*HH*DD];
__device__ float    g_active[HH];
// pre-split tf32-bit operand arrays
__device__ unsigned g_xh[MM*EE],      g_xl[MM*EE];        // x hi/lo
__device__ unsigned g_wh[3*EE*EE],    g_wl[3*EE*EE];      // qkv_w hi/lo
__device__ unsigned g_owh[EE*EE],     g_owl[EE*EE];       // out_w hi/lo
__device__ unsigned g_aoh[MM*EE],     g_aol[MM*EE];       // attn out hi/lo [B,S,H*D]

// ---------------------------------------------------------------------------
// helpers
// ---------------------------------------------------------------------------
__device__ __forceinline__ unsigned f2tf32(float x) {
    unsigned r;
    asm("cvt.rna.tf32.f32 %0, %1;" : "=r"(r) : "f"(x));
    return r;
}
__device__ __forceinline__ float uaf(unsigned u) { return __uint_as_float(u); }

__device__ __forceinline__ void mma_tf32(float c[4], const unsigned a[4], const unsigned b[2]) {
    asm volatile(
        "mma.sync.aligned.m16n8k8.row.col.f32.tf32.tf32.f32 "
        "{%0,%1,%2,%3}, {%4,%5,%6,%7}, {%8,%9}, {%0,%1,%2,%3};"
        : "+f"(c[0]), "+f"(c[1]), "+f"(c[2]), "+f"(c[3])
        : "r"(a[0]), "r"(a[1]), "r"(a[2]), "r"(a[3]),
          "r"(b[0]), "r"(b[1]));
}

__device__ __forceinline__ void cp16(unsigned dst, const void* src) {
    asm volatile("cp.async.cg.shared.global [%0], [%1], 16;\n" :: "r"(dst), "l"(src));
}
__device__ __forceinline__ void cp_commit() {
    asm volatile("cp.async.commit_group;\n");
}
__device__ __forceinline__ void cp_wait1() {
    asm volatile("cp.async.wait_group 1;\n");
}

// ---------------------------------------------------------------------------
// Head mask
// ---------------------------------------------------------------------------
__global__ void mask_kernel(const float* __restrict__ gates,
                            const float* __restrict__ imp,
                            const float* __restrict__ thr) {
    int h = threadIdx.x;
    if (h < HH) {
        float z  = gates[h] * imp[h];
        float gs = 1.0f / (1.0f + expf(-z));
        g_active[h] = (gs > thr[0]) ? 1.0f : 0.0f;
    }
}

// ---------------------------------------------------------------------------
// hi/lo tf32 split: hi = rna(x), lo = rna(x - hi)
// ---------------------------------------------------------------------------
__global__ void split_kernel(const float* __restrict__ src,
                             unsigned* __restrict__ hi,
                             unsigned* __restrict__ lo, int n4) {
    int i = blockIdx.x * blockDim.x + threadIdx.x;
    if (i < n4) {
        float4 v = ((const float4*)src)[i];
        uint4 h, l;
        h.x = f2tf32(v.x); l.x = f2tf32(v.x - uaf(h.x));
        h.y = f2tf32(v.y); l.y = f2tf32(v.y - uaf(h.y));
        h.z = f2tf32(v.z); l.z = f2tf32(v.z - uaf(h.z));
        h.w = f2tf32(v.w); l.w = f2tf32(v.w - uaf(h.w));
        ((uint4*)hi)[i] = h;
        ((uint4*)lo)[i] = l;
    }
}

// ---------------------------------------------------------------------------
// Pre-split TF32 GEMM: C[m,n] = sum_k A[m,k]*B[n,k] + bias[n]
// Operands arrive as tf32-bit hi/lo arrays -> mainloop is copy + mma only.
// BM=BN=128, BK=16, 256 threads (8 warps 2x4), warp tile 64x32.
// Terms: Ah*Bh + Al*Bh (+ Ah*Bl if SB).
// MODE 0: qkv scatter epilogue (k,v stored tf32-rounded). MODE 1: row-major.
// ---------------------------------------------------------------------------
template <int MODE, bool SB>
__global__ void __launch_bounds__(256, 2) gemm_ps_kernel(
    const unsigned* __restrict__ Ahg, const unsigned* __restrict__ Alg,
    const unsigned* __restrict__ Bhg, const unsigned* __restrict__ Blg,
    const float* __restrict__ bias, float* __restrict__ Y) {
    __shared__ unsigned Ah[128][20];
    __shared__ unsigned Al[128][20];
    __shared__ unsigned Bh[128][20];
    __shared__ unsigned Bl[128][20];

    const int m0 = blockIdx.y * 128;
    const int n0 = blockIdx.x * 128;

    if (MODE == 0) {
        const int hA = (n0 & 1023) >> 6;
        if (g_active[hA] == 0.0f && g_active[hA + 1] == 0.0f) return;
    }

    const int tid  = threadIdx.x;
    const int lane = tid & 31;
    const int warp = tid >> 5;
    const int wm = (warp >> 2) * 64;
    const int wn = (warp & 3) * 32;
    const int grp = lane >> 2;
    const int tig = lane & 3;

    const int grow = tid >> 1;          // 0..127
    const int gk   = (tid & 1) * 8;     // 0 or 8
    const unsigned* Aph = Ahg + (size_t)(m0 + grow) * EE + gk;
    const unsigned* Apl = Alg + (size_t)(m0 + grow) * EE + gk;
    const unsigned* Bph = Bhg + (size_t)(n0 + grow) * EE + gk;
    const unsigned* Bpl = Blg + (size_t)(n0 + grow) * EE + gk;

    float acc[4][4][4];
#pragma unroll
    for (int i = 0; i < 4; i++)
#pragma unroll
        for (int j = 0; j < 4; j++)
#pragma unroll
            for (int r = 0; r < 4; r++) acc[i][j][r] = 0.f;

    uint4 pah[2], pal[2], pbh[2], pbl[2];
#pragma unroll
    for (int i = 0; i < 2; i++) {
        pah[i] = *(const uint4*)(Aph + 4 * i);
        pal[i] = *(const uint4*)(Apl + 4 * i);
        pbh[i] = *(const uint4*)(Bph + 4 * i);
        if (SB) pbl[i] = *(const uint4*)(Bpl + 4 * i);
    }

    const int NT = EE / 16;  // 64 k-tiles
    for (int kt = 0; kt < NT; kt++) {
#pragma unroll
        for (int i = 0; i < 2; i++) {
            *(uint4*)&Ah[grow][gk + 4 * i] = pah[i];
            *(uint4*)&Al[grow][gk + 4 * i] = pal[i];
            *(uint4*)&Bh[grow][gk + 4 * i] = pbh[i];
            if (SB) *(uint4*)&Bl[grow][gk + 4 * i] = pbl[i];
        }
        __syncthreads();

        if (kt + 1 < NT) {
            const int o = (kt + 1) * 16;
#pragma unroll
            for (int i = 0; i < 2; i++) {
                pah[i] = *(const uint4*)(Aph + o + 4 * i);
                pal[i] = *(const uint4*)(Apl + o + 4 * i);
                pbh[i] = *(const uint4*)(Bph + o + 4 * i);
                if (SB) pbl[i] = *(const uint4*)(Bpl + o + 4 * i);
            }
        }

#pragma unroll
        for (int ks = 0; ks < 2; ks++) {
            const int kq = ks * 8 + tig;
            unsigned ah[4][4], al[4][4];
#pragma unroll
            for (int mi = 0; mi < 4; mi++) {
                const int mr = wm + mi * 16 + grp;
                ah[mi][0] = Ah[mr][kq];     ah[mi][1] = Ah[mr + 8][kq];
                ah[mi][2] = Ah[mr][kq + 4]; ah[mi][3] = Ah[mr + 8][kq + 4];
                al[mi][0] = Al[mr][kq];     al[mi][1] = Al[mr + 8][kq];
                al[mi][2] = Al[mr][kq + 4]; al[mi][3] = Al[mr + 8][kq + 4];
            }
            unsigned bh[4][2], bl[4][2];
#pragma unroll
            for (int ni = 0; ni < 4; ni++) {
                const int nr = wn + ni * 8 + grp;
                bh[ni][0] = Bh[nr][kq]; bh[ni][1] = Bh[nr][kq + 4];
                if (SB) { bl[ni][0] = Bl[nr][kq]; bl[ni][1] = Bl[nr][kq + 4]; }
            }
#pragma unroll
            for (int mi = 0; mi < 4; mi++)
#pragma unroll
                for (int ni = 0; ni < 4; ni++) {
                    mma_tf32(acc[mi][ni], ah[mi], bh[ni]);
                    mma_tf32(acc[mi][ni], al[mi], bh[ni]);
                    if (SB) mma_tf32(acc[mi][ni], ah[mi], bl[ni]);
                }
        }
        __syncthreads();
    }

    // epilogue
#pragma unroll
    for (int mi = 0; mi < 4; mi++) {
        const int rbase = m0 + wm + mi * 16 + grp;
#pragma unroll
        for (int ni = 0; ni < 4; ni++) {
            const int j = n0 + wn + ni * 8 + 2 * tig;
            const float b0 = bias[j], b1 = bias[j + 1];
#pragma unroll
            for (int rh = 0; rh < 2; rh++) {
                const int m = rbase + rh * 8;
                const float v0 = acc[mi][ni][rh * 2 + 0] + b0;
                const float v1 = acc[mi][ni][rh * 2 + 1] + b1;
                if (MODE == 1) {
                    float2 o; o.x = v0; o.y = v1;
                    *(float2*)(Y + (size_t)m * EE + j) = o;
                } else {
                    const int cc  = j >> 10;
                    const int rem = j & 1023;
                    const int h = rem >> 6, d = rem & 63;
                    const int bI = m >> 11;
                    const int s  = m & (SS - 1);
                    const size_t off = (((size_t)(bI * HH + h)) * SS + s) * DD + d;
                    float2 o;
                    if (cc == 0) {
                        o.x = v0; o.y = v1;                 // q raw
                        *(float2*)(g_q + off) = o;
                    } else if (cc == 1) {
                        o.x = uaf(f2tf32(v0));              // k pre-rounded
                        o.y = uaf(f2tf32(v1));
                        *(float2*)(g_k + off) = o;
                    } else {
                        const float am = g_active[h];
                        o.x = uaf(f2tf32(v0 * am));         // v masked + rounded
                        o.y = uaf(f2tf32(v1 * am));
                        *(float2*)(g_v + off) = o;
                    }
                }
            }
        }
    }
}

// ---------------------------------------------------------------------------
// vmean[b,h,d] = mean_s v[b,h,s,d]  (float4 loads, skip inactive heads)
// ---------------------------------------------------------------------------
__global__ void vmean_kernel() {
    const int bh = blockIdx.x;
    if (g_active[bh & (HH - 1)] == 0.0f) return;
    const int d4    = (threadIdx.x & 15) * 4;
    const int chunk = threadIdx.x >> 4;
    const size_t base = (size_t)bh * SS * DD;
    float4 sum = {0.f, 0.f, 0.f, 0.f};
    for (int s = chunk * 128; s < (chunk + 1) * 128; s++) {
        float4 t = *(const float4*)(g_v + base + (size_t)s * DD + d4);
        sum.x += t.x; sum.y += t.y; sum.z += t.z; sum.w += t.w;
    }
    __shared__ float4 red[256];
    red[threadIdx.x] = sum;
    __syncthreads();
    if (chunk == 0) {
        float4 t = {0.f, 0.f, 0.f, 0.f};
#pragma unroll
        for (int c = 0; c < 16; c++) {
            float4 r = red[c * 16 + (threadIdx.x & 15)];
            t.x += r.x; t.y += r.y; t.z += r.z; t.w += r.w;
        }
        const float inv = 1.0f / SS;
        t.x *= inv; t.y *= inv; t.z *= inv; t.w *= inv;
        *(float4*)(g_vmean + bh * DD + d4) = t;
    }
}

// ---------------------------------------------------------------------------
// Tensor-core flash attention, v3:
//  - K/V arrive tf32-rounded from the QKV epilogue -> B-frag loads are pure LDS
//  - P rounded once at exp time, reused in-register as PV A-frag (permuted k)
//  - Q raw in 32 regs, hi/lo split inline per ks (amortized over 8 nt)
//  - 2 CTAs/SM via __launch_bounds__(256,2)
// ---------------------------------------------------------------------------
#define KSTR 68
#define VSTR 68
#define TKW  (64 * KSTR)
#define TVW  (64 * VSTR)
#define BUFW (TKW + TVW)
#define SMEM_ATTN (2 * BUFW * 4)      // 69632 B

__global__ void __launch_bounds__(256, 2) attn_tc_kernel() {
    extern __shared__ float sh[];

    const int tid  = threadIdx.x;
    const int lane = tid & 31;
    const int warp = tid >> 5;
    const int grp  = lane >> 4 ? 0 : 0; // placeholder to keep regs tight (unused)
    const int g8   = lane >> 2;         // 0..7
    const int tig  = lane & 3;
    const int wr   = warp * 16;

    const int b = blockIdx.z, h = blockIdx.y;
    const int q0 = blockIdx.x * 128;
    const size_t bh = (size_t)(b * HH + h) * SS * DD;

    if (g_active[h] == 0.0f) {
        const uint4 z = {0u, 0u, 0u, 0u};
        for (int i = tid; i < 128 * 16; i += 256) {
            const int r = i >> 4, c = (i & 15) * 4;
            const size_t off = ((size_t)(b * SS + q0 + r) * HH + h) * DD + c;
            *(uint4*)(g_aoh + off) = z;
            *(uint4*)(g_aol + off) = z;
        }
        return;
    }

    const unsigned sbase = (unsigned)__cvta_generic_to_shared(sh);
    const int ldr = tid >> 2;
    const int ldc = (tid & 3) * 16;

    // Q raw fragments (32 regs)
    float qraw[8][4];
#pragma unroll
    for (int kt = 0; kt < 8; kt++) {
        const int r0 = q0 + wr + g8;
        const int c0 = kt * 8 + tig;
        qraw[kt][0] = g_q[bh + (size_t)r0 * DD + c0];
        qraw[kt][1] = g_q[bh + (size_t)(r0 + 8) * DD + c0];
        qraw[kt][2] = g_q[bh + (size_t)r0 * DD + c0 + 4];
        qraw[kt][3] = g_q[bh + (size_t)(r0 + 8) * DD + c0 + 4];
    }

    float o[8][4];
#pragma unroll
    for (int i = 0; i < 8; i++)
#pragma unroll
        for (int j = 0; j < 4; j++) o[i][j] = 0.f;
    float m0 = -1e30f, m1 = -1e30f, l0 = 0.f, l1 = 0.f;

    auto issue_tile = [&](int kvt, int buf) {
        const float* kp = g_k + bh + (size_t)(kvt * 64 + ldr) * DD + ldc;
        const float* vp = g_v + bh + (size_t)(kvt * 64 + ldr) * DD + ldc;
        const unsigned kd = sbase + (buf * BUFW + ldr * KSTR + ldc) * 4;
        const unsigned vd = sbase + (buf * BUFW + TKW + ldr * VSTR + ldc) * 4;
#pragma unroll
        for (int c = 0; c < 4; c++) {
            cp16(kd + 16 * c, kp + 4 * c);
            cp16(vd + 16 * c, vp + 4 * c);
        }
    };

    issue_tile(0, 0);
    cp_commit();

    const int NTILE = SS / 64;  // 32
    for (int t = 0; t < NTILE; t++) {
        const int buf = t & 1;
        if (t + 1 < NTILE) issue_tile(t + 1, buf ^ 1);
        cp_commit();
        cp_wait1();
        __syncthreads();

        const unsigned* Ku = (const unsigned*)(sh + buf * BUFW);
        const unsigned* Vu = Ku + TKW;

        // ---- QK: 2-term split, Q split inline per ks ----
        float c[8][4];
#pragma unroll
        for (int i = 0; i < 8; i++)
#pragma unroll
            for (int j = 0; j < 4; j++) c[i][j] = 0.f;
#pragma unroll
        for (int ks = 0; ks < 8; ks++) {
            unsigned ah[4], al[4];
#pragma unroll
            for (int e = 0; e < 4; e++) {
                ah[e] = f2tf32(qraw[ks][e]);
                al[e] = f2tf32(qraw[ks][e] - uaf(ah[e]));
            }
            const int kq = ks * 8 + tig;
#pragma unroll
            for (int nt = 0; nt < 8; nt++) {
                unsigned bb[2];
                bb[0] = Ku[(nt * 8 + g8) * KSTR + kq];
                bb[1] = Ku[(nt * 8 + g8) * KSTR + kq + 4];
                mma_tf32(c[nt], ah, bb);
                mma_tf32(c[nt], al, bb);
            }
        }

        // ---- online softmax; P rounded in-place into c ----
        float mx0 = c[0][0], mx1 = c[0][2];
#pragma unroll
        for (int nt = 0; nt < 8; nt++) {
            mx0 = fmaxf(mx0, fmaxf(c[nt][0], c[nt][1]));
            mx1 = fmaxf(mx1, fmaxf(c[nt][2], c[nt][3]));
        }
        mx0 = fmaxf(mx0, __shfl_xor_sync(0xffffffffu, mx0, 1));
        mx0 = fmaxf(mx0, __shfl_xor_sync(0xffffffffu, mx0, 2));
        mx1 = fmaxf(mx1, __shfl_xor_sync(0xffffffffu, mx1, 1));
        mx1 = fmaxf(mx1, __shfl_xor_sync(0xffffffffu, mx1, 2));
        const float mn0 = fmaxf(m0, mx0);
        const float mn1 = fmaxf(m1, mx1);
        const float sc0 = __expf(m0 - mn0);
        const float sc1 = __expf(m1 - mn1);
        m0 = mn0; m1 = mn1;
#pragma unroll
        for (int dt = 0; dt < 8; dt++) {
            o[dt][0] *= sc0; o[dt][1] *= sc0;
            o[dt][2] *= sc1; o[dt][3] *= sc1;
        }
        float s0 = 0.f, s1 = 0.f;
#pragma unroll
        for (int nt = 0; nt < 8; nt++) {
            const float p00 = uaf(f2tf32(__expf(c[nt][0] - m0)));
            const float p01 = uaf(f2tf32(__expf(c[nt][1] - m0)));
            const float p10 = uaf(f2tf32(__expf(c[nt][2] - m1)));
            const float p11 = uaf(f2tf32(__expf(c[nt][3] - m1)));
            s0 += p00 + p01;
            s1 += p10 + p11;
            c[nt][0] = p00; c[nt][1] = p01;
            c[nt][2] = p10; c[nt][3] = p11;
        }
        s0 += __shfl_xor_sync(0xffffffffu, s0, 1);
        s0 += __shfl_xor_sync(0xffffffffu, s0, 2);
        s1 += __shfl_xor_sync(0xffffffffu, s1, 1);
        s1 += __shfl_xor_sync(0xffffffffu, s1, 2);
        l0 = l0 * sc0 + s0;
        l1 = l1 * sc1 + s1;

        // ---- PV, permuted k-slots; A-frag = own accumulator bits ----
#pragma unroll
        for (int ks = 0; ks < 8; ks++) {
            unsigned aa[4] = {__float_as_uint(c[ks][0]), __float_as_uint(c[ks][2]),
                              __float_as_uint(c[ks][1]), __float_as_uint(c[ks][3])};
            const int vr0 = (ks * 8 + 2 * tig) * VSTR;
#pragma unroll
            for (int dt = 0; dt < 8; dt++) {
                unsigned bb[2];
                bb[0] = Vu[vr0 + dt * 8 + g8];
                bb[1] = Vu[vr0 + VSTR + dt * 8 + g8];
                mma_tf32(o[dt], aa, bb);
            }
        }
        __syncthreads();
    }

    // epilogue: normalize, add vmean, emit hi/lo tf32 bits for out-GEMM
    const float inv0 = 1.0f / l0;
    const float inv1 = 1.0f / l1;
    const int r0 = q0 + wr + g8;
    const size_t ob0 = ((size_t)(b * SS + r0) * HH + h) * DD;
    const size_t ob1 = ((size_t)(b * SS + r0 + 8) * HH + h) * DD;
    const float* vm = g_vmean + (size_t)(b * HH + h) * DD;
#pragma unroll
    for (int dt = 0; dt < 8; dt++) {
        const int col = dt * 8 + 2 * tig;
        const float v0 = vm[col], v1 = vm[col + 1];
        float f00 = o[dt][0] * inv0 + v0, f01 = o[dt][1] * inv0 + v1;
        float f10 = o[dt][2] * inv1 + v0, f11 = o[dt][3] * inv1 + v1;
        uint2 h0, h1, lo0, lo1;
        h0.x = f2tf32(f00); lo0.x = f2tf32(f00 - uaf(h0.x));
        h0.y = f2tf32(f01); lo0.y = f2tf32(f01 - uaf(h0.y));
        h1.x = f2tf32(f10); lo1.x = f2tf32(f10 - uaf(h1.x));
        h1.y = f2tf32(f11); lo1.y = f2tf32(f11 - uaf(h1.y));
        *(uint2*)(g_aoh + ob0 + col) = h0;
        *(uint2*)(g_aol + ob0 + col) = lo0;
        *(uint2*)(g_aoh + ob1 + col) = h1;
        *(uint2*)(g_aol + ob1 + col) = lo1;
    }
}

// ---------------------------------------------------------------------------
extern "C" void kernel_launch(void* const* d_in, const int* in_sizes, int n_in,
                              void* d_out, int out_size) {
    const float* x      = (const float*)d_in[0];
    const float* qkv_w  = (const float*)d_in[1];
    const float* qkv_b  = (const float*)d_in[2];
    const float* out_w  = (const float*)d_in[3];
    const float* out_b  = (const float*)d_in[4];
    const float* gates  = (const float*)d_in[5];
    const float* imp    = (const float*)d_in[6];
    const float* thr    = (const float*)d_in[7];
    float* out = (float*)d_out;

    static bool attr_set = false;
    if (!attr_set) {
        cudaFuncSetAttribute(attn_tc_kernel,
                             cudaFuncAttributeMaxDynamicSharedMemorySize, SMEM_ATTN);
        attr_set = true;
    }

    unsigned *xh, *xl, *wh, *wl, *owh, *owl, *aoh, *aol;
    cudaGetSymbolAddress((void**)&xh,  g_xh);
    cudaGetSymbolAddress((void**)&xl,  g_xl);
    cudaGetSymbolAddress((void**)&wh,  g_wh);
    cudaGetSymbolAddress((void**)&wl,  g_wl);
    cudaGetSymbolAddress((void**)&owh, g_owh);
    cudaGetSymbolAddress((void**)&owl, g_owl);
    cudaGetSymbolAddress((void**)&aoh, g_aoh);
    cudaGetSymbolAddress((void**)&aol, g_aol);

    mask_kernel<<<1, 32>>>(gates, imp, thr);

    // operand pre-splits (bandwidth-bound, ~15 us total)
    split_kernel<<<(MM*EE/4 + 255)/256, 256>>>(x, xh, xl, MM*EE/4);
    split_kernel<<<(3*EE*EE/4 + 255)/256, 256>>>(qkv_w, wh, wl, 3*EE*EE/4);
    split_kernel<<<(EE*EE/4 + 255)/256, 256>>>(out_w, owh, owl, EE*EE/4);

    // QKV projection (3-term)
    {
        dim3 g(3 * EE / 128, MM / 128);      // 24 x 32
        gemm_ps_kernel<0, true><<<g, 256>>>(xh, xl, wh, wl, qkv_b, nullptr);
    }

    vmean_kernel<<<BB * HH, 256>>>();

    // Attention
    {
        dim3 g(SS / 128, HH, BB);            // 16 x 16 x 2
        attn_tc_kernel<<<g, 256, SMEM_ATTN>>>();
    }

    // Output projection (2-term, A=ao pre-split by attn epilogue)
    {
        dim3 g(EE / 128, MM / 128);          // 8 x 32
        gemm_ps_kernel<1, false><<<g, 256>>>(aoh, aol, owh, owh, out_b, out);
    }
}

// round 6
// speedup vs baseline: 1.2116x; 1.2116x over previous
#include <cuda_runtime.h>
#include <math.h>

#define BB 2
#define SS 2048
#define EE 1024
#define HH 16
#define DD 64
#define MM (BB*SS)

// Scratch (static device globals; no runtime allocation)
__device__ float g_q[BB*HH*SS*DD];      // raw fp32 q   [B,H,S,D]
__device__ float g_k[BB*HH*SS*DD];      // tf32-valued fp32
__device__ float g_v[BB*HH*SS*DD];      // tf32-valued fp32, pre-masked
__device__ float g_vmean[BB*HH*DD];
__device__ float g_ao[BB*SS*EE];        // fp32 attn out, [B,S,H,D] == [B,S,E]
__device__ float g_active[HH];

// ---------------------------------------------------------------------------
// helpers
// ---------------------------------------------------------------------------
__device__ __forceinline__ unsigned f2tf32(float x) {
    unsigned r;
    asm("cvt.rna.tf32.f32 %0, %1;" : "=r"(r) : "f"(x));
    return r;
}
__device__ __forceinline__ float uaf(unsigned u) { return __uint_as_float(u); }

__device__ __forceinline__ void mma_tf32(float c[4], const unsigned a[4], const unsigned b[2]) {
    asm volatile(
        "mma.sync.aligned.m16n8k8.row.col.f32.tf32.tf32.f32 "
        "{%0,%1,%2,%3}, {%4,%5,%6,%7}, {%8,%9}, {%0,%1,%2,%3};"
        : "+f"(c[0]), "+f"(c[1]), "+f"(c[2]), "+f"(c[3])
        : "r"(a[0]), "r"(a[1]), "r"(a[2]), "r"(a[3]),
          "r"(b[0]), "r"(b[1]));
}

__device__ __forceinline__ void cp16(unsigned dst, const void* src) {
    asm volatile("cp.async.cg.shared.global [%0], [%1], 16;\n" :: "r"(dst), "l"(src));
}
__device__ __forceinline__ void cp_commit() {
    asm volatile("cp.async.commit_group;\n");
}
__device__ __forceinline__ void cp_wait1() {
    asm volatile("cp.async.wait_group 1;\n");
}

// ---------------------------------------------------------------------------
// Head mask
// ---------------------------------------------------------------------------
__global__ void mask_kernel(const float* __restrict__ gates,
                            const float* __restrict__ imp,
                            const float* __restrict__ thr) {
    int h = threadIdx.x;
    if (h < HH) {
        float z  = gates[h] * imp[h];
        float gs = 1.0f / (1.0f + expf(-z));
        g_active[h] = (gs > thr[0]) ? 1.0f : 0.0f;
    }
}

// ---------------------------------------------------------------------------
// Split-TF32 GEMM (round-4 form: single fp32 read, inline split at smem store)
// C[m,n] = sum_k A[m,k]*B[n,k] + bias[n]
// BM=BN=128, BK=16, 256 threads (8 warps 2x4), warp tile 64x32.
// Terms: Ah*Bh + Al*Bh (+ Ah*Bl if SB).
// MODE 0: qkv scatter epilogue (k,v stored tf32-pre-rounded). MODE 1: row-major.
// ---------------------------------------------------------------------------
template <int MODE, bool SB>
__global__ void __launch_bounds__(256, 2) gemm_split_kernel(
    const float* __restrict__ A,
    const float* __restrict__ B,
    const float* __restrict__ bias,
    float* __restrict__ Y) {
    __shared__ unsigned Ah[128][20];
    __shared__ unsigned Al[128][20];
    __shared__ unsigned Bh[128][20];
    __shared__ unsigned Bl[128][20];

    const int m0 = blockIdx.y * 128;
    const int n0 = blockIdx.x * 128;

    if (MODE == 0) {
        // block covers exactly 2 heads of one of q/k/v; skip if both inactive
        const int hA = (n0 & 1023) >> 6;
        if (g_active[hA] == 0.0f && g_active[hA + 1] == 0.0f) return;
    }

    const int tid  = threadIdx.x;
    const int lane = tid & 31;
    const int warp = tid >> 5;
    const int wm = (warp >> 2) * 64;
    const int wn = (warp & 3) * 32;
    const int grp = lane >> 2;
    const int tig = lane & 3;

    const int grow = tid >> 1;          // 0..127
    const int gk   = (tid & 1) * 8;     // 0 or 8
    const float* Aptr = A + (size_t)(m0 + grow) * EE + gk;
    const float* Bptr = B + (size_t)(n0 + grow) * EE + gk;

    float acc[4][4][4];
#pragma unroll
    for (int i = 0; i < 4; i++)
#pragma unroll
        for (int j = 0; j < 4; j++)
#pragma unroll
            for (int r = 0; r < 4; r++) acc[i][j][r] = 0.f;

    float4 pa[2], pb[2];
#pragma unroll
    for (int i = 0; i < 2; i++) {
        pa[i] = *(const float4*)(Aptr + 4 * i);
        pb[i] = *(const float4*)(Bptr + 4 * i);
    }

    const int NT = EE / 16;  // 64 k-tiles
    for (int kt = 0; kt < NT; kt++) {
#pragma unroll
        for (int i = 0; i < 2; i++) {
            float av[4] = {pa[i].x, pa[i].y, pa[i].z, pa[i].w};
            float bv[4] = {pb[i].x, pb[i].y, pb[i].z, pb[i].w};
            uint4 ah, al, bh, bl;
            unsigned* ahp = &ah.x; unsigned* alp = &al.x;
            unsigned* bhp = &bh.x; unsigned* blp = &bl.x;
#pragma unroll
            for (int c = 0; c < 4; c++) {
                unsigned h = f2tf32(av[c]);
                ahp[c] = h; alp[c] = f2tf32(av[c] - uaf(h));
                unsigned hb = f2tf32(bv[c]);
                bhp[c] = hb; blp[c] = f2tf32(bv[c] - uaf(hb));
            }
            *(uint4*)&Ah[grow][gk + 4 * i] = ah;
            *(uint4*)&Al[grow][gk + 4 * i] = al;
            *(uint4*)&Bh[grow][gk + 4 * i] = bh;
            if (SB) *(uint4*)&Bl[grow][gk + 4 * i] = bl;
        }
        __syncthreads();

        if (kt + 1 < NT) {
            const float* An = Aptr + (kt + 1) * 16;
            const float* Bn = Bptr + (kt + 1) * 16;
#pragma unroll
            for (int i = 0; i < 2; i++) {
                pa[i] = *(const float4*)(An + 4 * i);
                pb[i] = *(const float4*)(Bn + 4 * i);
            }
        }

#pragma unroll
        for (int ks = 0; ks < 2; ks++) {
            const int kq = ks * 8 + tig;
            unsigned ah[4][4], al[4][4];
#pragma unroll
            for (int mi = 0; mi < 4; mi++) {
                const int mr = wm + mi * 16 + grp;
                ah[mi][0] = Ah[mr][kq];     ah[mi][1] = Ah[mr + 8][kq];
                ah[mi][2] = Ah[mr][kq + 4]; ah[mi][3] = Ah[mr + 8][kq + 4];
                al[mi][0] = Al[mr][kq];     al[mi][1] = Al[mr + 8][kq];
                al[mi][2] = Al[mr][kq + 4]; al[mi][3] = Al[mr + 8][kq + 4];
            }
            unsigned bh[4][2], bl[4][2];
#pragma unroll
            for (int ni = 0; ni < 4; ni++) {
                const int nr = wn + ni * 8 + grp;
                bh[ni][0] = Bh[nr][kq]; bh[ni][1] = Bh[nr][kq + 4];
                if (SB) { bl[ni][0] = Bl[nr][kq]; bl[ni][1] = Bl[nr][kq + 4]; }
            }
#pragma unroll
            for (int mi = 0; mi < 4; mi++)
#pragma unroll
                for (int ni = 0; ni < 4; ni++) {
                    mma_tf32(acc[mi][ni], ah[mi], bh[ni]);
                    mma_tf32(acc[mi][ni], al[mi], bh[ni]);
                    if (SB) mma_tf32(acc[mi][ni], ah[mi], bl[ni]);
                }
        }
        __syncthreads();
    }

    // epilogue
#pragma unroll
    for (int mi = 0; mi < 4; mi++) {
        const int rbase = m0 + wm + mi * 16 + grp;
#pragma unroll
        for (int ni = 0; ni < 4; ni++) {
            const int j = n0 + wn + ni * 8 + 2 * tig;
            const float b0 = bias[j], b1 = bias[j + 1];
#pragma unroll
            for (int rh = 0; rh < 2; rh++) {
                const int m = rbase + rh * 8;
                const float v0 = acc[mi][ni][rh * 2 + 0] + b0;
                const float v1 = acc[mi][ni][rh * 2 + 1] + b1;
                if (MODE == 1) {
                    float2 o; o.x = v0; o.y = v1;
                    *(float2*)(Y + (size_t)m * EE + j) = o;
                } else {
                    const int cc  = j >> 10;
                    const int rem = j & 1023;
                    const int h = rem >> 6, d = rem & 63;
                    const int bI = m >> 11;
                    const int s  = m & (SS - 1);
                    const size_t off = (((size_t)(bI * HH + h)) * SS + s) * DD + d;
                    float2 o;
                    if (cc == 0) {
                        o.x = v0; o.y = v1;                 // q raw
                        *(float2*)(g_q + off) = o;
                    } else if (cc == 1) {
                        o.x = uaf(f2tf32(v0));              // k pre-rounded
                        o.y = uaf(f2tf32(v1));
                        *(float2*)(g_k + off) = o;
                    } else {
                        const float am = g_active[h];
                        o.x = uaf(f2tf32(v0 * am));         // v masked + rounded
                        o.y = uaf(f2tf32(v1 * am));
                        *(float2*)(g_v + off) = o;
                    }
                }
            }
        }
    }
}

// ---------------------------------------------------------------------------
// vmean[b,h,d] = mean_s v[b,h,s,d]  (float4 loads, skip inactive heads)
// ---------------------------------------------------------------------------
__global__ void vmean_kernel() {
    const int bh = blockIdx.x;
    if (g_active[bh & (HH - 1)] == 0.0f) return;
    const int d4    = (threadIdx.x & 15) * 4;
    const int chunk = threadIdx.x >> 4;
    const size_t base = (size_t)bh * SS * DD;
    float4 sum = {0.f, 0.f, 0.f, 0.f};
    for (int s = chunk * 128; s < (chunk + 1) * 128; s++) {
        float4 t = *(const float4*)(g_v + base + (size_t)s * DD + d4);
        sum.x += t.x; sum.y += t.y; sum.z += t.z; sum.w += t.w;
    }
    __shared__ float4 red[256];
    red[threadIdx.x] = sum;
    __syncthreads();
    if (chunk == 0) {
        float4 t = {0.f, 0.f, 0.f, 0.f};
#pragma unroll
        for (int c = 0; c < 16; c++) {
            float4 r = red[c * 16 + (threadIdx.x & 15)];
            t.x += r.x; t.y += r.y; t.z += r.z; t.w += r.w;
        }
        const float inv = 1.0f / SS;
        t.x *= inv; t.y *= inv; t.z *= inv; t.w *= inv;
        *(float4*)(g_vmean + bh * DD + d4) = t;
    }
}

// ---------------------------------------------------------------------------
// Tensor-core flash attention, v3 (the validated attention half of round 5):
//  - K/V arrive tf32-rounded from the QKV epilogue -> B-frag loads are pure LDS
//  - P rounded once at exp time, reused in-register as PV A-frag (permuted k)
//  - Q raw in 32 regs, hi/lo split inline per ks (amortized over 8 nt)
//  - 2 CTAs/SM via __launch_bounds__(256,2)
//  - epilogue writes plain fp32 g_ao (single 16 MB write)
// ---------------------------------------------------------------------------
#define KSTR 68
#define VSTR 68
#define TKW  (64 * KSTR)
#define TVW  (64 * VSTR)
#define BUFW (TKW + TVW)
#define SMEM_ATTN (2 * BUFW * 4)      // 69632 B

__global__ void __launch_bounds__(256, 2) attn_tc_kernel() {
    extern __shared__ float sh[];

    const int tid  = threadIdx.x;
    const int lane = tid & 31;
    const int warp = tid >> 5;
    const int g8   = lane >> 2;         // 0..7
    const int tig  = lane & 3;
    const int wr   = warp * 16;

    const int b = blockIdx.z, h = blockIdx.y;
    const int q0 = blockIdx.x * 128;
    const size_t bh = (size_t)(b * HH + h) * SS * DD;

    if (g_active[h] == 0.0f) {
        const float4 z = {0.f, 0.f, 0.f, 0.f};
        for (int i = tid; i < 128 * 16; i += 256) {
            const int r = i >> 4, c = (i & 15) * 4;
            *(float4*)(g_ao + ((size_t)(b * SS + q0 + r) * HH + h) * DD + c) = z;
        }
        return;
    }

    const unsigned sbase = (unsigned)__cvta_generic_to_shared(sh);
    const int ldr = tid >> 2;
    const int ldc = (tid & 3) * 16;

    // Q raw fragments (32 regs)
    float qraw[8][4];
#pragma unroll
    for (int kt = 0; kt < 8; kt++) {
        const int r0 = q0 + wr + g8;
        const int c0 = kt * 8 + tig;
        qraw[kt][0] = g_q[bh + (size_t)r0 * DD + c0];
        qraw[kt][1] = g_q[bh + (size_t)(r0 + 8) * DD + c0];
        qraw[kt][2] = g_q[bh + (size_t)r0 * DD + c0 + 4];
        qraw[kt][3] = g_q[bh + (size_t)(r0 + 8) * DD + c0 + 4];
    }

    float o[8][4];
#pragma unroll
    for (int i = 0; i < 8; i++)
#pragma unroll
        for (int j = 0; j < 4; j++) o[i][j] = 0.f;
    float m0 = -1e30f, m1 = -1e30f, l0 = 0.f, l1 = 0.f;

    auto issue_tile = [&](int kvt, int buf) {
        const float* kp = g_k + bh + (size_t)(kvt * 64 + ldr) * DD + ldc;
        const float* vp = g_v + bh + (size_t)(kvt * 64 + ldr) * DD + ldc;
        const unsigned kd = sbase + (buf * BUFW + ldr * KSTR + ldc) * 4;
        const unsigned vd = sbase + (buf * BUFW + TKW + ldr * VSTR + ldc) * 4;
#pragma unroll
        for (int c = 0; c < 4; c++) {
            cp16(kd + 16 * c, kp + 4 * c);
            cp16(vd + 16 * c, vp + 4 * c);
        }
    };

    issue_tile(0, 0);
    cp_commit();

    const int NTILE = SS / 64;  // 32
    for (int t = 0; t < NTILE; t++) {
        const int buf = t & 1;
        if (t + 1 < NTILE) issue_tile(t + 1, buf ^ 1);
        cp_commit();
        cp_wait1();
        __syncthreads();

        const unsigned* Ku = (const unsigned*)(sh + buf * BUFW);
        const unsigned* Vu = Ku + TKW;

        // ---- QK: 2-term split, Q split inline per ks ----
        float c[8][4];
#pragma unroll
        for (int i = 0; i < 8; i++)
#pragma unroll
            for (int j = 0; j < 4; j++) c[i][j] = 0.f;
#pragma unroll
        for (int ks = 0; ks < 8; ks++) {
            unsigned ah[4], al[4];
#pragma unroll
            for (int e = 0; e < 4; e++) {
                ah[e] = f2tf32(qraw[ks][e]);
                al[e] = f2tf32(qraw[ks][e] - uaf(ah[e]));
            }
            const int kq = ks * 8 + tig;
#pragma unroll
            for (int nt = 0; nt < 8; nt++) {
                unsigned bb[2];
                bb[0] = Ku[(nt * 8 + g8) * KSTR + kq];
                bb[1] = Ku[(nt * 8 + g8) * KSTR + kq + 4];
                mma_tf32(c[nt], ah, bb);
                mma_tf32(c[nt], al, bb);
            }
        }

        // ---- online softmax; P rounded in-place into c ----
        float mx0 = c[0][0], mx1 = c[0][2];
#pragma unroll
        for (int nt = 0; nt < 8; nt++) {
            mx0 = fmaxf(mx0, fmaxf(c[nt][0], c[nt][1]));
            mx1 = fmaxf(mx1, fmaxf(c[nt][2], c[nt][3]));
        }
        mx0 = fmaxf(mx0, __shfl_xor_sync(0xffffffffu, mx0, 1));
        mx0 = fmaxf(mx0, __shfl_xor_sync(0xffffffffu, mx0, 2));
        mx1 = fmaxf(mx1, __shfl_xor_sync(0xffffffffu, mx1, 1));
        mx1 = fmaxf(mx1, __shfl_xor_sync(0xffffffffu, mx1, 2));
        const float mn0 = fmaxf(m0, mx0);
        const float mn1 = fmaxf(m1, mx1);
        const float sc0 = __expf(m0 - mn0);
        const float sc1 = __expf(m1 - mn1);
        m0 = mn0; m1 = mn1;
#pragma unroll
        for (int dt = 0; dt < 8; dt++) {
            o[dt][0] *= sc0; o[dt][1] *= sc0;
            o[dt][2] *= sc1; o[dt][3] *= sc1;
        }
        float s0 = 0.f, s1 = 0.f;
#pragma unroll
        for (int nt = 0; nt < 8; nt++) {
            const float p00 = uaf(f2tf32(__expf(c[nt][0] - m0)));
            const float p01 = uaf(f2tf32(__expf(c[nt][1] - m0)));
            const float p10 = uaf(f2tf32(__expf(c[nt][2] - m1)));
            const float p11 = uaf(f2tf32(__expf(c[nt][3] - m1)));
            s0 += p00 + p01;
            s1 += p10 + p11;
            c[nt][0] = p00; c[nt][1] = p01;
            c[nt][2] = p10; c[nt][3] = p11;
        }
        s0 += __shfl_xor_sync(0xffffffffu, s0, 1);
        s0 += __shfl_xor_sync(0xffffffffu, s0, 2);
        s1 += __shfl_xor_sync(0xffffffffu, s1, 1);
        s1 += __shfl_xor_sync(0xffffffffu, s1, 2);
        l0 = l0 * sc0 + s0;
        l1 = l1 * sc1 + s1;

        // ---- PV, permuted k-slots; A-frag = own accumulator bits ----
#pragma unroll
        for (int ks = 0; ks < 8; ks++) {
            unsigned aa[4] = {__float_as_uint(c[ks][0]), __float_as_uint(c[ks][2]),
                              __float_as_uint(c[ks][1]), __float_as_uint(c[ks][3])};
            const int vr0 = (ks * 8 + 2 * tig) * VSTR;
#pragma unroll
            for (int dt = 0; dt < 8; dt++) {
                unsigned bb[2];
                bb[0] = Vu[vr0 + dt * 8 + g8];
                bb[1] = Vu[vr0 + VSTR + dt * 8 + g8];
                mma_tf32(o[dt], aa, bb);
            }
        }
        __syncthreads();
    }

    // epilogue: normalize, add vmean, write [B,S,H,D] fp32
    const float inv0 = 1.0f / l0;
    const float inv1 = 1.0f / l1;
    const int r0 = q0 + wr + g8;
    const size_t ob0 = ((size_t)(b * SS + r0) * HH + h) * DD;
    const size_t ob1 = ((size_t)(b * SS + r0 + 8) * HH + h) * DD;
    const float* vm = g_vmean + (size_t)(b * HH + h) * DD;
#pragma unroll
    for (int dt = 0; dt < 8; dt++) {
        const int col = dt * 8 + 2 * tig;
        const float v0 = vm[col], v1 = vm[col + 1];
        float2 w0, w1;
        w0.x = o[dt][0] * inv0 + v0; w0.y = o[dt][1] * inv0 + v1;
        w1.x = o[dt][2] * inv1 + v0; w1.y = o[dt][3] * inv1 + v1;
        *(float2*)(g_ao + ob0 + col) = w0;
        *(float2*)(g_ao + ob1 + col) = w1;
    }
}

// ---------------------------------------------------------------------------
extern "C" void kernel_launch(void* const* d_in, const int* in_sizes, int n_in,
                              void* d_out, int out_size) {
    const float* x      = (const float*)d_in[0];
    const float* qkv_w  = (const float*)d_in[1];
    const float* qkv_b  = (const float*)d_in[2];
    const float* out_w  = (const float*)d_in[3];
    const float* out_b  = (const float*)d_in[4];
    const float* gates  = (const float*)d_in[5];
    const float* imp    = (const float*)d_in[6];
    const float* thr    = (const float*)d_in[7];
    float* out = (float*)d_out;

    static bool attr_set = false;
    if (!attr_set) {
        cudaFuncSetAttribute(attn_tc_kernel,
                             cudaFuncAttributeMaxDynamicSharedMemorySize, SMEM_ATTN);
        attr_set = true;
    }

    mask_kernel<<<1, 32>>>(gates, imp, thr);

    // QKV projection (3-term split tf32)
    {
        dim3 g(3 * EE / 128, MM / 128);      // 24 x 32
        gemm_split_kernel<0, true><<<g, 256>>>(x, qkv_w, qkv_b, nullptr);
    }

    vmean_kernel<<<BB * HH, 256>>>();

    // Attention (tensor cores, double-buffered, 2 CTAs/SM)
    {
        dim3 g(SS / 128, HH, BB);            // 16 x 16 x 2
        attn_tc_kernel<<<g, 256, SMEM_ATTN>>>();
    }

    // Output projection (2-term split tf32)
    {
        float* ao;
        cudaGetSymbolAddress((void**)&ao, g_ao);
        dim3 g(EE / 128, MM / 128);          // 8 x 32
        gemm_split_kernel<1, false><<<g, 256>>>(ao, out_w, out_b, out);
    }
}

// round 7
// speedup vs baseline: 1.2549x; 1.0357x over previous
#include <cuda_runtime.h>
#include <math.h>

#define BB 2
#define SS 2048
#define EE 1024
#define HH 16
#define DD 64
#define MM (BB*SS)

// Scratch (static device globals; no runtime allocation)
__device__ float g_q[BB*HH*SS*DD];      // raw fp32 q   [B,H,S,D]
__device__ float g_k[BB*HH*SS*DD];      // tf32-valued fp32
__device__ float g_v[BB*HH*SS*DD];      // tf32-valued fp32, pre-masked
__device__ float g_vmean[BB*HH*DD];
__device__ float g_ao[BB*SS*EE];        // fp32 attn out, [B,S,H,D] == [B,S,E]
__device__ float g_active[HH];

// ---------------------------------------------------------------------------
// helpers
// ---------------------------------------------------------------------------
__device__ __forceinline__ unsigned f2tf32(float x) {
    unsigned r;
    asm("cvt.rna.tf32.f32 %0, %1;" : "=r"(r) : "f"(x));
    return r;
}
__device__ __forceinline__ float uaf(unsigned u) { return __uint_as_float(u); }

__device__ __forceinline__ void mma_tf32(float c[4], const unsigned a[4], const unsigned b[2]) {
    asm volatile(
        "mma.sync.aligned.m16n8k8.row.col.f32.tf32.tf32.f32 "
        "{%0,%1,%2,%3}, {%4,%5,%6,%7}, {%8,%9}, {%0,%1,%2,%3};"
        : "+f"(c[0]), "+f"(c[1]), "+f"(c[2]), "+f"(c[3])
        : "r"(a[0]), "r"(a[1]), "r"(a[2]), "r"(a[3]),
          "r"(b[0]), "r"(b[1]));
}

__device__ __forceinline__ void cp16(unsigned dst, const void* src) {
    asm volatile("cp.async.cg.shared.global [%0], [%1], 16;\n" :: "r"(dst), "l"(src));
}
__device__ __forceinline__ void cp_commit() {
    asm volatile("cp.async.commit_group;\n");
}
__device__ __forceinline__ void cp_wait1() {
    asm volatile("cp.async.wait_group 1;\n");
}

// ---------------------------------------------------------------------------
// Head mask
// ---------------------------------------------------------------------------
__global__ void mask_kernel(const float* __restrict__ gates,
                            const float* __restrict__ imp,
                            const float* __restrict__ thr) {
    int h = threadIdx.x;
    if (h < HH) {
        float z  = gates[h] * imp[h];
        float gs = 1.0f / (1.0f + expf(-z));
        g_active[h] = (gs > thr[0]) ? 1.0f : 0.0f;
    }
}

// ---------------------------------------------------------------------------
// Split-TF32 GEMM, double-buffered smem (ONE barrier per k-tile).
// C[m,n] = sum_k A[m,k]*B[n,k] + bias[n]
// BM=BN=128, BK=16, 256 threads (8 warps 2x4), warp tile 64x32.
// Terms: Ah*Bh + Al*Bh (+ Ah*Bl if SB).
// Dynamic smem: 2 stages x (Ah|Al|Bh|Bl)[128][20] = 81920 B.
// MODE 0: qkv scatter epilogue (k,v stored tf32-pre-rounded). MODE 1: row-major.
// ---------------------------------------------------------------------------
#define GARR  (128 * 20)            // words per operand array
#define GSTG  (4 * GARR)            // words per stage
#define SMEM_GEMM (2 * GSTG * 4)    // 81920 B

template <int MODE, bool SB>
__global__ void __launch_bounds__(256, 2) gemm_split_kernel(
    const float* __restrict__ A,
    const float* __restrict__ B,
    const float* __restrict__ bias,
    float* __restrict__ Y) {
    extern __shared__ unsigned gsm[];

    const int m0 = blockIdx.y * 128;
    const int n0 = blockIdx.x * 128;

    if (MODE == 0) {
        // block covers exactly 2 heads of one of q/k/v; skip if both inactive
        const int hA = (n0 & 1023) >> 6;
        if (g_active[hA] == 0.0f && g_active[hA + 1] == 0.0f) return;
    }

    const int tid  = threadIdx.x;
    const int lane = tid & 31;
    const int warp = tid >> 5;
    const int wm = (warp >> 2) * 64;
    const int wn = (warp & 3) * 32;
    const int grp = lane >> 2;
    const int tig = lane & 3;

    const int grow = tid >> 1;          // 0..127
    const int gk   = (tid & 1) * 8;     // 0 or 8
    const float* Aptr = A + (size_t)(m0 + grow) * EE + gk;
    const float* Bptr = B + (size_t)(n0 + grow) * EE + gk;

    float acc[4][4][4];
#pragma unroll
    for (int i = 0; i < 4; i++)
#pragma unroll
        for (int j = 0; j < 4; j++)
#pragma unroll
            for (int r = 0; r < 4; r++) acc[i][j][r] = 0.f;

    // split + store a prefetched tile into stage st
    auto store_stage = [&](int st, const float4 pa[2], const float4 pb[2]) {
        unsigned* Ah = gsm + st * GSTG;
        unsigned* Al = Ah + GARR;
        unsigned* Bh = Al + GARR;
        unsigned* Bl = Bh + GARR;
#pragma unroll
        for (int i = 0; i < 2; i++) {
            const float av[4] = {pa[i].x, pa[i].y, pa[i].z, pa[i].w};
            const float bv[4] = {pb[i].x, pb[i].y, pb[i].z, pb[i].w};
            uint4 ah, al, bh, bl;
            unsigned* ahp = &ah.x; unsigned* alp = &al.x;
            unsigned* bhp = &bh.x; unsigned* blp = &bl.x;
#pragma unroll
            for (int c = 0; c < 4; c++) {
                unsigned hh = f2tf32(av[c]);
                ahp[c] = hh; alp[c] = f2tf32(av[c] - uaf(hh));
                unsigned hb = f2tf32(bv[c]);
                bhp[c] = hb; blp[c] = f2tf32(bv[c] - uaf(hb));
            }
            const int o = grow * 20 + gk + 4 * i;
            *(uint4*)&Ah[o] = ah;
            *(uint4*)&Al[o] = al;
            *(uint4*)&Bh[o] = bh;
            if (SB) *(uint4*)&Bl[o] = bl;
        }
    };

    // prologue: tile 0 -> stage 0
    {
        float4 pa[2], pb[2];
#pragma unroll
        for (int i = 0; i < 2; i++) {
            pa[i] = *(const float4*)(Aptr + 4 * i);
            pb[i] = *(const float4*)(Bptr + 4 * i);
        }
        store_stage(0, pa, pb);
    }
    __syncthreads();

    const int NT = EE / 16;  // 64 k-tiles
    for (int kt = 0; kt < NT; kt++) {
        float4 pa[2], pb[2];
        if (kt + 1 < NT) {
            const float* An = Aptr + (kt + 1) * 16;
            const float* Bn = Bptr + (kt + 1) * 16;
#pragma unroll
            for (int i = 0; i < 2; i++) {
                pa[i] = *(const float4*)(An + 4 * i);
                pb[i] = *(const float4*)(Bn + 4 * i);
            }
        }

        const unsigned* Ah = gsm + (kt & 1) * GSTG;
        const unsigned* Al = Ah + GARR;
        const unsigned* Bh = Al + GARR;
        const unsigned* Bl = Bh + GARR;

#pragma unroll
        for (int ks = 0; ks < 2; ks++) {
            const int kq = ks * 8 + tig;
            unsigned ah[4][4], al[4][4];
#pragma unroll
            for (int mi = 0; mi < 4; mi++) {
                const int mr = wm + mi * 16 + grp;
                ah[mi][0] = Ah[mr * 20 + kq];       ah[mi][1] = Ah[(mr + 8) * 20 + kq];
                ah[mi][2] = Ah[mr * 20 + kq + 4];   ah[mi][3] = Ah[(mr + 8) * 20 + kq + 4];
                al[mi][0] = Al[mr * 20 + kq];       al[mi][1] = Al[(mr + 8) * 20 + kq];
                al[mi][2] = Al[mr * 20 + kq + 4];   al[mi][3] = Al[(mr + 8) * 20 + kq + 4];
            }
            unsigned bh[4][2], bl[4][2];
#pragma unroll
            for (int ni = 0; ni < 4; ni++) {
                const int nr = wn + ni * 8 + grp;
                bh[ni][0] = Bh[nr * 20 + kq]; bh[ni][1] = Bh[nr * 20 + kq + 4];
                if (SB) { bl[ni][0] = Bl[nr * 20 + kq]; bl[ni][1] = Bl[nr * 20 + kq + 4]; }
            }
#pragma unroll
            for (int mi = 0; mi < 4; mi++)
#pragma unroll
                for (int ni = 0; ni < 4; ni++) {
                    mma_tf32(acc[mi][ni], ah[mi], bh[ni]);
                    mma_tf32(acc[mi][ni], al[mi], bh[ni]);
                    if (SB) mma_tf32(acc[mi][ni], ah[mi], bl[ni]);
                }
        }

        if (kt + 1 < NT) store_stage((kt + 1) & 1, pa, pb);
        __syncthreads();
    }

    // epilogue
#pragma unroll
    for (int mi = 0; mi < 4; mi++) {
        const int rbase = m0 + wm + mi * 16 + grp;
#pragma unroll
        for (int ni = 0; ni < 4; ni++) {
            const int j = n0 + wn + ni * 8 + 2 * tig;
            const float b0 = bias[j], b1 = bias[j + 1];
#pragma unroll
            for (int rh = 0; rh < 2; rh++) {
                const int m = rbase + rh * 8;
                const float v0 = acc[mi][ni][rh * 2 + 0] + b0;
                const float v1 = acc[mi][ni][rh * 2 + 1] + b1;
                if (MODE == 1) {
                    float2 o; o.x = v0; o.y = v1;
                    *(float2*)(Y + (size_t)m * EE + j) = o;
                } else {
                    const int cc  = j >> 10;
                    const int rem = j & 1023;
                    const int h = rem >> 6, d = rem & 63;
                    const int bI = m >> 11;
                    const int s  = m & (SS - 1);
                    const size_t off = (((size_t)(bI * HH + h)) * SS + s) * DD + d;
                    float2 o;
                    if (cc == 0) {
                        o.x = v0; o.y = v1;                 // q raw
                        *(float2*)(g_q + off) = o;
                    } else if (cc == 1) {
                        o.x = uaf(f2tf32(v0));              // k pre-rounded
                        o.y = uaf(f2tf32(v1));
                        *(float2*)(g_k + off) = o;
                    } else {
                        const float am = g_active[h];
                        o.x = uaf(f2tf32(v0 * am));         // v masked + rounded
                        o.y = uaf(f2tf32(v1 * am));
                        *(float2*)(g_v + off) = o;
                    }
                }
            }
        }
    }
}

// ---------------------------------------------------------------------------
// vmean[b,h,d] = mean_s v[b,h,s,d]  (float4 loads, skip inactive heads)
// ---------------------------------------------------------------------------
__global__ void vmean_kernel() {
    const int bh = blockIdx.x;
    if (g_active[bh & (HH - 1)] == 0.0f) return;
    const int d4    = (threadIdx.x & 15) * 4;
    const int chunk = threadIdx.x >> 4;
    const size_t base = (size_t)bh * SS * DD;
    float4 sum = {0.f, 0.f, 0.f, 0.f};
    for (int s = chunk * 128; s < (chunk + 1) * 128; s++) {
        float4 t = *(const float4*)(g_v + base + (size_t)s * DD + d4);
        sum.x += t.x; sum.y += t.y; sum.z += t.z; sum.w += t.w;
    }
    __shared__ float4 red[256];
    red[threadIdx.x] = sum;
    __syncthreads();
    if (chunk == 0) {
        float4 t = {0.f, 0.f, 0.f, 0.f};
#pragma unroll
        for (int c = 0; c < 16; c++) {
            float4 r = red[c * 16 + (threadIdx.x & 15)];
            t.x += r.x; t.y += r.y; t.z += r.z; t.w += r.w;
        }
        const float inv = 1.0f / SS;
        t.x *= inv; t.y *= inv; t.z *= inv; t.w *= inv;
        *(float4*)(g_vmean + bh * DD + d4) = t;
    }
}

// ---------------------------------------------------------------------------
// Tensor-core flash attention, v4: 3-stage cp.async ring, ONE barrier per tile.
//  - K/V arrive tf32-rounded from the QKV epilogue -> B-frag loads are pure LDS
//  - P rounded once at exp time, reused in-register as PV A-frag (permuted k)
//  - Q raw in 32 regs, hi/lo split inline per ks
//  - 2 CTAs/SM via __launch_bounds__(256,2); 3 x 34816 B = 104448 B smem
// ---------------------------------------------------------------------------
#define KSTR 68
#define VSTR 68
#define TKW  (64 * KSTR)
#define TVW  (64 * VSTR)
#define BUFW (TKW + TVW)
#define NSTG 3
#define SMEM_ATTN (NSTG * BUFW * 4)   // 104448 B

__global__ void __launch_bounds__(256, 2) attn_tc_kernel() {
    extern __shared__ float sh[];

    const int tid  = threadIdx.x;
    const int lane = tid & 31;
    const int warp = tid >> 5;
    const int g8   = lane >> 2;         // 0..7
    const int tig  = lane & 3;
    const int wr   = warp * 16;

    const int b = blockIdx.z, h = blockIdx.y;
    const int q0 = blockIdx.x * 128;
    const size_t bh = (size_t)(b * HH + h) * SS * DD;

    if (g_active[h] == 0.0f) {
        const float4 z = {0.f, 0.f, 0.f, 0.f};
        for (int i = tid; i < 128 * 16; i += 256) {
            const int r = i >> 4, c = (i & 15) * 4;
            *(float4*)(g_ao + ((size_t)(b * SS + q0 + r) * HH + h) * DD + c) = z;
        }
        return;
    }

    const unsigned sbase = (unsigned)__cvta_generic_to_shared(sh);
    const int ldr = tid >> 2;
    const int ldc = (tid & 3) * 16;

    // Q raw fragments (32 regs)
    float qraw[8][4];
#pragma unroll
    for (int kt = 0; kt < 8; kt++) {
        const int r0 = q0 + wr + g8;
        const int c0 = kt * 8 + tig;
        qraw[kt][0] = g_q[bh + (size_t)r0 * DD + c0];
        qraw[kt][1] = g_q[bh + (size_t)(r0 + 8) * DD + c0];
        qraw[kt][2] = g_q[bh + (size_t)r0 * DD + c0 + 4];
        qraw[kt][3] = g_q[bh + (size_t)(r0 + 8) * DD + c0 + 4];
    }

    float o[8][4];
#pragma unroll
    for (int i = 0; i < 8; i++)
#pragma unroll
        for (int j = 0; j < 4; j++) o[i][j] = 0.f;
    float m0 = -1e30f, m1 = -1e30f, l0 = 0.f, l1 = 0.f;

    auto issue_tile = [&](int kvt, int st) {
        const float* kp = g_k + bh + (size_t)(kvt * 64 + ldr) * DD + ldc;
        const float* vp = g_v + bh + (size_t)(kvt * 64 + ldr) * DD + ldc;
        const unsigned kd = sbase + (st * BUFW + ldr * KSTR + ldc) * 4;
        const unsigned vd = sbase + (st * BUFW + TKW + ldr * VSTR + ldc) * 4;
#pragma unroll
        for (int c = 0; c < 4; c++) {
            cp16(kd + 16 * c, kp + 4 * c);
            cp16(vd + 16 * c, vp + 4 * c);
        }
    };

    issue_tile(0, 0); cp_commit();
    issue_tile(1, 1); cp_commit();

    const int NTILE = SS / 64;  // 32
    int stage = 0;
    for (int t = 0; t < NTILE; t++) {
        cp_wait1();              // tile t resident (<=1 outstanding group)
        __syncthreads();         // all warps see it; all warps done with stage (t+2)%3

        // refill the stage consumed two iterations ago (overlaps compute below)
        if (t + 2 < NTILE) {
            int st2 = stage + 2; if (st2 >= NSTG) st2 -= NSTG;
            issue_tile(t + 2, st2);
        }
        cp_commit();

        const unsigned* Ku = (const unsigned*)(sh + stage * BUFW);
        const unsigned* Vu = Ku + TKW;

        // ---- QK: 2-term split, Q split inline per ks ----
        float c[8][4];
#pragma unroll
        for (int i = 0; i < 8; i++)
#pragma unroll
            for (int j = 0; j < 4; j++) c[i][j] = 0.f;
#pragma unroll
        for (int ks = 0; ks < 8; ks++) {
            unsigned ah[4], al[4];
#pragma unroll
            for (int e = 0; e < 4; e++) {
                ah[e] = f2tf32(qraw[ks][e]);
                al[e] = f2tf32(qraw[ks][e] - uaf(ah[e]));
            }
            const int kq = ks * 8 + tig;
#pragma unroll
            for (int nt = 0; nt < 8; nt++) {
                unsigned bb[2];
                bb[0] = Ku[(nt * 8 + g8) * KSTR + kq];
                bb[1] = Ku[(nt * 8 + g8) * KSTR + kq + 4];
                mma_tf32(c[nt], ah, bb);
                mma_tf32(c[nt], al, bb);
            }
        }

        // ---- online softmax; P rounded in-place into c ----
        float mx0 = c[0][0], mx1 = c[0][2];
#pragma unroll
        for (int nt = 0; nt < 8; nt++) {
            mx0 = fmaxf(mx0, fmaxf(c[nt][0], c[nt][1]));
            mx1 = fmaxf(mx1, fmaxf(c[nt][2], c[nt][3]));
        }
        mx0 = fmaxf(mx0, __shfl_xor_sync(0xffffffffu, mx0, 1));
        mx0 = fmaxf(mx0, __shfl_xor_sync(0xffffffffu, mx0, 2));
        mx1 = fmaxf(mx1, __shfl_xor_sync(0xffffffffu, mx1, 1));
        mx1 = fmaxf(mx1, __shfl_xor_sync(0xffffffffu, mx1, 2));
        const float mn0 = fmaxf(m0, mx0);
        const float mn1 = fmaxf(m1, mx1);
        const float sc0 = __expf(m0 - mn0);
        const float sc1 = __expf(m1 - mn1);
        m0 = mn0; m1 = mn1;
#pragma unroll
        for (int dt = 0; dt < 8; dt++) {
            o[dt][0] *= sc0; o[dt][1] *= sc0;
            o[dt][2] *= sc1; o[dt][3] *= sc1;
        }
        float s0 = 0.f, s1 = 0.f;
#pragma unroll
        for (int nt = 0; nt < 8; nt++) {
            const float p00 = uaf(f2tf32(__expf(c[nt][0] - m0)));
            const float p01 = uaf(f2tf32(__expf(c[nt][1] - m0)));
            const float p10 = uaf(f2tf32(__expf(c[nt][2] - m1)));
            const float p11 = uaf(f2tf32(__expf(c[nt][3] - m1)));
            s0 += p00 + p01;
            s1 += p10 + p11;
            c[nt][0] = p00; c[nt][1] = p01;
            c[nt][2] = p10; c[nt][3] = p11;
        }
        s0 += __shfl_xor_sync(0xffffffffu, s0, 1);
        s0 += __shfl_xor_sync(0xffffffffu, s0, 2);
        s1 += __shfl_xor_sync(0xffffffffu, s1, 1);
        s1 += __shfl_xor_sync(0xffffffffu, s1, 2);
        l0 = l0 * sc0 + s0;
        l1 = l1 * sc1 + s1;

        // ---- PV, permuted k-slots; A-frag = own accumulator bits ----
#pragma unroll
        for (int ks = 0; ks < 8; ks++) {
            unsigned aa[4] = {__float_as_uint(c[ks][0]), __float_as_uint(c[ks][2]),
                              __float_as_uint(c[ks][1]), __float_as_uint(c[ks][3])};
            const int vr0 = (ks * 8 + 2 * tig) * VSTR;
#pragma unroll
            for (int dt = 0; dt < 8; dt++) {
                unsigned bb[2];
                bb[0] = Vu[vr0 + dt * 8 + g8];
                bb[1] = Vu[vr0 + VSTR + dt * 8 + g8];
                mma_tf32(o[dt], aa, bb);
            }
        }

        stage = (stage + 1 == NSTG) ? 0 : stage + 1;
    }

    // epilogue: normalize, add vmean, write [B,S,H,D] fp32
    const float inv0 = 1.0f / l0;
    const float inv1 = 1.0f / l1;
    const int r0 = q0 + wr + g8;
    const size_t ob0 = ((size_t)(b * SS + r0) * HH + h) * DD;
    const size_t ob1 = ((size_t)(b * SS + r0 + 8) * HH + h) * DD;
    const float* vm = g_vmean + (size_t)(b * HH + h) * DD;
#pragma unroll
    for (int dt = 0; dt < 8; dt++) {
        const int col = dt * 8 + 2 * tig;
        const float v0 = vm[col], v1 = vm[col + 1];
        float2 w0, w1;
        w0.x = o[dt][0] * inv0 + v0; w0.y = o[dt][1] * inv0 + v1;
        w1.x = o[dt][2] * inv1 + v0; w1.y = o[dt][3] * inv1 + v1;
        *(float2*)(g_ao + ob0 + col) = w0;
        *(float2*)(g_ao + ob1 + col) = w1;
    }
}

// ---------------------------------------------------------------------------
extern "C" void kernel_launch(void* const* d_in, const int* in_sizes, int n_in,
                              void* d_out, int out_size) {
    const float* x      = (const float*)d_in[0];
    const float* qkv_w  = (const float*)d_in[1];
    const float* qkv_b  = (const float*)d_in[2];
    const float* out_w  = (const float*)d_in[3];
    const float* out_b  = (const float*)d_in[4];
    const float* gates  = (const float*)d_in[5];
    const float* imp    = (const float*)d_in[6];
    const float* thr    = (const float*)d_in[7];
    float* out = (float*)d_out;

    static bool attr_set = false;
    if (!attr_set) {
        cudaFuncSetAttribute(attn_tc_kernel,
                             cudaFuncAttributeMaxDynamicSharedMemorySize, SMEM_ATTN);
        cudaFuncSetAttribute(gemm_split_kernel<0, true>,
                             cudaFuncAttributeMaxDynamicSharedMemorySize, SMEM_GEMM);
        cudaFuncSetAttribute(gemm_split_kernel<1, false>,
                             cudaFuncAttributeMaxDynamicSharedMemorySize, SMEM_GEMM);
        attr_set = true;
    }

    mask_kernel<<<1, 32>>>(gates, imp, thr);

    // QKV projection (3-term split tf32)
    {
        dim3 g(3 * EE / 128, MM / 128);      // 24 x 32
        gemm_split_kernel<0, true><<<g, 256, SMEM_GEMM>>>(x, qkv_w, qkv_b, nullptr);
    }

    vmean_kernel<<<BB * HH, 256>>>();

    // Attention (tensor cores, 3-stage ring, 2 CTAs/SM)
    {
        dim3 g(SS / 128, HH, BB);            // 16 x 16 x 2
        attn_tc_kernel<<<g, 256, SMEM_ATTN>>>();
    }

    // Output projection (2-term split tf32)
    {
        float* ao;
        cudaGetSymbolAddress((void**)&ao, g_ao);
        dim3 g(EE / 128, MM / 128);          // 8 x 32
        gemm_split_kernel<1, false><<<g, 256, SMEM_GEMM>>>(ao, out_w, out_b, out);
    }
}

// round 10
// speedup vs baseline: 1.3910x; 1.1084x over previous
#include <cuda_runtime.h>
#include <cuda_bf16.h>
#include <stdint.h>
#include <math.h>

#define BB 2
#define SS 2048
#define EE 1024
#define HH 16
#define DD 64
#define MM (BB*SS)

// Scratch (static device globals; no runtime allocation)
__device__ float g_q[BB*HH*SS*DD];      // raw fp32 q   [B,H,S,D]
__device__ float g_k[BB*HH*SS*DD];      // tf32-valued fp32
__device__ float g_v[BB*HH*SS*DD];      // tf32-valued fp32, pre-masked
__device__ float g_vmean[BB*HH*DD];
__device__ float g_active[HH];
// bf16 hi/lo operand arrays for bf16 mma GEMMs
__device__ __align__(16) __nv_bfloat16 g_xh[MM*EE],   g_xl[MM*EE];     // x
__device__ __align__(16) __nv_bfloat16 g_wh[3*EE*EE], g_wl[3*EE*EE];   // qkv_w
__device__ __align__(16) __nv_bfloat16 g_owh[EE*EE],  g_owl[EE*EE];    // out_w
__device__ __align__(16) __nv_bfloat16 g_aoh[MM*EE],  g_aol[MM*EE];    // attn out [B,S,H*D]

// ---------------------------------------------------------------------------
// helpers
// ---------------------------------------------------------------------------
__device__ __forceinline__ unsigned f2tf32(float x) {
    unsigned r;
    asm("cvt.rna.tf32.f32 %0, %1;" : "=r"(r) : "f"(x));
    return r;
}
__device__ __forceinline__ float uaf(unsigned u) { return __uint_as_float(u); }

__device__ __forceinline__ void mma_tf32(float c[4], const unsigned a[4], const unsigned b[2]) {
    asm volatile(
        "mma.sync.aligned.m16n8k8.row.col.f32.tf32.tf32.f32 "
        "{%0,%1,%2,%3}, {%4,%5,%6,%7}, {%8,%9}, {%0,%1,%2,%3};"
        : "+f"(c[0]), "+f"(c[1]), "+f"(c[2]), "+f"(c[3])
        : "r"(a[0]), "r"(a[1]), "r"(a[2]), "r"(a[3]),
          "r"(b[0]), "r"(b[1]));
}

// m16n8k16 bf16 mma: same word-level fragment indexing as tf32 k8
// (each 32-bit word = 2 consecutive bf16 along k)
__device__ __forceinline__ void mma_bf16(float c[4], const unsigned a[4], const unsigned b[2]) {
    asm volatile(
        "mma.sync.aligned.m16n8k16.row.col.f32.bf16.bf16.f32 "
        "{%0,%1,%2,%3}, {%4,%5,%6,%7}, {%8,%9}, {%0,%1,%2,%3};"
        : "+f"(c[0]), "+f"(c[1]), "+f"(c[2]), "+f"(c[3])
        : "r"(a[0]), "r"(a[1]), "r"(a[2]), "r"(a[3]),
          "r"(b[0]), "r"(b[1]));
}

__device__ __forceinline__ void cp16(unsigned dst, const void* src) {
    asm volatile("cp.async.cg.shared.global [%0], [%1], 16;\n" :: "r"(dst), "l"(src));
}
__device__ __forceinline__ void cp_commit() {
    asm volatile("cp.async.commit_group;\n");
}
__device__ __forceinline__ void cp_wait1() {
    asm volatile("cp.async.wait_group 1;\n");
}

// ---------------------------------------------------------------------------
// Head mask
// ---------------------------------------------------------------------------
__global__ void mask_kernel(const float* __restrict__ gates,
                            const float* __restrict__ imp,
                            const float* __restrict__ thr) {
    int h = threadIdx.x;
    if (h < HH) {
        float z  = gates[h] * imp[h];
        float gs = 1.0f / (1.0f + expf(-z));
        g_active[h] = (gs > thr[0]) ? 1.0f : 0.0f;
    }
}

// ---------------------------------------------------------------------------
// bf16 hi/lo split: h = bf16(x), l = bf16(x - h)
// ---------------------------------------------------------------------------
__global__ void split_bf16_kernel(const float* __restrict__ src,
                                  __nv_bfloat16* __restrict__ h,
                                  __nv_bfloat16* __restrict__ l, int n4) {
    int i = blockIdx.x * blockDim.x + threadIdx.x;
    if (i < n4) {
        float4 v = ((const float4*)src)[i];
        __nv_bfloat16 hx = __float2bfloat16_rn(v.x);
        __nv_bfloat16 hy = __float2bfloat16_rn(v.y);
        __nv_bfloat16 hz = __float2bfloat16_rn(v.z);
        __nv_bfloat16 hw = __float2bfloat16_rn(v.w);
        __nv_bfloat162 h01; h01.x = hx; h01.y = hy;
        __nv_bfloat162 h23; h23.x = hz; h23.y = hw;
        *(__nv_bfloat162*)(h + 4 * (size_t)i)     = h01;
        *(__nv_bfloat162*)(h + 4 * (size_t)i + 2) = h23;
        __nv_bfloat162 l01, l23;
        l01.x = __float2bfloat16_rn(v.x - __bfloat162float(hx));
        l01.y = __float2bfloat16_rn(v.y - __bfloat162float(hy));
        l23.x = __float2bfloat16_rn(v.z - __bfloat162float(hz));
        l23.y = __float2bfloat16_rn(v.w - __bfloat162float(hw));
        *(__nv_bfloat162*)(l + 4 * (size_t)i)     = l01;
        *(__nv_bfloat162*)(l + 4 * (size_t)i + 2) = l23;
    }
}

// ---------------------------------------------------------------------------
// 3-term bf16-split GEMM on mma.sync.m16n8k16 (round-7 skeleton):
// C[m,n] = sum_k A[m,k]*B[n,k] + bias[n]
// BM=BN=128, BK=32 bf16 (=16 words/row), 256 threads, warp tile 64x32,
// double-buffered smem, ONE barrier per k-tile.
// Terms: Ah*Bh + Al*Bh + Ah*Bl.
// MODE 0: qkv scatter epilogue. MODE 1: row-major write.
// ---------------------------------------------------------------------------
#define GSTR  20                    // words per smem row (16 + 4 pad)
#define GARR  (128 * GSTR)          // words per operand array
#define GSTG  (4 * GARR)            // Ah|Al|Bh|Bl per stage
#define SMEM_GEMM (2 * GSTG * 4)    // 81920 B

template <int MODE>
__global__ void __launch_bounds__(256, 2) gemm_bf16_kernel(
    const __nv_bfloat16* __restrict__ Ahg, const __nv_bfloat16* __restrict__ Alg,
    const __nv_bfloat16* __restrict__ Bhg, const __nv_bfloat16* __restrict__ Blg,
    const float* __restrict__ bias, float* __restrict__ Y) {
    extern __shared__ unsigned gsm[];

    const int m0 = blockIdx.y * 128;
    const int n0 = blockIdx.x * 128;

    if (MODE == 0) {
        // block covers exactly 2 heads of one of q/k/v; skip if both inactive
        const int hA = (n0 & 1023) >> 6;
        if (g_active[hA] == 0.0f && g_active[hA + 1] == 0.0f) return;
    }

    const int tid  = threadIdx.x;
    const int lane = tid & 31;
    const int warp = tid >> 5;
    const int wm = (warp >> 2) * 64;
    const int wn = (warp & 3) * 32;
    const int grp = lane >> 2;
    const int tig = lane & 3;

    const int grow = tid >> 1;          // 0..127
    const int gkw  = (tid & 1) * 8;     // word offset 0 or 8 (=16 bf16)
    const __nv_bfloat16* Aph = Ahg + (size_t)(m0 + grow) * EE + gkw * 2;
    const __nv_bfloat16* Apl = Alg + (size_t)(m0 + grow) * EE + gkw * 2;
    const __nv_bfloat16* Bph = Bhg + (size_t)(n0 + grow) * EE + gkw * 2;
    const __nv_bfloat16* Bpl = Blg + (size_t)(n0 + grow) * EE + gkw * 2;

    float acc[4][4][4];
#pragma unroll
    for (int i = 0; i < 4; i++)
#pragma unroll
        for (int j = 0; j < 4; j++)
#pragma unroll
            for (int r = 0; r < 4; r++) acc[i][j][r] = 0.f;

    // store a prefetched tile (8 uint4 = Ah,Al,Bh,Bl x 2) into stage st
    auto store_stage = [&](int st, const uint4 p[8]) {
        unsigned* base = gsm + st * GSTG + grow * GSTR + gkw;
        *(uint4*)(base)                = p[0];
        *(uint4*)(base + 4)            = p[1];
        *(uint4*)(base + GARR)         = p[2];
        *(uint4*)(base + GARR + 4)     = p[3];
        *(uint4*)(base + 2 * GARR)     = p[4];
        *(uint4*)(base + 2 * GARR + 4) = p[5];
        *(uint4*)(base + 3 * GARR)     = p[6];
        *(uint4*)(base + 3 * GARR + 4) = p[7];
    };
    auto load_tile = [&](int kt, uint4 p[8]) {
        const size_t o = (size_t)kt * 32;   // 32 bf16 per tile
        p[0] = *(const uint4*)(Aph + o);  p[1] = *(const uint4*)(Aph + o + 8);
        p[2] = *(const uint4*)(Apl + o);  p[3] = *(const uint4*)(Apl + o + 8);
        p[4] = *(const uint4*)(Bph + o);  p[5] = *(const uint4*)(Bph + o + 8);
        p[6] = *(const uint4*)(Bpl + o);  p[7] = *(const uint4*)(Bpl + o + 8);
    };

    {
        uint4 p[8];
        load_tile(0, p);
        store_stage(0, p);
    }
    __syncthreads();

    const int NT = EE / 32;  // 32 k-tiles
    for (int kt = 0; kt < NT; kt++) {
        uint4 p[8];
        if (kt + 1 < NT) load_tile(kt + 1, p);

        const unsigned* Ah = gsm + (kt & 1) * GSTG;
        const unsigned* Al = Ah + GARR;
        const unsigned* Bh = Al + GARR;
        const unsigned* Bl = Bh + GARR;

#pragma unroll
        for (int ks = 0; ks < 2; ks++) {
            const int kq = ks * 8 + tig;
            unsigned ah[4][4], al[4][4];
#pragma unroll
            for (int mi = 0; mi < 4; mi++) {
                const int mr = wm + mi * 16 + grp;
                ah[mi][0] = Ah[mr * GSTR + kq];       ah[mi][1] = Ah[(mr + 8) * GSTR + kq];
                ah[mi][2] = Ah[mr * GSTR + kq + 4];   ah[mi][3] = Ah[(mr + 8) * GSTR + kq + 4];
                al[mi][0] = Al[mr * GSTR + kq];       al[mi][1] = Al[(mr + 8) * GSTR + kq];
                al[mi][2] = Al[mr * GSTR + kq + 4];   al[mi][3] = Al[(mr + 8) * GSTR + kq + 4];
            }
            unsigned bh[4][2], bl[4][2];
#pragma unroll
            for (int ni = 0; ni < 4; ni++) {
                const int nr = wn + ni * 8 + grp;
                bh[ni][0] = Bh[nr * GSTR + kq]; bh[ni][1] = Bh[nr * GSTR + kq + 4];
                bl[ni][0] = Bl[nr * GSTR + kq]; bl[ni][1] = Bl[nr * GSTR + kq + 4];
            }
#pragma unroll
            for (int mi = 0; mi < 4; mi++)
#pragma unroll
                for (int ni = 0; ni < 4; ni++) {
                    mma_bf16(acc[mi][ni], ah[mi], bh[ni]);
                    mma_bf16(acc[mi][ni], al[mi], bh[ni]);
                    mma_bf16(acc[mi][ni], ah[mi], bl[ni]);
                }
        }

        if (kt + 1 < NT) store_stage((kt + 1) & 1, p);
        __syncthreads();
    }

    // epilogue
#pragma unroll
    for (int mi = 0; mi < 4; mi++) {
        const int rbase = m0 + wm + mi * 16 + grp;
#pragma unroll
        for (int ni = 0; ni < 4; ni++) {
            const int j = n0 + wn + ni * 8 + 2 * tig;
            const float b0 = bias[j], b1 = bias[j + 1];
#pragma unroll
            for (int rh = 0; rh < 2; rh++) {
                const int m = rbase + rh * 8;
                const float v0 = acc[mi][ni][rh * 2 + 0] + b0;
                const float v1 = acc[mi][ni][rh * 2 + 1] + b1;
                if (MODE == 1) {
                    float2 o; o.x = v0; o.y = v1;
                    *(float2*)(Y + (size_t)m * EE + j) = o;
                } else {
                    const int cc  = j >> 10;
                    const int rem = j & 1023;
                    const int h = rem >> 6, d = rem & 63;
                    const int bI = m >> 11;
                    const int s  = m & (SS - 1);
                    const size_t off = (((size_t)(bI * HH + h)) * SS + s) * DD + d;
                    float2 o;
                    if (cc == 0) {
                        o.x = v0; o.y = v1;                 // q raw
                        *(float2*)(g_q + off) = o;
                    } else if (cc == 1) {
                        o.x = uaf(f2tf32(v0));              // k pre-rounded to tf32
                        o.y = uaf(f2tf32(v1));
                        *(float2*)(g_k + off) = o;
                    } else {
                        const float am = g_active[h];
                        o.x = uaf(f2tf32(v0 * am));         // v masked + rounded
                        o.y = uaf(f2tf32(v1 * am));
                        *(float2*)(g_v + off) = o;
                    }
                }
            }
        }
    }
}

// ---------------------------------------------------------------------------
// vmean[b,h,d] = mean_s v[b,h,s,d]  (float4 loads, skip inactive heads)
// ---------------------------------------------------------------------------
__global__ void vmean_kernel() {
    const int bh = blockIdx.x;
    if (g_active[bh & (HH - 1)] == 0.0f) return;
    const int d4    = (threadIdx.x & 15) * 4;
    const int chunk = threadIdx.x >> 4;
    const size_t base = (size_t)bh * SS * DD;
    float4 sum = {0.f, 0.f, 0.f, 0.f};
    for (int s = chunk * 128; s < (chunk + 1) * 128; s++) {
        float4 t = *(const float4*)(g_v + base + (size_t)s * DD + d4);
        sum.x += t.x; sum.y += t.y; sum.z += t.z; sum.w += t.w;
    }
    __shared__ float4 red[256];
    red[threadIdx.x] = sum;
    __syncthreads();
    if (chunk == 0) {
        float4 t = {0.f, 0.f, 0.f, 0.f};
#pragma unroll
        for (int c = 0; c < 16; c++) {
            float4 r = red[c * 16 + (threadIdx.x & 15)];
            t.x += r.x; t.y += r.y; t.z += r.z; t.w += r.w;
        }
        const float inv = 1.0f / SS;
        t.x *= inv; t.y *= inv; t.z *= inv; t.w *= inv;
        *(float4*)(g_vmean + bh * DD + d4) = t;
    }
}

// ---------------------------------------------------------------------------
// Tensor-core flash attention (round-7 validated core; epilogue emits bf16 hi/lo)
// ---------------------------------------------------------------------------
#define KSTR 68
#define VSTR 68
#define TKW  (64 * KSTR)
#define TVW  (64 * VSTR)
#define BUFW (TKW + TVW)
#define NSTG 3
#define SMEM_ATTN (NSTG * BUFW * 4)   // 104448 B

__global__ void __launch_bounds__(256, 2) attn_tc_kernel() {
    extern __shared__ float sh[];

    const int tid  = threadIdx.x;
    const int lane = tid & 31;
    const int warp = tid >> 5;
    const int g8   = lane >> 2;
    const int tig  = lane & 3;
    const int wr   = warp * 16;

    const int b = blockIdx.z, h = blockIdx.y;
    const int q0 = blockIdx.x * 128;
    const size_t bh = (size_t)(b * HH + h) * SS * DD;

    if (g_active[h] == 0.0f) {
        const uint4 z = {0u, 0u, 0u, 0u};
        for (int i = tid; i < 128 * 8; i += 256) {
            const int r = i >> 3, c = (i & 7) * 8;
            const size_t off = ((size_t)(b * SS + q0 + r) * HH + h) * DD + c;
            *(uint4*)(g_aoh + off) = z;
            *(uint4*)(g_aol + off) = z;
        }
        return;
    }

    const unsigned sbase = (unsigned)__cvta_generic_to_shared(sh);
    const int ldr = tid >> 2;
    const int ldc = (tid & 3) * 16;

    float qraw[8][4];
#pragma unroll
    for (int kt = 0; kt < 8; kt++) {
        const int r0 = q0 + wr + g8;
        const int c0 = kt * 8 + tig;
        qraw[kt][0] = g_q[bh + (size_t)r0 * DD + c0];
        qraw[kt][1] = g_q[bh + (size_t)(r0 + 8) * DD + c0];
        qraw[kt][2] = g_q[bh + (size_t)r0 * DD + c0 + 4];
        qraw[kt][3] = g_q[bh + (size_t)(r0 + 8) * DD + c0 + 4];
    }

    float o[8][4];
#pragma unroll
    for (int i = 0; i < 8; i++)
#pragma unroll
        for (int j = 0; j < 4; j++) o[i][j] = 0.f;
    float m0 = -1e30f, m1 = -1e30f, l0 = 0.f, l1 = 0.f;

    auto issue_tile = [&](int kvt, int st) {
        const float* kp = g_k + bh + (size_t)(kvt * 64 + ldr) * DD + ldc;
        const float* vp = g_v + bh + (size_t)(kvt * 64 + ldr) * DD + ldc;
        const unsigned kd = sbase + (st * BUFW + ldr * KSTR + ldc) * 4;
        const unsigned vd = sbase + (st * BUFW + TKW + ldr * VSTR + ldc) * 4;
#pragma unroll
        for (int c = 0; c < 4; c++) {
            cp16(kd + 16 * c, kp + 4 * c);
            cp16(vd + 16 * c, vp + 4 * c);
        }
    };

    issue_tile(0, 0); cp_commit();
    issue_tile(1, 1); cp_commit();

    const int NTILE = SS / 64;
    int stage = 0;
    for (int t = 0; t < NTILE; t++) {
        cp_wait1();
        __syncthreads();

        if (t + 2 < NTILE) {
            int st2 = stage + 2; if (st2 >= NSTG) st2 -= NSTG;
            issue_tile(t + 2, st2);
        }
        cp_commit();

        const unsigned* Ku = (const unsigned*)(sh + stage * BUFW);
        const unsigned* Vu = Ku + TKW;

        float c[8][4];
#pragma unroll
        for (int i = 0; i < 8; i++)
#pragma unroll
            for (int j = 0; j < 4; j++) c[i][j] = 0.f;
#pragma unroll
        for (int ks = 0; ks < 8; ks++) {
            unsigned ah[4], al[4];
#pragma unroll
            for (int e = 0; e < 4; e++) {
                ah[e] = f2tf32(qraw[ks][e]);
                al[e] = f2tf32(qraw[ks][e] - uaf(ah[e]));
            }
            const int kq = ks * 8 + tig;
#pragma unroll
            for (int nt = 0; nt < 8; nt++) {
                unsigned bb[2];
                bb[0] = Ku[(nt * 8 + g8) * KSTR + kq];
                bb[1] = Ku[(nt * 8 + g8) * KSTR + kq + 4];
                mma_tf32(c[nt], ah, bb);
                mma_tf32(c[nt], al, bb);
            }
        }

        float mx0 = c[0][0], mx1 = c[0][2];
#pragma unroll
        for (int nt = 0; nt < 8; nt++) {
            mx0 = fmaxf(mx0, fmaxf(c[nt][0], c[nt][1]));
            mx1 = fmaxf(mx1, fmaxf(c[nt][2], c[nt][3]));
        }
        mx0 = fmaxf(mx0, __shfl_xor_sync(0xffffffffu, mx0, 1));
        mx0 = fmaxf(mx0, __shfl_xor_sync(0xffffffffu, mx0, 2));
        mx1 = fmaxf(mx1, __shfl_xor_sync(0xffffffffu, mx1, 1));
        mx1 = fmaxf(mx1, __shfl_xor_sync(0xffffffffu, mx1, 2));
        const float mn0 = fmaxf(m0, mx0);
        const float mn1 = fmaxf(m1, mx1);
        const float sc0 = __expf(m0 - mn0);
        const float sc1 = __expf(m1 - mn1);
        m0 = mn0; m1 = mn1;
#pragma unroll
        for (int dt = 0; dt < 8; dt++) {
            o[dt][0] *= sc0; o[dt][1] *= sc0;
            o[dt][2] *= sc1; o[dt][3] *= sc1;
        }
        float s0 = 0.f, s1 = 0.f;
#pragma unroll
        for (int nt = 0; nt < 8; nt++) {
            const float p00 = uaf(f2tf32(__expf(c[nt][0] - m0)));
            const float p01 = uaf(f2tf32(__expf(c[nt][1] - m0)));
            const float p10 = uaf(f2tf32(__expf(c[nt][2] - m1)));
            const float p11 = uaf(f2tf32(__expf(c[nt][3] - m1)));
            s0 += p00 + p01;
            s1 += p10 + p11;
            c[nt][0] = p00; c[nt][1] = p01;
            c[nt][2] = p10; c[nt][3] = p11;
        }
        s0 += __shfl_xor_sync(0xffffffffu, s0, 1);
        s0 += __shfl_xor_sync(0xffffffffu, s0, 2);
        s1 += __shfl_xor_sync(0xffffffffu, s1, 1);
        s1 += __shfl_xor_sync(0xffffffffu, s1, 2);
        l0 = l0 * sc0 + s0;
        l1 = l1 * sc1 + s1;

#pragma unroll
        for (int ks = 0; ks < 8; ks++) {
            unsigned aa[4] = {__float_as_uint(c[ks][0]), __float_as_uint(c[ks][2]),
                              __float_as_uint(c[ks][1]), __float_as_uint(c[ks][3])};
            const int vr0 = (ks * 8 + 2 * tig) * VSTR;
#pragma unroll
            for (int dt = 0; dt < 8; dt++) {
                unsigned bb[2];
                bb[0] = Vu[vr0 + dt * 8 + g8];
                bb[1] = Vu[vr0 + VSTR + dt * 8 + g8];
                mma_tf32(o[dt], aa, bb);
            }
        }

        stage = (stage + 1 == NSTG) ? 0 : stage + 1;
    }

    // epilogue: normalize, add vmean, emit bf16 hi/lo for out-projection
    const float inv0 = 1.0f / l0;
    const float inv1 = 1.0f / l1;
    const int r0 = q0 + wr + g8;
    const size_t ob0 = ((size_t)(b * SS + r0) * HH + h) * DD;
    const size_t ob1 = ((size_t)(b * SS + r0 + 8) * HH + h) * DD;
    const float* vm = g_vmean + (size_t)(b * HH + h) * DD;
#pragma unroll
    for (int dt = 0; dt < 8; dt++) {
        const int col = dt * 8 + 2 * tig;
        const float v0 = vm[col], v1 = vm[col + 1];
        const float f00 = o[dt][0] * inv0 + v0, f01 = o[dt][1] * inv0 + v1;
        const float f10 = o[dt][2] * inv1 + v0, f11 = o[dt][3] * inv1 + v1;
        __nv_bfloat162 h0, h1, lo0, lo1;
        h0.x = __float2bfloat16_rn(f00); lo0.x = __float2bfloat16_rn(f00 - __bfloat162float(h0.x));
        h0.y = __float2bfloat16_rn(f01); lo0.y = __float2bfloat16_rn(f01 - __bfloat162float(h0.y));
        h1.x = __float2bfloat16_rn(f10); lo1.x = __float2bfloat16_rn(f10 - __bfloat162float(h1.x));
        h1.y = __float2bfloat16_rn(f11); lo1.y = __float2bfloat16_rn(f11 - __bfloat162float(h1.y));
        *(__nv_bfloat162*)(g_aoh + ob0 + col) = h0;
        *(__nv_bfloat162*)(g_aol + ob0 + col) = lo0;
        *(__nv_bfloat162*)(g_aoh + ob1 + col) = h1;
        *(__nv_bfloat162*)(g_aol + ob1 + col) = lo1;
    }
}

// ---------------------------------------------------------------------------
extern "C" void kernel_launch(void* const* d_in, const int* in_sizes, int n_in,
                              void* d_out, int out_size) {
    const float* x      = (const float*)d_in[0];
    const float* qkv_w  = (const float*)d_in[1];
    const float* qkv_b  = (const float*)d_in[2];
    const float* out_w  = (const float*)d_in[3];
    const float* out_b  = (const float*)d_in[4];
    const float* gates  = (const float*)d_in[5];
    const float* imp    = (const float*)d_in[6];
    const float* thr    = (const float*)d_in[7];
    float* out = (float*)d_out;

    static bool attr_set = false;
    if (!attr_set) {
        cudaFuncSetAttribute(attn_tc_kernel,
                             cudaFuncAttributeMaxDynamicSharedMemorySize, SMEM_ATTN);
        cudaFuncSetAttribute(gemm_bf16_kernel<0>,
                             cudaFuncAttributeMaxDynamicSharedMemorySize, SMEM_GEMM);
        cudaFuncSetAttribute(gemm_bf16_kernel<1>,
                             cudaFuncAttributeMaxDynamicSharedMemorySize, SMEM_GEMM);
        attr_set = true;
    }

    __nv_bfloat16 *xh, *xl, *wh, *wl, *owh, *owl, *aoh, *aol;
    cudaGetSymbolAddress((void**)&xh,  g_xh);
    cudaGetSymbolAddress((void**)&xl,  g_xl);
    cudaGetSymbolAddress((void**)&wh,  g_wh);
    cudaGetSymbolAddress((void**)&wl,  g_wl);
    cudaGetSymbolAddress((void**)&owh, g_owh);
    cudaGetSymbolAddress((void**)&owl, g_owl);
    cudaGetSymbolAddress((void**)&aoh, g_aoh);
    cudaGetSymbolAddress((void**)&aol, g_aol);

    mask_kernel<<<1, 32>>>(gates, imp, thr);

    // operand pre-splits (hi+lo bf16 = same total bytes as fp32 source)
    split_bf16_kernel<<<(MM*EE/4 + 255)/256, 256>>>(x, xh, xl, MM*EE/4);
    split_bf16_kernel<<<(3*EE*EE/4 + 255)/256, 256>>>(qkv_w, wh, wl, 3*EE*EE/4);
    split_bf16_kernel<<<(EE*EE/4 + 255)/256, 256>>>(out_w, owh, owl, EE*EE/4);

    // QKV projection (3-term bf16 split, m16n8k16)
    {
        dim3 g(3 * EE / 128, MM / 128);      // 24 x 32
        gemm_bf16_kernel<0><<<g, 256, SMEM_GEMM>>>(xh, xl, wh, wl, qkv_b, nullptr);
    }

    vmean_kernel<<<BB * HH, 256>>>();

    // Attention (mma.sync tf32, 3-stage ring, 2 CTAs/SM)
    {
        dim3 g(SS / 128, HH, BB);            // 16 x 16 x 2
        attn_tc_kernel<<<g, 256, SMEM_ATTN>>>();
    }

    // Output projection (3-term bf16 split, m16n8k16)
    {
        dim3 g(EE / 128, MM / 128);          // 8 x 32
        gemm_bf16_kernel<1><<<g, 256, SMEM_GEMM>>>(aoh, aol, owh, owl, out_b, out);
    }
}

// round 11
// speedup vs baseline: 1.4800x; 1.0640x over previous
#include <cuda_runtime.h>
#include <cuda_bf16.h>
#include <stdint.h>
#include <math.h>

#define BB 2
#define SS 2048
#define EE 1024
#define HH 16
#define DD 64
#define MM (BB*SS)

// Scratch (static device globals; no runtime allocation)
__device__ float g_q[BB*HH*SS*DD];      // raw fp32 q   [B,H,S,D]
__device__ float g_v[BB*HH*SS*DD];      // tf32-valued fp32, pre-masked
__device__ float g_vmean[BB*HH*DD];
__device__ float g_active[HH];
// bf16 hi/lo K for attention QK
__device__ __align__(16) __nv_bfloat16 g_kh[BB*HH*SS*DD], g_kl[BB*HH*SS*DD];
// bf16 hi/lo operand arrays for bf16 mma GEMMs
__device__ __align__(16) __nv_bfloat16 g_xh[MM*EE],   g_xl[MM*EE];     // x
__device__ __align__(16) __nv_bfloat16 g_wh[3*EE*EE], g_wl[3*EE*EE];   // qkv_w
__device__ __align__(16) __nv_bfloat16 g_owh[EE*EE],  g_owl[EE*EE];    // out_w
__device__ __align__(16) __nv_bfloat16 g_aoh[MM*EE],  g_aol[MM*EE];    // attn out [B,S,H*D]

// ---------------------------------------------------------------------------
// helpers
// ---------------------------------------------------------------------------
__device__ __forceinline__ unsigned f2tf32(float x) {
    unsigned r;
    asm("cvt.rna.tf32.f32 %0, %1;" : "=r"(r) : "f"(x));
    return r;
}
__device__ __forceinline__ float uaf(unsigned u) { return __uint_as_float(u); }

__device__ __forceinline__ void mma_tf32(float c[4], const unsigned a[4], const unsigned b[2]) {
    asm volatile(
        "mma.sync.aligned.m16n8k8.row.col.f32.tf32.tf32.f32 "
        "{%0,%1,%2,%3}, {%4,%5,%6,%7}, {%8,%9}, {%0,%1,%2,%3};"
        : "+f"(c[0]), "+f"(c[1]), "+f"(c[2]), "+f"(c[3])
        : "r"(a[0]), "r"(a[1]), "r"(a[2]), "r"(a[3]),
          "r"(b[0]), "r"(b[1]));
}

// m16n8k16 bf16 mma: same word-level fragment indexing as tf32 k8
__device__ __forceinline__ void mma_bf16(float c[4], const unsigned a[4], const unsigned b[2]) {
    asm volatile(
        "mma.sync.aligned.m16n8k16.row.col.f32.bf16.bf16.f32 "
        "{%0,%1,%2,%3}, {%4,%5,%6,%7}, {%8,%9}, {%0,%1,%2,%3};"
        : "+f"(c[0]), "+f"(c[1]), "+f"(c[2]), "+f"(c[3])
        : "r"(a[0]), "r"(a[1]), "r"(a[2]), "r"(a[3]),
          "r"(b[0]), "r"(b[1]));
}

__device__ __forceinline__ void cp16(unsigned dst, const void* src) {
    asm volatile("cp.async.cg.shared.global [%0], [%1], 16;\n" :: "r"(dst), "l"(src));
}
__device__ __forceinline__ void cp_commit() {
    asm volatile("cp.async.commit_group;\n");
}
__device__ __forceinline__ void cp_wait1() {
    asm volatile("cp.async.wait_group 1;\n");
}

__device__ __forceinline__ unsigned bf2u(__nv_bfloat162 v) {
    return *(unsigned*)&v;
}

// ---------------------------------------------------------------------------
// Head mask
// ---------------------------------------------------------------------------
__global__ void mask_kernel(const float* __restrict__ gates,
                            const float* __restrict__ imp,
                            const float* __restrict__ thr) {
    int h = threadIdx.x;
    if (h < HH) {
        float z  = gates[h] * imp[h];
        float gs = 1.0f / (1.0f + expf(-z));
        g_active[h] = (gs > thr[0]) ? 1.0f : 0.0f;
    }
}

// ---------------------------------------------------------------------------
// bf16 hi/lo split: h = bf16(x), l = bf16(x - h)
// ---------------------------------------------------------------------------
__global__ void split_bf16_kernel(const float* __restrict__ src,
                                  __nv_bfloat16* __restrict__ h,
                                  __nv_bfloat16* __restrict__ l, int n4) {
    int i = blockIdx.x * blockDim.x + threadIdx.x;
    if (i < n4) {
        float4 v = ((const float4*)src)[i];
        __nv_bfloat162 h01 = __floats2bfloat162_rn(v.x, v.y);
        __nv_bfloat162 h23 = __floats2bfloat162_rn(v.z, v.w);
        *(__nv_bfloat162*)(h + 4 * (size_t)i)     = h01;
        *(__nv_bfloat162*)(h + 4 * (size_t)i + 2) = h23;
        __nv_bfloat162 l01 = __floats2bfloat162_rn(
            v.x - __bfloat162float(h01.x), v.y - __bfloat162float(h01.y));
        __nv_bfloat162 l23 = __floats2bfloat162_rn(
            v.z - __bfloat162float(h23.x), v.w - __bfloat162float(h23.y));
        *(__nv_bfloat162*)(l + 4 * (size_t)i)     = l01;
        *(__nv_bfloat162*)(l + 4 * (size_t)i + 2) = l23;
    }
}

// ---------------------------------------------------------------------------
// 3-term bf16-split GEMM on mma.sync.m16n8k16 (validated round-10 kernel):
// C[m,n] = sum_k A[m,k]*B[n,k] + bias[n]
// MODE 0: qkv scatter epilogue. MODE 1: row-major write.
// ---------------------------------------------------------------------------
#define GSTR  20                    // words per smem row (16 + 4 pad)
#define GARR  (128 * GSTR)          // words per operand array
#define GSTG  (4 * GARR)            // Ah|Al|Bh|Bl per stage
#define SMEM_GEMM (2 * GSTG * 4)    // 81920 B

template <int MODE>
__global__ void __launch_bounds__(256, 2) gemm_bf16_kernel(
    const __nv_bfloat16* __restrict__ Ahg, const __nv_bfloat16* __restrict__ Alg,
    const __nv_bfloat16* __restrict__ Bhg, const __nv_bfloat16* __restrict__ Blg,
    const float* __restrict__ bias, float* __restrict__ Y) {
    extern __shared__ unsigned gsm[];

    const int m0 = blockIdx.y * 128;
    const int n0 = blockIdx.x * 128;

    if (MODE == 0) {
        const int hA = (n0 & 1023) >> 6;
        if (g_active[hA] == 0.0f && g_active[hA + 1] == 0.0f) return;
    }

    const int tid  = threadIdx.x;
    const int lane = tid & 31;
    const int warp = tid >> 5;
    const int wm = (warp >> 2) * 64;
    const int wn = (warp & 3) * 32;
    const int grp = lane >> 2;
    const int tig = lane & 3;

    const int grow = tid >> 1;          // 0..127
    const int gkw  = (tid & 1) * 8;     // word offset 0 or 8 (=16 bf16)
    const __nv_bfloat16* Aph = Ahg + (size_t)(m0 + grow) * EE + gkw * 2;
    const __nv_bfloat16* Apl = Alg + (size_t)(m0 + grow) * EE + gkw * 2;
    const __nv_bfloat16* Bph = Bhg + (size_t)(n0 + grow) * EE + gkw * 2;
    const __nv_bfloat16* Bpl = Blg + (size_t)(n0 + grow) * EE + gkw * 2;

    float acc[4][4][4];
#pragma unroll
    for (int i = 0; i < 4; i++)
#pragma unroll
        for (int j = 0; j < 4; j++)
#pragma unroll
            for (int r = 0; r < 4; r++) acc[i][j][r] = 0.f;

    auto store_stage = [&](int st, const uint4 p[8]) {
        unsigned* base = gsm + st * GSTG + grow * GSTR + gkw;
        *(uint4*)(base)                = p[0];
        *(uint4*)(base + 4)            = p[1];
        *(uint4*)(base + GARR)         = p[2];
        *(uint4*)(base + GARR + 4)     = p[3];
        *(uint4*)(base + 2 * GARR)     = p[4];
        *(uint4*)(base + 2 * GARR + 4) = p[5];
        *(uint4*)(base + 3 * GARR)     = p[6];
        *(uint4*)(base + 3 * GARR + 4) = p[7];
    };
    auto load_tile = [&](int kt, uint4 p[8]) {
        const size_t o = (size_t)kt * 32;
        p[0] = *(const uint4*)(Aph + o);  p[1] = *(const uint4*)(Aph + o + 8);
        p[2] = *(const uint4*)(Apl + o);  p[3] = *(const uint4*)(Apl + o + 8);
        p[4] = *(const uint4*)(Bph + o);  p[5] = *(const uint4*)(Bph + o + 8);
        p[6] = *(const uint4*)(Bpl + o);  p[7] = *(const uint4*)(Bpl + o + 8);
    };

    {
        uint4 p[8];
        load_tile(0, p);
        store_stage(0, p);
    }
    __syncthreads();

    const int NT = EE / 32;  // 32 k-tiles
    for (int kt = 0; kt < NT; kt++) {
        uint4 p[8];
        if (kt + 1 < NT) load_tile(kt + 1, p);

        const unsigned* Ah = gsm + (kt & 1) * GSTG;
        const unsigned* Al = Ah + GARR;
        const unsigned* Bh = Al + GARR;
        const unsigned* Bl = Bh + GARR;

#pragma unroll
        for (int ks = 0; ks < 2; ks++) {
            const int kq = ks * 8 + tig;
            unsigned ah[4][4], al[4][4];
#pragma unroll
            for (int mi = 0; mi < 4; mi++) {
                const int mr = wm + mi * 16 + grp;
                ah[mi][0] = Ah[mr * GSTR + kq];       ah[mi][1] = Ah[(mr + 8) * GSTR + kq];
                ah[mi][2] = Ah[mr * GSTR + kq + 4];   ah[mi][3] = Ah[(mr + 8) * GSTR + kq + 4];
                al[mi][0] = Al[mr * GSTR + kq];       al[mi][1] = Al[(mr + 8) * GSTR + kq];
                al[mi][2] = Al[mr * GSTR + kq + 4];   al[mi][3] = Al[(mr + 8) * GSTR + kq + 4];
            }
            unsigned bh[4][2], bl[4][2];
#pragma unroll
            for (int ni = 0; ni < 4; ni++) {
                const int nr = wn + ni * 8 + grp;
                bh[ni][0] = Bh[nr * GSTR + kq]; bh[ni][1] = Bh[nr * GSTR + kq + 4];
                bl[ni][0] = Bl[nr * GSTR + kq]; bl[ni][1] = Bl[nr * GSTR + kq + 4];
            }
#pragma unroll
            for (int mi = 0; mi < 4; mi++)
#pragma unroll
                for (int ni = 0; ni < 4; ni++) {
                    mma_bf16(acc[mi][ni], ah[mi], bh[ni]);
                    mma_bf16(acc[mi][ni], al[mi], bh[ni]);
                    mma_bf16(acc[mi][ni], ah[mi], bl[ni]);
                }
        }

        if (kt + 1 < NT) store_stage((kt + 1) & 1, p);
        __syncthreads();
    }

    // epilogue
#pragma unroll
    for (int mi = 0; mi < 4; mi++) {
        const int rbase = m0 + wm + mi * 16 + grp;
#pragma unroll
        for (int ni = 0; ni < 4; ni++) {
            const int j = n0 + wn + ni * 8 + 2 * tig;
            const float b0 = bias[j], b1 = bias[j + 1];
#pragma unroll
            for (int rh = 0; rh < 2; rh++) {
                const int m = rbase + rh * 8;
                const float v0 = acc[mi][ni][rh * 2 + 0] + b0;
                const float v1 = acc[mi][ni][rh * 2 + 1] + b1;
                if (MODE == 1) {
                    float2 o; o.x = v0; o.y = v1;
                    *(float2*)(Y + (size_t)m * EE + j) = o;
                } else {
                    const int cc  = j >> 10;
                    const int rem = j & 1023;
                    const int h = rem >> 6, d = rem & 63;
                    const int bI = m >> 11;
                    const int s  = m & (SS - 1);
                    const size_t off = (((size_t)(bI * HH + h)) * SS + s) * DD + d;
                    if (cc == 0) {
                        float2 o; o.x = v0; o.y = v1;       // q raw
                        *(float2*)(g_q + off) = o;
                    } else if (cc == 1) {
                        // k as bf16 hi/lo (16-bit effective precision)
                        __nv_bfloat162 kh = __floats2bfloat162_rn(v0, v1);
                        __nv_bfloat162 kl = __floats2bfloat162_rn(
                            v0 - __bfloat162float(kh.x), v1 - __bfloat162float(kh.y));
                        *(__nv_bfloat162*)(g_kh + off) = kh;
                        *(__nv_bfloat162*)(g_kl + off) = kl;
                    } else {
                        const float am = g_active[h];
                        float2 o;
                        o.x = uaf(f2tf32(v0 * am));         // v masked + tf32-rounded
                        o.y = uaf(f2tf32(v1 * am));
                        *(float2*)(g_v + off) = o;
                    }
                }
            }
        }
    }
}

// ---------------------------------------------------------------------------
// vmean[b,h,d] = mean_s v[b,h,s,d]  (float4 loads, skip inactive heads)
// ---------------------------------------------------------------------------
__global__ void vmean_kernel() {
    const int bh = blockIdx.x;
    if (g_active[bh & (HH - 1)] == 0.0f) return;
    const int d4    = (threadIdx.x & 15) * 4;
    const int chunk = threadIdx.x >> 4;
    const size_t base = (size_t)bh * SS * DD;
    float4 sum = {0.f, 0.f, 0.f, 0.f};
    for (int s = chunk * 128; s < (chunk + 1) * 128; s++) {
        float4 t = *(const float4*)(g_v + base + (size_t)s * DD + d4);
        sum.x += t.x; sum.y += t.y; sum.z += t.z; sum.w += t.w;
    }
    __shared__ float4 red[256];
    red[threadIdx.x] = sum;
    __syncthreads();
    if (chunk == 0) {
        float4 t = {0.f, 0.f, 0.f, 0.f};
#pragma unroll
        for (int c = 0; c < 16; c++) {
            float4 r = red[c * 16 + (threadIdx.x & 15)];
            t.x += r.x; t.y += r.y; t.z += r.z; t.w += r.w;
        }
        const float inv = 1.0f / SS;
        t.x *= inv; t.y *= inv; t.z *= inv; t.w *= inv;
        *(float4*)(g_vmean + bh * DD + d4) = t;
    }
}

// ---------------------------------------------------------------------------
// Tensor-core flash attention, v5:
//  - QK on bf16 m16n8k16, 3-term (QhKh + QlKh + QhKl); K arrives as bf16 hi/lo
//  - Q hi/lo fragments precomputed ONCE per CTA (32 packed bf16x2 regs)
//  - PV unchanged: tf32 1-term, register-P permuted k-slots
//  - 3-stage cp.async ring, 1 barrier/tile, 2 CTAs/SM
// ---------------------------------------------------------------------------
#define KSTRW 36                       // words per Kh/Kl row (32 + 4 pad)
#define TKHW  (64 * KSTRW)             // words per Kh (or Kl) tile
#define VSTR  68
#define TVW   (64 * VSTR)
#define BUFW  (2 * TKHW + TVW)         // 8960 words
#define NSTG  3
#define SMEM_ATTN (NSTG * BUFW * 4)    // 107520 B

__global__ void __launch_bounds__(256, 2) attn_tc_kernel() {
    extern __shared__ float sh[];

    const int tid  = threadIdx.x;
    const int lane = tid & 31;
    const int warp = tid >> 5;
    const int g8   = lane >> 2;
    const int tig  = lane & 3;
    const int wr   = warp * 16;

    const int b = blockIdx.z, h = blockIdx.y;
    const int q0 = blockIdx.x * 128;
    const size_t bh = (size_t)(b * HH + h) * SS * DD;

    if (g_active[h] == 0.0f) {
        const uint4 z = {0u, 0u, 0u, 0u};
        for (int i = tid; i < 128 * 8; i += 256) {
            const int r = i >> 3, c = (i & 7) * 8;
            const size_t off = ((size_t)(b * SS + q0 + r) * HH + h) * DD + c;
            *(uint4*)(g_aoh + off) = z;
            *(uint4*)(g_aol + off) = z;
        }
        return;
    }

    const unsigned sbase = (unsigned)__cvta_generic_to_shared(sh);

    // Q bf16 hi/lo fragments, packed bf16x2, computed once (32 regs)
    unsigned qh[4][4], ql[4][4];
#pragma unroll
    for (int ks = 0; ks < 4; ks++) {
        const int r0 = q0 + wr + g8;
        const int k0 = ks * 16 + 2 * tig;
        const float* qr0 = g_q + bh + (size_t)r0 * DD;
        const float* qr1 = g_q + bh + (size_t)(r0 + 8) * DD;
        float a0 = qr0[k0],     a1 = qr0[k0 + 1];
        float b0 = qr1[k0],     b1 = qr1[k0 + 1];
        float c0 = qr0[k0 + 8], c1 = qr0[k0 + 9];
        float d0 = qr1[k0 + 8], d1 = qr1[k0 + 9];
        __nv_bfloat162 ha = __floats2bfloat162_rn(a0, a1);
        __nv_bfloat162 hb = __floats2bfloat162_rn(b0, b1);
        __nv_bfloat162 hc = __floats2bfloat162_rn(c0, c1);
        __nv_bfloat162 hd = __floats2bfloat162_rn(d0, d1);
        qh[ks][0] = bf2u(ha); qh[ks][1] = bf2u(hb);
        qh[ks][2] = bf2u(hc); qh[ks][3] = bf2u(hd);
        ql[ks][0] = bf2u(__floats2bfloat162_rn(a0 - __bfloat162float(ha.x),
                                               a1 - __bfloat162float(ha.y)));
        ql[ks][1] = bf2u(__floats2bfloat162_rn(b0 - __bfloat162float(hb.x),
                                               b1 - __bfloat162float(hb.y)));
        ql[ks][2] = bf2u(__floats2bfloat162_rn(c0 - __bfloat162float(hc.x),
                                               c1 - __bfloat162float(hc.y)));
        ql[ks][3] = bf2u(__floats2bfloat162_rn(d0 - __bfloat162float(hd.x),
                                               d1 - __bfloat162float(hd.y)));
    }

    float o[8][4];
#pragma unroll
    for (int i = 0; i < 8; i++)
#pragma unroll
        for (int j = 0; j < 4; j++) o[i][j] = 0.f;
    float m0 = -1e30f, m1 = -1e30f, l0 = 0.f, l1 = 0.f;

    auto issue_tile = [&](int kvt, int st) {
        const int row = tid >> 2;       // 0..63
        const int t4  = tid & 3;
        const __nv_bfloat16* khp = g_kh + bh + (size_t)(kvt * 64 + row) * DD + t4 * 16;
        const __nv_bfloat16* klp = g_kl + bh + (size_t)(kvt * 64 + row) * DD + t4 * 16;
        const float* vp = g_v + bh + (size_t)(kvt * 64 + row) * DD + t4 * 16;
        const unsigned khd = sbase + (st * BUFW + row * KSTRW + t4 * 8) * 4;
        const unsigned kld = khd + TKHW * 4;
        const unsigned vd  = sbase + (st * BUFW + 2 * TKHW + row * VSTR + t4 * 16) * 4;
        cp16(khd,      khp);
        cp16(khd + 16, khp + 8);
        cp16(kld,      klp);
        cp16(kld + 16, klp + 8);
#pragma unroll
        for (int c = 0; c < 4; c++)
            cp16(vd + 16 * c, vp + 4 * c);
    };

    issue_tile(0, 0); cp_commit();
    issue_tile(1, 1); cp_commit();

    const int NTILE = SS / 64;
    int stage = 0;
    for (int t = 0; t < NTILE; t++) {
        cp_wait1();
        __syncthreads();

        if (t + 2 < NTILE) {
            int st2 = stage + 2; if (st2 >= NSTG) st2 -= NSTG;
            issue_tile(t + 2, st2);
        }
        cp_commit();

        const unsigned* Kh = (const unsigned*)(sh + stage * BUFW);
        const unsigned* Kl = Kh + TKHW;
        const unsigned* Vu = Kh + 2 * TKHW;

        // ---- QK: bf16 3-term, 4 k16 steps x 8 n-tiles ----
        float c[8][4];
#pragma unroll
        for (int i = 0; i < 8; i++)
#pragma unroll
            for (int j = 0; j < 4; j++) c[i][j] = 0.f;
#pragma unroll
        for (int ks = 0; ks < 4; ks++) {
            const int kq = ks * 8 + tig;
#pragma unroll
            for (int nt = 0; nt < 8; nt++) {
                const int rw = (nt * 8 + g8) * KSTRW;
                unsigned bhv[2], blv[2];
                bhv[0] = Kh[rw + kq]; bhv[1] = Kh[rw + kq + 4];
                blv[0] = Kl[rw + kq]; blv[1] = Kl[rw + kq + 4];
                mma_bf16(c[nt], qh[ks], bhv);
                mma_bf16(c[nt], ql[ks], bhv);
                mma_bf16(c[nt], qh[ks], blv);
            }
        }

        // ---- online softmax; P rounded in-place into c ----
        float mx0 = c[0][0], mx1 = c[0][2];
#pragma unroll
        for (int nt = 0; nt < 8; nt++) {
            mx0 = fmaxf(mx0, fmaxf(c[nt][0], c[nt][1]));
            mx1 = fmaxf(mx1, fmaxf(c[nt][2], c[nt][3]));
        }
        mx0 = fmaxf(mx0, __shfl_xor_sync(0xffffffffu, mx0, 1));
        mx0 = fmaxf(mx0, __shfl_xor_sync(0xffffffffu, mx0, 2));
        mx1 = fmaxf(mx1, __shfl_xor_sync(0xffffffffu, mx1, 1));
        mx1 = fmaxf(mx1, __shfl_xor_sync(0xffffffffu, mx1, 2));
        const float mn0 = fmaxf(m0, mx0);
        const float mn1 = fmaxf(m1, mx1);
        const float sc0 = __expf(m0 - mn0);
        const float sc1 = __expf(m1 - mn1);
        m0 = mn0; m1 = mn1;
#pragma unroll
        for (int dt = 0; dt < 8; dt++) {
            o[dt][0] *= sc0; o[dt][1] *= sc0;
            o[dt][2] *= sc1; o[dt][3] *= sc1;
        }
        float s0 = 0.f, s1 = 0.f;
#pragma unroll
        for (int nt = 0; nt < 8; nt++) {
            const float p00 = uaf(f2tf32(__expf(c[nt][0] - m0)));
            const float p01 = uaf(f2tf32(__expf(c[nt][1] - m0)));
            const float p10 = uaf(f2tf32(__expf(c[nt][2] - m1)));
            const float p11 = uaf(f2tf32(__expf(c[nt][3] - m1)));
            s0 += p00 + p01;
            s1 += p10 + p11;
            c[nt][0] = p00; c[nt][1] = p01;
            c[nt][2] = p10; c[nt][3] = p11;
        }
        s0 += __shfl_xor_sync(0xffffffffu, s0, 1);
        s0 += __shfl_xor_sync(0xffffffffu, s0, 2);
        s1 += __shfl_xor_sync(0xffffffffu, s1, 1);
        s1 += __shfl_xor_sync(0xffffffffu, s1, 2);
        l0 = l0 * sc0 + s0;
        l1 = l1 * sc1 + s1;

        // ---- PV, tf32, permuted k-slots; A-frag = own accumulator bits ----
#pragma unroll
        for (int ks = 0; ks < 8; ks++) {
            unsigned aa[4] = {__float_as_uint(c[ks][0]), __float_as_uint(c[ks][2]),
                              __float_as_uint(c[ks][1]), __float_as_uint(c[ks][3])};
            const int vr0 = (ks * 8 + 2 * tig) * VSTR;
#pragma unroll
            for (int dt = 0; dt < 8; dt++) {
                unsigned bb[2];
                bb[0] = Vu[vr0 + dt * 8 + g8];
                bb[1] = Vu[vr0 + VSTR + dt * 8 + g8];
                mma_tf32(o[dt], aa, bb);
            }
        }

        stage = (stage + 1 == NSTG) ? 0 : stage + 1;
    }

    // epilogue: normalize, add vmean, emit bf16 hi/lo for out-projection
    const float inv0 = 1.0f / l0;
    const float inv1 = 1.0f / l1;
    const int r0 = q0 + wr + g8;
    const size_t ob0 = ((size_t)(b * SS + r0) * HH + h) * DD;
    const size_t ob1 = ((size_t)(b * SS + r0 + 8) * HH + h) * DD;
    const float* vm = g_vmean + (size_t)(b * HH + h) * DD;
#pragma unroll
    for (int dt = 0; dt < 8; dt++) {
        const int col = dt * 8 + 2 * tig;
        const float v0 = vm[col], v1 = vm[col + 1];
        const float f00 = o[dt][0] * inv0 + v0, f01 = o[dt][1] * inv0 + v1;
        const float f10 = o[dt][2] * inv1 + v0, f11 = o[dt][3] * inv1 + v1;
        __nv_bfloat162 h0 = __floats2bfloat162_rn(f00, f01);
        __nv_bfloat162 h1 = __floats2bfloat162_rn(f10, f11);
        __nv_bfloat162 lo0 = __floats2bfloat162_rn(
            f00 - __bfloat162float(h0.x), f01 - __bfloat162float(h0.y));
        __nv_bfloat162 lo1 = __floats2bfloat162_rn(
            f10 - __bfloat162float(h1.x), f11 - __bfloat162float(h1.y));
        *(__nv_bfloat162*)(g_aoh + ob0 + col) = h0;
        *(__nv_bfloat162*)(g_aol + ob0 + col) = lo0;
        *(__nv_bfloat162*)(g_aoh + ob1 + col) = h1;
        *(__nv_bfloat162*)(g_aol + ob1 + col) = lo1;
    }
}

// ---------------------------------------------------------------------------
extern "C" void kernel_launch(void* const* d_in, const int* in_sizes, int n_in,
                              void* d_out, int out_size) {
    const float* x      = (const float*)d_in[0];
    const float* qkv_w  = (const float*)d_in[1];
    const float* qkv_b  = (const float*)d_in[2];
    const float* out_w  = (const float*)d_in[3];
    const float* out_b  = (const float*)d_in[4];
    const float* gates  = (const float*)d_in[5];
    const float* imp    = (const float*)d_in[6];
    const float* thr    = (const float*)d_in[7];
    float* out = (float*)d_out;

    static bool attr_set = false;
    if (!attr_set) {
        cudaFuncSetAttribute(attn_tc_kernel,
                             cudaFuncAttributeMaxDynamicSharedMemorySize, SMEM_ATTN);
        cudaFuncSetAttribute(gemm_bf16_kernel<0>,
                             cudaFuncAttributeMaxDynamicSharedMemorySize, SMEM_GEMM);
        cudaFuncSetAttribute(gemm_bf16_kernel<1>,
                             cudaFuncAttributeMaxDynamicSharedMemorySize, SMEM_GEMM);
        attr_set = true;
    }

    __nv_bfloat16 *xh, *xl, *wh, *wl, *owh, *owl, *aoh, *aol;
    cudaGetSymbolAddress((void**)&xh,  g_xh);
    cudaGetSymbolAddress((void**)&xl,  g_xl);
    cudaGetSymbolAddress((void**)&wh,  g_wh);
    cudaGetSymbolAddress((void**)&wl,  g_wl);
    cudaGetSymbolAddress((void**)&owh, g_owh);
    cudaGetSymbolAddress((void**)&owl, g_owl);
    cudaGetSymbolAddress((void**)&aoh, g_aoh);
    cudaGetSymbolAddress((void**)&aol, g_aol);

    mask_kernel<<<1, 32>>>(gates, imp, thr);

    // operand pre-splits (hi+lo bf16 = same total bytes as fp32 source)
    split_bf16_kernel<<<(MM*EE/4 + 255)/256, 256>>>(x, xh, xl, MM*EE/4);
    split_bf16_kernel<<<(3*EE*EE/4 + 255)/256, 256>>>(qkv_w, wh, wl, 3*EE*EE/4);
    split_bf16_kernel<<<(EE*EE/4 + 255)/256, 256>>>(out_w, owh, owl, EE*EE/4);

    // QKV projection (3-term bf16 split, m16n8k16)
    {
        dim3 g(3 * EE / 128, MM / 128);      // 24 x 32
        gemm_bf16_kernel<0><<<g, 256, SMEM_GEMM>>>(xh, xl, wh, wl, qkv_b, nullptr);
    }

    vmean_kernel<<<BB * HH, 256>>>();

    // Attention (bf16 QK 3-term + tf32 PV, 3-stage ring, 2 CTAs/SM)
    {
        dim3 g(SS / 128, HH, BB);            // 16 x 16 x 2
        attn_tc_kernel<<<g, 256, SMEM_ATTN>>>();
    }

    // Output projection (3-term bf16 split, m16n8k16)
    {
        dim3 g(EE / 128, MM / 128);          // 8 x 32
        gemm_bf16_kernel<1><<<g, 256, SMEM_GEMM>>>(aoh, aol, owh, owl, out_b, out);
    }
}

// round 12
// speedup vs baseline: 1.6503x; 1.1150x over previous
#include <cuda_runtime.h>
#include <cuda_bf16.h>
#include <stdint.h>
#include <math.h>

#define BB 2
#define SS 2048
#define EE 1024
#define HH 16
#define DD 64
#define MM (BB*SS)

// Scratch (static device globals; no runtime allocation)
__device__ float g_q[BB*HH*SS*DD];      // raw fp32 q   [B,H,S,D]
__device__ float g_v[BB*HH*SS*DD];      // tf32-valued fp32, pre-masked
__device__ float g_vmean[BB*HH*DD];
__device__ float g_active[HH];
// bf16 hi/lo K for attention QK
__device__ __align__(16) __nv_bfloat16 g_kh[BB*HH*SS*DD], g_kl[BB*HH*SS*DD];
// bf16 hi/lo operand arrays for bf16 mma GEMMs
__device__ __align__(16) __nv_bfloat16 g_xh[MM*EE],   g_xl[MM*EE];     // x
__device__ __align__(16) __nv_bfloat16 g_wh[3*EE*EE], g_wl[3*EE*EE];   // qkv_w
__device__ __align__(16) __nv_bfloat16 g_owh[EE*EE],  g_owl[EE*EE];    // out_w
__device__ __align__(16) __nv_bfloat16 g_aoh[MM*EE],  g_aol[MM*EE];    // attn out [B,S,H*D]

// ---------------------------------------------------------------------------
// helpers
// ---------------------------------------------------------------------------
__device__ __forceinline__ unsigned f2tf32(float x) {
    unsigned r;
    asm("cvt.rna.tf32.f32 %0, %1;" : "=r"(r) : "f"(x));
    return r;
}
__device__ __forceinline__ float uaf(unsigned u) { return __uint_as_float(u); }

__device__ __forceinline__ void mma_tf32(float c[4], const unsigned a[4], const unsigned b[2]) {
    asm volatile(
        "mma.sync.aligned.m16n8k8.row.col.f32.tf32.tf32.f32 "
        "{%0,%1,%2,%3}, {%4,%5,%6,%7}, {%8,%9}, {%0,%1,%2,%3};"
        : "+f"(c[0]), "+f"(c[1]), "+f"(c[2]), "+f"(c[3])
        : "r"(a[0]), "r"(a[1]), "r"(a[2]), "r"(a[3]),
          "r"(b[0]), "r"(b[1]));
}

// m16n8k16 bf16 mma: same word-level fragment indexing as tf32 k8
__device__ __forceinline__ void mma_bf16(float c[4], const unsigned a[4], const unsigned b[2]) {
    asm volatile(
        "mma.sync.aligned.m16n8k16.row.col.f32.bf16.bf16.f32 "
        "{%0,%1,%2,%3}, {%4,%5,%6,%7}, {%8,%9}, {%0,%1,%2,%3};"
        : "+f"(c[0]), "+f"(c[1]), "+f"(c[2]), "+f"(c[3])
        : "r"(a[0]), "r"(a[1]), "r"(a[2]), "r"(a[3]),
          "r"(b[0]), "r"(b[1]));
}

__device__ __forceinline__ void ldsm4(unsigned &r0, unsigned &r1, unsigned &r2,
                                      unsigned &r3, unsigned addr) {
    asm volatile("ldmatrix.sync.aligned.m8n8.x4.shared.b16 {%0,%1,%2,%3}, [%4];"
                 : "=r"(r0), "=r"(r1), "=r"(r2), "=r"(r3) : "r"(addr));
}

__device__ __forceinline__ void cp16(unsigned dst, const void* src) {
    asm volatile("cp.async.cg.shared.global [%0], [%1], 16;\n" :: "r"(dst), "l"(src));
}
__device__ __forceinline__ void cp_commit() {
    asm volatile("cp.async.commit_group;\n");
}
__device__ __forceinline__ void cp_wait1() {
    asm volatile("cp.async.wait_group 1;\n");
}

__device__ __forceinline__ unsigned bf2u(__nv_bfloat162 v) {
    return *(unsigned*)&v;
}

// ---------------------------------------------------------------------------
// Head mask
// ---------------------------------------------------------------------------
__global__ void mask_kernel(const float* __restrict__ gates,
                            const float* __restrict__ imp,
                            const float* __restrict__ thr) {
    int h = threadIdx.x;
    if (h < HH) {
        float z  = gates[h] * imp[h];
        float gs = 1.0f / (1.0f + expf(-z));
        g_active[h] = (gs > thr[0]) ? 1.0f : 0.0f;
    }
}

// ---------------------------------------------------------------------------
// bf16 hi/lo split: h = bf16(x), l = bf16(x - h)
// ---------------------------------------------------------------------------
__global__ void split_bf16_kernel(const float* __restrict__ src,
                                  __nv_bfloat16* __restrict__ h,
                                  __nv_bfloat16* __restrict__ l, int n4) {
    int i = blockIdx.x * blockDim.x + threadIdx.x;
    if (i < n4) {
        float4 v = ((const float4*)src)[i];
        __nv_bfloat162 h01 = __floats2bfloat162_rn(v.x, v.y);
        __nv_bfloat162 h23 = __floats2bfloat162_rn(v.z, v.w);
        *(__nv_bfloat162*)(h + 4 * (size_t)i)     = h01;
        *(__nv_bfloat162*)(h + 4 * (size_t)i + 2) = h23;
        __nv_bfloat162 l01 = __floats2bfloat162_rn(
            v.x - __bfloat162float(h01.x), v.y - __bfloat162float(h01.y));
        __nv_bfloat162 l23 = __floats2bfloat162_rn(
            v.z - __bfloat162float(h23.x), v.w - __bfloat162float(h23.y));
        *(__nv_bfloat162*)(l + 4 * (size_t)i)     = l01;
        *(__nv_bfloat162*)(l + 4 * (size_t)i + 2) = l23;
    }
}

// ---------------------------------------------------------------------------
// 3-term bf16-split GEMM on mma.sync.m16n8k16, ldmatrix fragment loads.
// C[m,n] = sum_k A[m,k]*B[n,k] + bias[n]
// MODE 0: qkv scatter epilogue. MODE 1: row-major write.
// ---------------------------------------------------------------------------
#define GSTR  20                    // words per smem row (16 + 4 pad)
#define GARR  (128 * GSTR)          // words per operand array
#define GSTG  (4 * GARR)            // Ah|Al|Bh|Bl per stage
#define SMEM_GEMM (2 * GSTG * 4)    // 81920 B

template <int MODE>
__global__ void __launch_bounds__(256, 2) gemm_bf16_kernel(
    const __nv_bfloat16* __restrict__ Ahg, const __nv_bfloat16* __restrict__ Alg,
    const __nv_bfloat16* __restrict__ Bhg, const __nv_bfloat16* __restrict__ Blg,
    const float* __restrict__ bias, float* __restrict__ Y) {
    extern __shared__ unsigned gsm[];

    const int m0 = blockIdx.y * 128;
    const int n0 = blockIdx.x * 128;

    if (MODE == 0) {
        const int hA = (n0 & 1023) >> 6;
        if (g_active[hA] == 0.0f && g_active[hA + 1] == 0.0f) return;
    }

    const int tid  = threadIdx.x;
    const int lane = tid & 31;
    const int warp = tid >> 5;
    const int wm = (warp >> 2) * 64;
    const int wn = (warp & 3) * 32;
    const int grp = lane >> 2;
    const int tig = lane & 3;

    const int grow = tid >> 1;          // 0..127
    const int gkw  = (tid & 1) * 8;     // word offset 0 or 8 (=16 bf16)
    const __nv_bfloat16* Aph = Ahg + (size_t)(m0 + grow) * EE + gkw * 2;
    const __nv_bfloat16* Apl = Alg + (size_t)(m0 + grow) * EE + gkw * 2;
    const __nv_bfloat16* Bph = Bhg + (size_t)(n0 + grow) * EE + gkw * 2;
    const __nv_bfloat16* Bpl = Blg + (size_t)(n0 + grow) * EE + gkw * 2;

    // ldmatrix lane mapping (verified: d0=[grp][tig], d1=[grp+8][tig],
    // d2=[grp][tig+4], d3=[grp+8][tig+4] for A; B covers ni pair per x4)
    const unsigned gb = (unsigned)__cvta_generic_to_shared(gsm);
    const int seg = lane >> 3, lr8 = lane & 7;
    const int arow = wm + (seg & 1) * 8 + lr8;   // + mi*16
    const int acol = (seg >> 1) * 4;             // + ks*8
    const int brow = wn + (seg >> 1) * 8 + lr8;  // + np*16
    const int bcol = (seg & 1) * 4;              // + ks*8

    float acc[4][4][4];
#pragma unroll
    for (int i = 0; i < 4; i++)
#pragma unroll
        for (int j = 0; j < 4; j++)
#pragma unroll
            for (int r = 0; r < 4; r++) acc[i][j][r] = 0.f;

    auto store_stage = [&](int st, const uint4 p[8]) {
        unsigned* base = gsm + st * GSTG + grow * GSTR + gkw;
        *(uint4*)(base)                = p[0];
        *(uint4*)(base + 4)            = p[1];
        *(uint4*)(base + GARR)         = p[2];
        *(uint4*)(base + GARR + 4)     = p[3];
        *(uint4*)(base + 2 * GARR)     = p[4];
        *(uint4*)(base + 2 * GARR + 4) = p[5];
        *(uint4*)(base + 3 * GARR)     = p[6];
        *(uint4*)(base + 3 * GARR + 4) = p[7];
    };
    auto load_tile = [&](int kt, uint4 p[8]) {
        const size_t o = (size_t)kt * 32;
        p[0] = *(const uint4*)(Aph + o);  p[1] = *(const uint4*)(Aph + o + 8);
        p[2] = *(const uint4*)(Apl + o);  p[3] = *(const uint4*)(Apl + o + 8);
        p[4] = *(const uint4*)(Bph + o);  p[5] = *(const uint4*)(Bph + o + 8);
        p[6] = *(const uint4*)(Bpl + o);  p[7] = *(const uint4*)(Bpl + o + 8);
    };

    {
        uint4 p[8];
        load_tile(0, p);
        store_stage(0, p);
    }
    __syncthreads();

    const int NT = EE / 32;  // 32 k-tiles
    for (int kt = 0; kt < NT; kt++) {
        uint4 p[8];
        if (kt + 1 < NT) load_tile(kt + 1, p);

        const unsigned stb = gb + ((kt & 1) * GSTG) * 4;

#pragma unroll
        for (int ks = 0; ks < 2; ks++) {
            const int kw = ks * 8;
            unsigned bh[4][2], bl[4][2];
#pragma unroll
            for (int np = 0; np < 2; np++) {
                const unsigned addr =
                    stb + (2 * GARR + (brow + np * 16) * GSTR + kw + bcol) * 4;
                ldsm4(bh[2*np][0], bh[2*np][1], bh[2*np+1][0], bh[2*np+1][1], addr);
                ldsm4(bl[2*np][0], bl[2*np][1], bl[2*np+1][0], bl[2*np+1][1],
                      addr + GARR * 4);
            }
#pragma unroll
            for (int mi = 0; mi < 4; mi++) {
                unsigned ah[4], al[4];
                const unsigned addr =
                    stb + ((arow + mi * 16) * GSTR + kw + acol) * 4;
                ldsm4(ah[0], ah[1], ah[2], ah[3], addr);
                ldsm4(al[0], al[1], al[2], al[3], addr + GARR * 4);
#pragma unroll
                for (int ni = 0; ni < 4; ni++) {
                    mma_bf16(acc[mi][ni], ah, bh[ni]);
                    mma_bf16(acc[mi][ni], al, bh[ni]);
                    mma_bf16(acc[mi][ni], ah, bl[ni]);
                }
            }
        }

        if (kt + 1 < NT) store_stage((kt + 1) & 1, p);
        __syncthreads();
    }

    // epilogue
#pragma unroll
    for (int mi = 0; mi < 4; mi++) {
        const int rbase = m0 + wm + mi * 16 + grp;
#pragma unroll
        for (int ni = 0; ni < 4; ni++) {
            const int j = n0 + wn + ni * 8 + 2 * tig;
            const float b0 = bias[j], b1 = bias[j + 1];
#pragma unroll
            for (int rh = 0; rh < 2; rh++) {
                const int m = rbase + rh * 8;
                const float v0 = acc[mi][ni][rh * 2 + 0] + b0;
                const float v1 = acc[mi][ni][rh * 2 + 1] + b1;
                if (MODE == 1) {
                    float2 o; o.x = v0; o.y = v1;
                    *(float2*)(Y + (size_t)m * EE + j) = o;
                } else {
                    const int cc  = j >> 10;
                    const int rem = j & 1023;
                    const int h = rem >> 6, d = rem & 63;
                    const int bI = m >> 11;
                    const int s  = m & (SS - 1);
                    const size_t off = (((size_t)(bI * HH + h)) * SS + s) * DD + d;
                    if (cc == 0) {
                        float2 o; o.x = v0; o.y = v1;       // q raw
                        *(float2*)(g_q + off) = o;
                    } else if (cc == 1) {
                        __nv_bfloat162 kh = __floats2bfloat162_rn(v0, v1);
                        __nv_bfloat162 kl = __floats2bfloat162_rn(
                            v0 - __bfloat162float(kh.x), v1 - __bfloat162float(kh.y));
                        *(__nv_bfloat162*)(g_kh + off) = kh;
                        *(__nv_bfloat162*)(g_kl + off) = kl;
                    } else {
                        const float am = g_active[h];
                        float2 o;
                        o.x = uaf(f2tf32(v0 * am));         // v masked + tf32-rounded
                        o.y = uaf(f2tf32(v1 * am));
                        *(float2*)(g_v + off) = o;
                    }
                }
            }
        }
    }
}

// ---------------------------------------------------------------------------
// vmean[b,h,d] = mean_s v[b,h,s,d]  (float4 loads, skip inactive heads)
// ---------------------------------------------------------------------------
__global__ void vmean_kernel() {
    const int bh = blockIdx.x;
    if (g_active[bh & (HH - 1)] == 0.0f) return;
    const int d4    = (threadIdx.x & 15) * 4;
    const int chunk = threadIdx.x >> 4;
    const size_t base = (size_t)bh * SS * DD;
    float4 sum = {0.f, 0.f, 0.f, 0.f};
    for (int s = chunk * 128; s < (chunk + 1) * 128; s++) {
        float4 t = *(const float4*)(g_v + base + (size_t)s * DD + d4);
        sum.x += t.x; sum.y += t.y; sum.z += t.z; sum.w += t.w;
    }
    __shared__ float4 red[256];
    red[threadIdx.x] = sum;
    __syncthreads();
    if (chunk == 0) {
        float4 t = {0.f, 0.f, 0.f, 0.f};
#pragma unroll
        for (int c = 0; c < 16; c++) {
            float4 r = red[c * 16 + (threadIdx.x & 15)];
            t.x += r.x; t.y += r.y; t.z += r.z; t.w += r.w;
        }
        const float inv = 1.0f / SS;
        t.x *= inv; t.y *= inv; t.z *= inv; t.w *= inv;
        *(float4*)(g_vmean + bh * DD + d4) = t;
    }
}

// ---------------------------------------------------------------------------
// Tensor-core flash attention, v6:
//  - QK bf16 3-term with ldmatrix K-fragment loads
//  - Q hi/lo fragments precomputed once (32 packed bf16x2 regs)
//  - PV tf32 1-term, register-P permuted k-slots
//  - 3-stage cp.async ring, 1 barrier/tile, 2 CTAs/SM
// ---------------------------------------------------------------------------
#define KSTRW 36                       // words per Kh/Kl row (32 + 4 pad)
#define TKHW  (64 * KSTRW)             // words per Kh (or Kl) tile
#define VSTR  68
#define TVW   (64 * VSTR)
#define BUFW  (2 * TKHW + TVW)         // 8960 words
#define NSTG  3
#define SMEM_ATTN (NSTG * BUFW * 4)    // 107520 B

__global__ void __launch_bounds__(256, 2) attn_tc_kernel() {
    extern __shared__ float sh[];

    const int tid  = threadIdx.x;
    const int lane = tid & 31;
    const int warp = tid >> 5;
    const int g8   = lane >> 2;
    const int tig  = lane & 3;
    const int wr   = warp * 16;

    const int b = blockIdx.z, h = blockIdx.y;
    const int q0 = blockIdx.x * 128;
    const size_t bh = (size_t)(b * HH + h) * SS * DD;

    if (g_active[h] == 0.0f) {
        const uint4 z = {0u, 0u, 0u, 0u};
        for (int i = tid; i < 128 * 8; i += 256) {
            const int r = i >> 3, c = (i & 7) * 8;
            const size_t off = ((size_t)(b * SS + q0 + r) * HH + h) * DD + c;
            *(uint4*)(g_aoh + off) = z;
            *(uint4*)(g_aol + off) = z;
        }
        return;
    }

    const unsigned sbase = (unsigned)__cvta_generic_to_shared(sh);

    // ldmatrix lane mapping for K fragments (nt pair per x4)
    const int seg = lane >> 3, lr8 = lane & 7;
    const int krow = (seg >> 1) * 8 + lr8;   // + ntp*16
    const int kcol = (seg & 1) * 4;          // + ks*8

    // Q bf16 hi/lo fragments, packed bf16x2, computed once (32 regs)
    unsigned qh[4][4], ql[4][4];
#pragma unroll
    for (int ks = 0; ks < 4; ks++) {
        const int r0 = q0 + wr + g8;
        const int k0 = ks * 16 + 2 * tig;
        const float* qr0 = g_q + bh + (size_t)r0 * DD;
        const float* qr1 = g_q + bh + (size_t)(r0 + 8) * DD;
        float a0 = qr0[k0],     a1 = qr0[k0 + 1];
        float b0 = qr1[k0],     b1 = qr1[k0 + 1];
        float c0 = qr0[k0 + 8], c1 = qr0[k0 + 9];
        float d0 = qr1[k0 + 8], d1 = qr1[k0 + 9];
        __nv_bfloat162 ha = __floats2bfloat162_rn(a0, a1);
        __nv_bfloat162 hb = __floats2bfloat162_rn(b0, b1);
        __nv_bfloat162 hc = __floats2bfloat162_rn(c0, c1);
        __nv_bfloat162 hd = __floats2bfloat162_rn(d0, d1);
        qh[ks][0] = bf2u(ha); qh[ks][1] = bf2u(hb);
        qh[ks][2] = bf2u(hc); qh[ks][3] = bf2u(hd);
        ql[ks][0] = bf2u(__floats2bfloat162_rn(a0 - __bfloat162float(ha.x),
                                               a1 - __bfloat162float(ha.y)));
        ql[ks][1] = bf2u(__floats2bfloat162_rn(b0 - __bfloat162float(hb.x),
                                               b1 - __bfloat162float(hb.y)));
        ql[ks][2] = bf2u(__floats2bfloat162_rn(c0 - __bfloat162float(hc.x),
                                               c1 - __bfloat162float(hc.y)));
        ql[ks][3] = bf2u(__floats2bfloat162_rn(d0 - __bfloat162float(hd.x),
                                               d1 - __bfloat162float(hd.y)));
    }

    float o[8][4];
#pragma unroll
    for (int i = 0; i < 8; i++)
#pragma unroll
        for (int j = 0; j < 4; j++) o[i][j] = 0.f;
    float m0 = -1e30f, m1 = -1e30f, l0 = 0.f, l1 = 0.f;

    auto issue_tile = [&](int kvt, int st) {
        const int row = tid >> 2;       // 0..63
        const int t4  = tid & 3;
        const __nv_bfloat16* khp = g_kh + bh + (size_t)(kvt * 64 + row) * DD + t4 * 16;
        const __nv_bfloat16* klp = g_kl + bh + (size_t)(kvt * 64 + row) * DD + t4 * 16;
        const float* vp = g_v + bh + (size_t)(kvt * 64 + row) * DD + t4 * 16;
        const unsigned khd = sbase + (st * BUFW + row * KSTRW + t4 * 8) * 4;
        const unsigned kld = khd + TKHW * 4;
        const unsigned vd  = sbase + (st * BUFW + 2 * TKHW + row * VSTR + t4 * 16) * 4;
        cp16(khd,      khp);
        cp16(khd + 16, khp + 8);
        cp16(kld,      klp);
        cp16(kld + 16, klp + 8);
#pragma unroll
        for (int c = 0; c < 4; c++)
            cp16(vd + 16 * c, vp + 4 * c);
    };

    issue_tile(0, 0); cp_commit();
    issue_tile(1, 1); cp_commit();

    const int NTILE = SS / 64;
    int stage = 0;
    for (int t = 0; t < NTILE; t++) {
        cp_wait1();
        __syncthreads();

        if (t + 2 < NTILE) {
            int st2 = stage + 2; if (st2 >= NSTG) st2 -= NSTG;
            issue_tile(t + 2, st2);
        }
        cp_commit();

        const unsigned stb = sbase + (stage * BUFW) * 4;
        const unsigned* Vu = (const unsigned*)(sh + stage * BUFW + 2 * TKHW);

        // ---- QK: bf16 3-term, ldmatrix K fragments ----
        float c[8][4];
#pragma unroll
        for (int i = 0; i < 8; i++)
#pragma unroll
            for (int j = 0; j < 4; j++) c[i][j] = 0.f;
#pragma unroll
        for (int ks = 0; ks < 4; ks++) {
            const int kw = ks * 8;
#pragma unroll
            for (int ntp = 0; ntp < 4; ntp++) {
                unsigned kh0[2], kh1[2], kl0[2], kl1[2];
                const unsigned addr =
                    stb + ((krow + ntp * 16) * KSTRW + kw + kcol) * 4;
                ldsm4(kh0[0], kh0[1], kh1[0], kh1[1], addr);
                ldsm4(kl0[0], kl0[1], kl1[0], kl1[1], addr + TKHW * 4);
                mma_bf16(c[2*ntp],     qh[ks], kh0);
                mma_bf16(c[2*ntp],     ql[ks], kh0);
                mma_bf16(c[2*ntp],     qh[ks], kl0);
                mma_bf16(c[2*ntp + 1], qh[ks], kh1);
                mma_bf16(c[2*ntp + 1], ql[ks], kh1);
                mma_bf16(c[2*ntp + 1], qh[ks], kl1);
            }
        }

        // ---- online softmax; P rounded in-place into c ----
        float mx0 = c[0][0], mx1 = c[0][2];
#pragma unroll
        for (int nt = 0; nt < 8; nt++) {
            mx0 = fmaxf(mx0, fmaxf(c[nt][0], c[nt][1]));
            mx1 = fmaxf(mx1, fmaxf(c[nt][2], c[nt][3]));
        }
        mx0 = fmaxf(mx0, __shfl_xor_sync(0xffffffffu, mx0, 1));
        mx0 = fmaxf(mx0, __shfl_xor_sync(0xffffffffu, mx0, 2));
        mx1 = fmaxf(mx1, __shfl_xor_sync(0xffffffffu, mx1, 1));
        mx1 = fmaxf(mx1, __shfl_xor_sync(0xffffffffu, mx1, 2));
        const float mn0 = fmaxf(m0, mx0);
        const float mn1 = fmaxf(m1, mx1);
        const float sc0 = __expf(m0 - mn0);
        const float sc1 = __expf(m1 - mn1);
        m0 = mn0; m1 = mn1;
#pragma unroll
        for (int dt = 0; dt < 8; dt++) {
            o[dt][0] *= sc0; o[dt][1] *= sc0;
            o[dt][2] *= sc1; o[dt][3] *= sc1;
        }
        float s0 = 0.f, s1 = 0.f;
#pragma unroll
        for (int nt = 0; nt < 8; nt++) {
            const float p00 = uaf(f2tf32(__expf(c[nt][0] - m0)));
            const float p01 = uaf(f2tf32(__expf(c[nt][1] - m0)));
            const float p10 = uaf(f2tf32(__expf(c[nt][2] - m1)));
            const float p11 = uaf(f2tf32(__expf(c[nt][3] - m1)));
            s0 += p00 + p01;
            s1 += p10 + p11;
            c[nt][0] = p00; c[nt][1] = p01;
            c[nt][2] = p10; c[nt][3] = p11;
        }
        s0 += __shfl_xor_sync(0xffffffffu, s0, 1);
        s0 += __shfl_xor_sync(0xffffffffu, s0, 2);
        s1 += __shfl_xor_sync(0xffffffffu, s1, 1);
        s1 += __shfl_xor_sync(0xffffffffu, s1, 2);
        l0 = l0 * sc0 + s0;
        l1 = l1 * sc1 + s1;

        // ---- PV, tf32, permuted k-slots; A-frag = own accumulator bits ----
#pragma unroll
        for (int ks = 0; ks < 8; ks++) {
            unsigned aa[4] = {__float_as_uint(c[ks][0]), __float_as_uint(c[ks][2]),
                              __float_as_uint(c[ks][1]), __float_as_uint(c[ks][3])};
            const int vr0 = (ks * 8 + 2 * tig) * VSTR;
#pragma unroll
            for (int dt = 0; dt < 8; dt++) {
                unsigned bb[2];
                bb[0] = Vu[vr0 + dt * 8 + g8];
                bb[1] = Vu[vr0 + VSTR + dt * 8 + g8];
                mma_tf32(o[dt], aa, bb);
            }
        }

        stage = (stage + 1 == NSTG) ? 0 : stage + 1;
    }

    // epilogue: normalize, add vmean, emit bf16 hi/lo for out-projection
    const float inv0 = 1.0f / l0;
    const float inv1 = 1.0f / l1;
    const int r0 = q0 + wr + g8;
    const size_t ob0 = ((size_t)(b * SS + r0) * HH + h) * DD;
    const size_t ob1 = ((size_t)(b * SS + r0 + 8) * HH + h) * DD;
    const float* vm = g_vmean + (size_t)(b * HH + h) * DD;
#pragma unroll
    for (int dt = 0; dt < 8; dt++) {
        const int col = dt * 8 + 2 * tig;
        const float v0 = vm[col], v1 = vm[col + 1];
        const float f00 = o[dt][0] * inv0 + v0, f01 = o[dt][1] * inv0 + v1;
        const float f10 = o[dt][2] * inv1 + v0, f11 = o[dt][3] * inv1 + v1;
        __nv_bfloat162 h0 = __floats2bfloat162_rn(f00, f01);
        __nv_bfloat162 h1 = __floats2bfloat162_rn(f10, f11);
        __nv_bfloat162 lo0 = __floats2bfloat162_rn(
            f00 - __bfloat162float(h0.x), f01 - __bfloat162float(h0.y));
        __nv_bfloat162 lo1 = __floats2bfloat162_rn(
            f10 - __bfloat162float(h1.x), f11 - __bfloat162float(h1.y));
        *(__nv_bfloat162*)(g_aoh + ob0 + col) = h0;
        *(__nv_bfloat162*)(g_aol + ob0 + col) = lo0;
        *(__nv_bfloat162*)(g_aoh + ob1 + col) = h1;
        *(__nv_bfloat162*)(g_aol + ob1 + col) = lo1;
    }
}

// ---------------------------------------------------------------------------
extern "C" void kernel_launch(void* const* d_in, const int* in_sizes, int n_in,
                              void* d_out, int out_size) {
    const float* x      = (const float*)d_in[0];
    const float* qkv_w  = (const float*)d_in[1];
    const float* qkv_b  = (const float*)d_in[2];
    const float* out_w  = (const float*)d_in[3];
    const float* out_b  = (const float*)d_in[4];
    const float* gates  = (const float*)d_in[5];
    const float* imp    = (const float*)d_in[6];
    const float* thr    = (const float*)d_in[7];
    float* out = (float*)d_out;

    static bool attr_set = false;
    if (!attr_set) {
        cudaFuncSetAttribute(attn_tc_kernel,
                             cudaFuncAttributeMaxDynamicSharedMemorySize, SMEM_ATTN);
        cudaFuncSetAttribute(gemm_bf16_kernel<0>,
                             cudaFuncAttributeMaxDynamicSharedMemorySize, SMEM_GEMM);
        cudaFuncSetAttribute(gemm_bf16_kernel<1>,
                             cudaFuncAttributeMaxDynamicSharedMemorySize, SMEM_GEMM);
        attr_set = true;
    }

    __nv_bfloat16 *xh, *xl, *wh, *wl, *owh, *owl, *aoh, *aol;
    cudaGetSymbolAddress((void**)&xh,  g_xh);
    cudaGetSymbolAddress((void**)&xl,  g_xl);
    cudaGetSymbolAddress((void**)&wh,  g_wh);
    cudaGetSymbolAddress((void**)&wl,  g_wl);
    cudaGetSymbolAddress((void**)&owh, g_owh);
    cudaGetSymbolAddress((void**)&owl, g_owl);
    cudaGetSymbolAddress((void**)&aoh, g_aoh);
    cudaGetSymbolAddress((void**)&aol, g_aol);

    mask_kernel<<<1, 32>>>(gates, imp, thr);

    // operand pre-splits (hi+lo bf16 = same total bytes as fp32 source)
    split_bf16_kernel<<<(MM*EE/4 + 255)/256, 256>>>(x, xh, xl, MM*EE/4);
    split_bf16_kernel<<<(3*EE*EE/4 + 255)/256, 256>>>(qkv_w, wh, wl, 3*EE*EE/4);
    split_bf16_kernel<<<(EE*EE/4 + 255)/256, 256>>>(out_w, owh, owl, EE*EE/4);

    // QKV projection (3-term bf16 split, m16n8k16 + ldmatrix)
    {
        dim3 g(3 * EE / 128, MM / 128);      // 24 x 32
        gemm_bf16_kernel<0><<<g, 256, SMEM_GEMM>>>(xh, xl, wh, wl, qkv_b, nullptr);
    }

    vmean_kernel<<<BB * HH, 256>>>();

    // Attention (bf16 QK 3-term + tf32 PV, ldmatrix K frags)
    {
        dim3 g(SS / 128, HH, BB);            // 16 x 16 x 2
        attn_tc_kernel<<<g, 256, SMEM_ATTN>>>();
    }

    // Output projection (3-term bf16 split, m16n8k16 + ldmatrix)
    {
        dim3 g(EE / 128, MM / 128);          // 8 x 32
        gemm_bf16_kernel<1><<<g, 256, SMEM_GEMM>>>(aoh, aol, owh, owl, out_b, out);
    }
}

// round 13
// speedup vs baseline: 1.8415x; 1.1159x over previous
#include <cuda_runtime.h>
#include <cuda_bf16.h>
#include <cuda_fp16.h>
#include <stdint.h>
#include <math.h>

#define BB 2
#define SS 2048
#define EE 1024
#define HH 16
#define DD 64
#define MM (BB*SS)

// Scratch (static device globals; no runtime allocation)
__device__ float g_q[BB*HH*SS*DD];      // raw fp32 q   [B,H,S,D]
__device__ float g_vmean[BB*HH*DD];
__device__ float g_active[HH];
// V stored fp16, s-pair interleaved: word [bh][s2][d] = (V[2*s2][d], V[2*s2+1][d])
__device__ __align__(16) __half g_vp[BB*HH*SS*DD];
// bf16 hi/lo K for attention QK
__device__ __align__(16) __nv_bfloat16 g_kh[BB*HH*SS*DD], g_kl[BB*HH*SS*DD];
// bf16 hi/lo operand arrays for bf16 mma GEMMs
__device__ __align__(16) __nv_bfloat16 g_xh[MM*EE],   g_xl[MM*EE];     // x
__device__ __align__(16) __nv_bfloat16 g_wh[3*EE*EE], g_wl[3*EE*EE];   // qkv_w
__device__ __align__(16) __nv_bfloat16 g_owh[EE*EE],  g_owl[EE*EE];    // out_w
__device__ __align__(16) __nv_bfloat16 g_aoh[MM*EE],  g_aol[MM*EE];    // attn out [B,S,H*D]

// ---------------------------------------------------------------------------
// helpers
// ---------------------------------------------------------------------------
__device__ __forceinline__ float uaf(unsigned u) { return __uint_as_float(u); }

// m16n8k16 bf16 mma
__device__ __forceinline__ void mma_bf16(float c[4], const unsigned a[4], const unsigned b[2]) {
    asm volatile(
        "mma.sync.aligned.m16n8k16.row.col.f32.bf16.bf16.f32 "
        "{%0,%1,%2,%3}, {%4,%5,%6,%7}, {%8,%9}, {%0,%1,%2,%3};"
        : "+f"(c[0]), "+f"(c[1]), "+f"(c[2]), "+f"(c[3])
        : "r"(a[0]), "r"(a[1]), "r"(a[2]), "r"(a[3]),
          "r"(b[0]), "r"(b[1]));
}

// m16n8k16 fp16 mma (fp32 accumulate)
__device__ __forceinline__ void mma_f16(float c[4], const unsigned a[4], const unsigned b[2]) {
    asm volatile(
        "mma.sync.aligned.m16n8k16.row.col.f32.f16.f16.f32 "
        "{%0,%1,%2,%3}, {%4,%5,%6,%7}, {%8,%9}, {%0,%1,%2,%3};"
        : "+f"(c[0]), "+f"(c[1]), "+f"(c[2]), "+f"(c[3])
        : "r"(a[0]), "r"(a[1]), "r"(a[2]), "r"(a[3]),
          "r"(b[0]), "r"(b[1]));
}

__device__ __forceinline__ void ldsm4(unsigned &r0, unsigned &r1, unsigned &r2,
                                      unsigned &r3, unsigned addr) {
    asm volatile("ldmatrix.sync.aligned.m8n8.x4.shared.b16 {%0,%1,%2,%3}, [%4];"
                 : "=r"(r0), "=r"(r1), "=r"(r2), "=r"(r3) : "r"(addr));
}

__device__ __forceinline__ void cp16(unsigned dst, const void* src) {
    asm volatile("cp.async.cg.shared.global [%0], [%1], 16;\n" :: "r"(dst), "l"(src));
}
__device__ __forceinline__ void cp_commit() {
    asm volatile("cp.async.commit_group;\n");
}
__device__ __forceinline__ void cp_wait1() {
    asm volatile("cp.async.wait_group 1;\n");
}

__device__ __forceinline__ unsigned bf2u(__nv_bfloat162 v) {
    return *(unsigned*)&v;
}
__device__ __forceinline__ unsigned h2u(__half2 v) {
    return *(unsigned*)&v;
}

// ---------------------------------------------------------------------------
// Head mask
// ---------------------------------------------------------------------------
__global__ void mask_kernel(const float* __restrict__ gates,
                            const float* __restrict__ imp,
                            const float* __restrict__ thr) {
    int h = threadIdx.x;
    if (h < HH) {
        float z  = gates[h] * imp[h];
        float gs = 1.0f / (1.0f + expf(-z));
        g_active[h] = (gs > thr[0]) ? 1.0f : 0.0f;
    }
}

// ---------------------------------------------------------------------------
// bf16 hi/lo split: h = bf16(x), l = bf16(x - h)
// ---------------------------------------------------------------------------
__global__ void split_bf16_kernel(const float* __restrict__ src,
                                  __nv_bfloat16* __restrict__ h,
                                  __nv_bfloat16* __restrict__ l, int n4) {
    int i = blockIdx.x * blockDim.x + threadIdx.x;
    if (i < n4) {
        float4 v = ((const float4*)src)[i];
        __nv_bfloat162 h01 = __floats2bfloat162_rn(v.x, v.y);
        __nv_bfloat162 h23 = __floats2bfloat162_rn(v.z, v.w);
        *(__nv_bfloat162*)(h + 4 * (size_t)i)     = h01;
        *(__nv_bfloat162*)(h + 4 * (size_t)i + 2) = h23;
        __nv_bfloat162 l01 = __floats2bfloat162_rn(
            v.x - __bfloat162float(h01.x), v.y - __bfloat162float(h01.y));
        __nv_bfloat162 l23 = __floats2bfloat162_rn(
            v.z - __bfloat162float(h23.x), v.w - __bfloat162float(h23.y));
        *(__nv_bfloat162*)(l + 4 * (size_t)i)     = l01;
        *(__nv_bfloat162*)(l + 4 * (size_t)i + 2) = l23;
    }
}

// ---------------------------------------------------------------------------
// 3-term bf16-split GEMM on mma.sync.m16n8k16, ldmatrix fragment loads.
// C[m,n] = sum_k A[m,k]*B[n,k] + bias[n]
// MODE 0: qkv scatter epilogue. MODE 1: row-major write.
// ---------------------------------------------------------------------------
#define GSTR  20                    // words per smem row (16 + 4 pad)
#define GARR  (128 * GSTR)          // words per operand array
#define GSTG  (4 * GARR)            // Ah|Al|Bh|Bl per stage
#define SMEM_GEMM (2 * GSTG * 4)    // 81920 B

template <int MODE>
__global__ void __launch_bounds__(256, 2) gemm_bf16_kernel(
    const __nv_bfloat16* __restrict__ Ahg, const __nv_bfloat16* __restrict__ Alg,
    const __nv_bfloat16* __restrict__ Bhg, const __nv_bfloat16* __restrict__ Blg,
    const float* __restrict__ bias, float* __restrict__ Y) {
    extern __shared__ unsigned gsm[];

    const int m0 = blockIdx.y * 128;
    const int n0 = blockIdx.x * 128;

    if (MODE == 0) {
        const int hA = (n0 & 1023) >> 6;
        if (g_active[hA] == 0.0f && g_active[hA + 1] == 0.0f) return;
    }

    const int tid  = threadIdx.x;
    const int lane = tid & 31;
    const int warp = tid >> 5;
    const int wm = (warp >> 2) * 64;
    const int wn = (warp & 3) * 32;
    const int grp = lane >> 2;
    const int tig = lane & 3;

    const int grow = tid >> 1;          // 0..127
    const int gkw  = (tid & 1) * 8;     // word offset 0 or 8 (=16 bf16)
    const __nv_bfloat16* Aph = Ahg + (size_t)(m0 + grow) * EE + gkw * 2;
    const __nv_bfloat16* Apl = Alg + (size_t)(m0 + grow) * EE + gkw * 2;
    const __nv_bfloat16* Bph = Bhg + (size_t)(n0 + grow) * EE + gkw * 2;
    const __nv_bfloat16* Bpl = Blg + (size_t)(n0 + grow) * EE + gkw * 2;

    const unsigned gb = (unsigned)__cvta_generic_to_shared(gsm);
    const int seg = lane >> 3, lr8 = lane & 7;
    const int arow = wm + (seg & 1) * 8 + lr8;   // + mi*16
    const int acol = (seg >> 1) * 4;             // + ks*8
    const int brow = wn + (seg >> 1) * 8 + lr8;  // + np*16
    const int bcol = (seg & 1) * 4;              // + ks*8

    float acc[4][4][4];
#pragma unroll
    for (int i = 0; i < 4; i++)
#pragma unroll
        for (int j = 0; j < 4; j++)
#pragma unroll
            for (int r = 0; r < 4; r++) acc[i][j][r] = 0.f;

    auto store_stage = [&](int st, const uint4 p[8]) {
        unsigned* base = gsm + st * GSTG + grow * GSTR + gkw;
        *(uint4*)(base)                = p[0];
        *(uint4*)(base + 4)            = p[1];
        *(uint4*)(base + GARR)         = p[2];
        *(uint4*)(base + GARR + 4)     = p[3];
        *(uint4*)(base + 2 * GARR)     = p[4];
        *(uint4*)(base + 2 * GARR + 4) = p[5];
        *(uint4*)(base + 3 * GARR)     = p[6];
        *(uint4*)(base + 3 * GARR + 4) = p[7];
    };
    auto load_tile = [&](int kt, uint4 p[8]) {
        const size_t o = (size_t)kt * 32;
        p[0] = *(const uint4*)(Aph + o);  p[1] = *(const uint4*)(Aph + o + 8);
        p[2] = *(const uint4*)(Apl + o);  p[3] = *(const uint4*)(Apl + o + 8);
        p[4] = *(const uint4*)(Bph + o);  p[5] = *(const uint4*)(Bph + o + 8);
        p[6] = *(const uint4*)(Bpl + o);  p[7] = *(const uint4*)(Bpl + o + 8);
    };

    {
        uint4 p[8];
        load_tile(0, p);
        store_stage(0, p);
    }
    __syncthreads();

    const int NT = EE / 32;  // 32 k-tiles
    for (int kt = 0; kt < NT; kt++) {
        uint4 p[8];
        if (kt + 1 < NT) load_tile(kt + 1, p);

        const unsigned stb = gb + ((kt & 1) * GSTG) * 4;

#pragma unroll
        for (int ks = 0; ks < 2; ks++) {
            const int kw = ks * 8;
            unsigned bh[4][2], bl[4][2];
#pragma unroll
            for (int np = 0; np < 2; np++) {
                const unsigned addr =
                    stb + (2 * GARR + (brow + np * 16) * GSTR + kw + bcol) * 4;
                ldsm4(bh[2*np][0], bh[2*np][1], bh[2*np+1][0], bh[2*np+1][1], addr);
                ldsm4(bl[2*np][0], bl[2*np][1], bl[2*np+1][0], bl[2*np+1][1],
                      addr + GARR * 4);
            }
#pragma unroll
            for (int mi = 0; mi < 4; mi++) {
                unsigned ah[4], al[4];
                const unsigned addr =
                    stb + ((arow + mi * 16) * GSTR + kw + acol) * 4;
                ldsm4(ah[0], ah[1], ah[2], ah[3], addr);
                ldsm4(al[0], al[1], al[2], al[3], addr + GARR * 4);
#pragma unroll
                for (int ni = 0; ni < 4; ni++) {
                    mma_bf16(acc[mi][ni], ah, bh[ni]);
                    mma_bf16(acc[mi][ni], al, bh[ni]);
                    mma_bf16(acc[mi][ni], ah, bl[ni]);
                }
            }
        }

        if (kt + 1 < NT) store_stage((kt + 1) & 1, p);
        __syncthreads();
    }

    // epilogue
#pragma unroll
    for (int mi = 0; mi < 4; mi++) {
        const int rbase = m0 + wm + mi * 16 + grp;
#pragma unroll
        for (int ni = 0; ni < 4; ni++) {
            const int j = n0 + wn + ni * 8 + 2 * tig;
            const float b0 = bias[j], b1 = bias[j + 1];
#pragma unroll
            for (int rh = 0; rh < 2; rh++) {
                const int m = rbase + rh * 8;
                const float v0 = acc[mi][ni][rh * 2 + 0] + b0;
                const float v1 = acc[mi][ni][rh * 2 + 1] + b1;
                if (MODE == 1) {
                    float2 o; o.x = v0; o.y = v1;
                    *(float2*)(Y + (size_t)m * EE + j) = o;
                } else {
                    const int cc  = j >> 10;
                    const int rem = j & 1023;
                    const int h = rem >> 6, d = rem & 63;
                    const int bI = m >> 11;
                    const int s  = m & (SS - 1);
                    const size_t off = (((size_t)(bI * HH + h)) * SS + s) * DD + d;
                    if (cc == 0) {
                        float2 o; o.x = v0; o.y = v1;       // q raw
                        *(float2*)(g_q + off) = o;
                    } else if (cc == 1) {
                        __nv_bfloat162 kh = __floats2bfloat162_rn(v0, v1);
                        __nv_bfloat162 kl = __floats2bfloat162_rn(
                            v0 - __bfloat162float(kh.x), v1 - __bfloat162float(kh.y));
                        *(__nv_bfloat162*)(g_kh + off) = kh;
                        *(__nv_bfloat162*)(g_kl + off) = kl;
                    } else {
                        // v masked, fp16, s-pair interleaved: halves at
                        // [bh][s>>1][d].(s&1)
                        const float am = g_active[h];
                        const int s2 = s >> 1, so = s & 1;
                        __half* vp = g_vp + (size_t)(bI * HH + h) * SS * DD
                                   + (size_t)s2 * (2 * DD) + 2 * d + so;
                        vp[0] = __float2half_rn(v0 * am);
                        vp[2] = __float2half_rn(v1 * am);
                    }
                }
            }
        }
    }
}

// ---------------------------------------------------------------------------
// vmean[b,h,d] = mean_s v[b,h,s,d]  (reads interleaved fp16 VP)
// ---------------------------------------------------------------------------
__global__ void vmean_kernel() {
    const int bh = blockIdx.x;
    if (g_active[bh & (HH - 1)] == 0.0f) return;
    const int d     = threadIdx.x & 63;
    const int chunk = threadIdx.x >> 6;   // 0..3, 256 s2-rows each
    const __half2* vp = (const __half2*)g_vp + (size_t)bh * (SS / 2) * DD;
    float sum = 0.f;
    for (int s2 = chunk * 256; s2 < (chunk + 1) * 256; s2++) {
        float2 f = __half22float2(vp[(size_t)s2 * DD + d]);
        sum += f.x + f.y;
    }
    __shared__ float red[256];
    red[threadIdx.x] = sum;
    __syncthreads();
    if (chunk == 0) {
        float t = red[d] + red[64 + d] + red[128 + d] + red[192 + d];
        g_vmean[bh * DD + d] = t * (1.0f / SS);
    }
}

// ---------------------------------------------------------------------------
// Tensor-core flash attention, v7:
//  - QK bf16 3-term with ldmatrix K-fragment loads (unchanged)
//  - PV fp16 m16n8k16: A-frag = packed own P registers (k-pair coincidence),
//    B-frag = single-word LDS from s-pair-interleaved VP tile
//  - 3-stage cp.async ring, 1 barrier/tile, 2 CTAs/SM
// ---------------------------------------------------------------------------
#define KSTRW 36                       // words per Kh/Kl row (32 + 4 pad)
#define TKHW  (64 * KSTRW)             // words per Kh (or Kl) tile
#define VPSTR 72                       // words per VP row (64 + 8 pad; ==8 mod 32)
#define TVPW  (32 * VPSTR)             // words per VP tile (32 s2-rows)
#define BUFW  (2 * TKHW + TVPW)        // 6912 words
#define NSTG  3
#define SMEM_ATTN (NSTG * BUFW * 4)    // 82944 B

__global__ void __launch_bounds__(256, 2) attn_tc_kernel() {
    extern __shared__ float sh[];

    const int tid  = threadIdx.x;
    const int lane = tid & 31;
    const int warp = tid >> 5;
    const int g8   = lane >> 2;
    const int tig  = lane & 3;
    const int wr   = warp * 16;

    const int b = blockIdx.z, h = blockIdx.y;
    const int q0 = blockIdx.x * 128;
    const size_t bh = (size_t)(b * HH + h) * SS * DD;

    if (g_active[h] == 0.0f) {
        const uint4 z = {0u, 0u, 0u, 0u};
        for (int i = tid; i < 128 * 8; i += 256) {
            const int r = i >> 3, c = (i & 7) * 8;
            const size_t off = ((size_t)(b * SS + q0 + r) * HH + h) * DD + c;
            *(uint4*)(g_aoh + off) = z;
            *(uint4*)(g_aol + off) = z;
        }
        return;
    }

    const unsigned sbase = (unsigned)__cvta_generic_to_shared(sh);

    // ldmatrix lane mapping for K fragments (nt pair per x4)
    const int seg = lane >> 3, lr8 = lane & 7;
    const int krow = (seg >> 1) * 8 + lr8;   // + ntp*16
    const int kcol = (seg & 1) * 4;          // + ks*8

    // Q bf16 hi/lo fragments, packed bf16x2, computed once (32 regs)
    unsigned qh[4][4], ql[4][4];
#pragma unroll
    for (int ks = 0; ks < 4; ks++) {
        const int r0 = q0 + wr + g8;
        const int k0 = ks * 16 + 2 * tig;
        const float* qr0 = g_q + bh + (size_t)r0 * DD;
        const float* qr1 = g_q + bh + (size_t)(r0 + 8) * DD;
        float a0 = qr0[k0],     a1 = qr0[k0 + 1];
        float b0 = qr1[k0],     b1 = qr1[k0 + 1];
        float c0 = qr0[k0 + 8], c1 = qr0[k0 + 9];
        float d0 = qr1[k0 + 8], d1 = qr1[k0 + 9];
        __nv_bfloat162 ha = __floats2bfloat162_rn(a0, a1);
        __nv_bfloat162 hb = __floats2bfloat162_rn(b0, b1);
        __nv_bfloat162 hc = __floats2bfloat162_rn(c0, c1);
        __nv_bfloat162 hd = __floats2bfloat162_rn(d0, d1);
        qh[ks][0] = bf2u(ha); qh[ks][1] = bf2u(hb);
        qh[ks][2] = bf2u(hc); qh[ks][3] = bf2u(hd);
        ql[ks][0] = bf2u(__floats2bfloat162_rn(a0 - __bfloat162float(ha.x),
                                               a1 - __bfloat162float(ha.y)));
        ql[ks][1] = bf2u(__floats2bfloat162_rn(b0 - __bfloat162float(hb.x),
                                               b1 - __bfloat162float(hb.y)));
        ql[ks][2] = bf2u(__floats2bfloat162_rn(c0 - __bfloat162float(hc.x),
                                               c1 - __bfloat162float(hc.y)));
        ql[ks][3] = bf2u(__floats2bfloat162_rn(d0 - __bfloat162float(hd.x),
                                               d1 - __bfloat162float(hd.y)));
    }

    float o[8][4];
#pragma unroll
    for (int i = 0; i < 8; i++)
#pragma unroll
        for (int j = 0; j < 4; j++) o[i][j] = 0.f;
    float m0 = -1e30f, m1 = -1e30f, l0 = 0.f, l1 = 0.f;

    // VP word base for this (b,h): words per bh = SS/2 * DD
    const unsigned* vpw = (const unsigned*)g_vp + (size_t)(b * HH + h) * (SS / 2) * DD;

    auto issue_tile = [&](int kvt, int st) {
        // K tiles: 64 rows x 32 words each (hi + lo)
        const int row = tid >> 2;       // 0..63
        const int t4  = tid & 3;
        const __nv_bfloat16* khp = g_kh + bh + (size_t)(kvt * 64 + row) * DD + t4 * 16;
        const __nv_bfloat16* klp = g_kl + bh + (size_t)(kvt * 64 + row) * DD + t4 * 16;
        const unsigned khd = sbase + (st * BUFW + row * KSTRW + t4 * 8) * 4;
        const unsigned kld = khd + TKHW * 4;
        cp16(khd,      khp);
        cp16(khd + 16, khp + 8);
        cp16(kld,      klp);
        cp16(kld + 16, klp + 8);
        // VP tile: 32 s2-rows x 64 words
        const int vrow = tid >> 3;      // 0..31
        const int vcol = (tid & 7) * 8;
        const unsigned* vg = vpw + (size_t)(kvt * 32 + vrow) * DD + vcol;
        const unsigned vd = sbase + (st * BUFW + 2 * TKHW + vrow * VPSTR + vcol) * 4;
        cp16(vd,      vg);
        cp16(vd + 16, vg + 4);
    };

    issue_tile(0, 0); cp_commit();
    issue_tile(1, 1); cp_commit();

    const int NTILE = SS / 64;
    int stage = 0;
    for (int t = 0; t < NTILE; t++) {
        cp_wait1();
        __syncthreads();

        if (t + 2 < NTILE) {
            int st2 = stage + 2; if (st2 >= NSTG) st2 -= NSTG;
            issue_tile(t + 2, st2);
        }
        cp_commit();

        const unsigned stb = sbase + (stage * BUFW) * 4;
        const unsigned* VPu = (const unsigned*)(sh + stage * BUFW + 2 * TKHW);

        // ---- QK: bf16 3-term, ldmatrix K fragments ----
        float c[8][4];
#pragma unroll
        for (int i = 0; i < 8; i++)
#pragma unroll
            for (int j = 0; j < 4; j++) c[i][j] = 0.f;
#pragma unroll
        for (int ks = 0; ks < 4; ks++) {
            const int kw = ks * 8;
#pragma unroll
            for (int ntp = 0; ntp < 4; ntp++) {
                unsigned kh0[2], kh1[2], kl0[2], kl1[2];
                const unsigned addr =
                    stb + ((krow + ntp * 16) * KSTRW + kw + kcol) * 4;
                ldsm4(kh0[0], kh0[1], kh1[0], kh1[1], addr);
                ldsm4(kl0[0], kl0[1], kl1[0], kl1[1], addr + TKHW * 4);
                mma_bf16(c[2*ntp],     qh[ks], kh0);
                mma_bf16(c[2*ntp],     ql[ks], kh0);
                mma_bf16(c[2*ntp],     qh[ks], kl0);
                mma_bf16(c[2*ntp + 1], qh[ks], kh1);
                mma_bf16(c[2*ntp + 1], ql[ks], kh1);
                mma_bf16(c[2*ntp + 1], qh[ks], kl1);
            }
        }

        // ---- online softmax; P packed to fp16 pairs ----
        float mx0 = c[0][0], mx1 = c[0][2];
#pragma unroll
        for (int nt = 0; nt < 8; nt++) {
            mx0 = fmaxf(mx0, fmaxf(c[nt][0], c[nt][1]));
            mx1 = fmaxf(mx1, fmaxf(c[nt][2], c[nt][3]));
        }
        mx0 = fmaxf(mx0, __shfl_xor_sync(0xffffffffu, mx0, 1));
        mx0 = fmaxf(mx0, __shfl_xor_sync(0xffffffffu, mx0, 2));
        mx1 = fmaxf(mx1, __shfl_xor_sync(0xffffffffu, mx1, 1));
        mx1 = fmaxf(mx1, __shfl_xor_sync(0xffffffffu, mx1, 2));
        const float mn0 = fmaxf(m0, mx0);
        const float mn1 = fmaxf(m1, mx1);
        const float sc0 = __expf(m0 - mn0);
        const float sc1 = __expf(m1 - mn1);
        m0 = mn0; m1 = mn1;
#pragma unroll
        for (int dt = 0; dt < 8; dt++) {
            o[dt][0] *= sc0; o[dt][1] *= sc0;
            o[dt][2] *= sc1; o[dt][3] *= sc1;
        }
        unsigned hp[8][2];
        float s0 = 0.f, s1 = 0.f;
#pragma unroll
        for (int nt = 0; nt < 8; nt++) {
            const float p00 = __expf(c[nt][0] - m0);
            const float p01 = __expf(c[nt][1] - m0);
            const float p10 = __expf(c[nt][2] - m1);
            const float p11 = __expf(c[nt][3] - m1);
            __half2 w0 = __floats2half2_rn(p00, p01);
            __half2 w1 = __floats2half2_rn(p10, p11);
            hp[nt][0] = h2u(w0);
            hp[nt][1] = h2u(w1);
            float2 f0 = __half22float2(w0);
            float2 f1 = __half22float2(w1);
            s0 += f0.x + f0.y;
            s1 += f1.x + f1.y;
        }
        s0 += __shfl_xor_sync(0xffffffffu, s0, 1);
        s0 += __shfl_xor_sync(0xffffffffu, s0, 2);
        s1 += __shfl_xor_sync(0xffffffffu, s1, 1);
        s1 += __shfl_xor_sync(0xffffffffu, s1, 2);
        l0 = l0 * sc0 + s0;
        l1 = l1 * sc1 + s1;

        // ---- PV: fp16 m16n8k16; A-frag = own packed P registers ----
        // k-block ks covers P cols [16ks,16ks+16): a0/a1 from nt=2ks,
        // a2/a3 from nt=2ks+1 (thread's k-pair {2tig,2tig+1} == held cols).
        // B-frag: VP word [8ks+tig][d] (b0), [8ks+tig+4][d] (b1).
#pragma unroll
        for (int ks = 0; ks < 4; ks++) {
            unsigned aa[4] = {hp[2*ks][0], hp[2*ks][1],
                              hp[2*ks + 1][0], hp[2*ks + 1][1]};
            const int r0 = (8 * ks + tig) * VPSTR;
#pragma unroll
            for (int dt = 0; dt < 8; dt++) {
                unsigned bb[2];
                bb[0] = VPu[r0 + dt * 8 + g8];
                bb[1] = VPu[r0 + 4 * VPSTR + dt * 8 + g8];
                mma_f16(o[dt], aa, bb);
            }
        }

        stage = (stage + 1 == NSTG) ? 0 : stage + 1;
    }

    // epilogue: normalize, add vmean, emit bf16 hi/lo for out-projection
    const float inv0 = 1.0f / l0;
    const float inv1 = 1.0f / l1;
    const int r0 = q0 + wr + g8;
    const size_t ob0 = ((size_t)(b * SS + r0) * HH + h) * DD;
    const size_t ob1 = ((size_t)(b * SS + r0 + 8) * HH + h) * DD;
    const float* vm = g_vmean + (size_t)(b * HH + h) * DD;
#pragma unroll
    for (int dt = 0; dt < 8; dt++) {
        const int col = dt * 8 + 2 * tig;
        const float v0 = vm[col], v1 = vm[col + 1];
        const float f00 = o[dt][0] * inv0 + v0, f01 = o[dt][1] * inv0 + v1;
        const float f10 = o[dt][2] * inv1 + v0, f11 = o[dt][3] * inv1 + v1;
        __nv_bfloat162 h0 = __floats2bfloat162_rn(f00, f01);
        __nv_bfloat162 h1 = __floats2bfloat162_rn(f10, f11);
        __nv_bfloat162 lo0 = __floats2bfloat162_rn(
            f00 - __bfloat162float(h0.x), f01 - __bfloat162float(h0.y));
        __nv_bfloat162 lo1 = __floats2bfloat162_rn(
            f10 - __bfloat162float(h1.x), f11 - __bfloat162float(h1.y));
        *(__nv_bfloat162*)(g_aoh + ob0 + col) = h0;
        *(__nv_bfloat162*)(g_aol + ob0 + col) = lo0;
        *(__nv_bfloat162*)(g_aoh + ob1 + col) = h1;
        *(__nv_bfloat162*)(g_aol + ob1 + col) = lo1;
    }
}

// ---------------------------------------------------------------------------
extern "C" void kernel_launch(void* const* d_in, const int* in_sizes, int n_in,
                              void* d_out, int out_size) {
    const float* x      = (const float*)d_in[0];
    const float* qkv_w  = (const float*)d_in[1];
    const float* qkv_b  = (const float*)d_in[2];
    const float* out_w  = (const float*)d_in[3];
    const float* out_b  = (const float*)d_in[4];
    const float* gates  = (const float*)d_in[5];
    const float* imp    = (const float*)d_in[6];
    const float* thr    = (const float*)d_in[7];
    float* out = (float*)d_out;

    static bool attr_set = false;
    if (!attr_set) {
        cudaFuncSetAttribute(attn_tc_kernel,
                             cudaFuncAttributeMaxDynamicSharedMemorySize, SMEM_ATTN);
        cudaFuncSetAttribute(gemm_bf16_kernel<0>,
                             cudaFuncAttributeMaxDynamicSharedMemorySize, SMEM_GEMM);
        cudaFuncSetAttribute(gemm_bf16_kernel<1>,
                             cudaFuncAttributeMaxDynamicSharedMemorySize, SMEM_GEMM);
        attr_set = true;
    }

    __nv_bfloat16 *xh, *xl, *wh, *wl, *owh, *owl, *aoh, *aol;
    cudaGetSymbolAddress((void**)&xh,  g_xh);
    cudaGetSymbolAddress((void**)&xl,  g_xl);
    cudaGetSymbolAddress((void**)&wh,  g_wh);
    cudaGetSymbolAddress((void**)&wl,  g_wl);
    cudaGetSymbolAddress((void**)&owh, g_owh);
    cudaGetSymbolAddress((void**)&owl, g_owl);
    cudaGetSymbolAddress((void**)&aoh, g_aoh);
    cudaGetSymbolAddress((void**)&aol, g_aol);

    mask_kernel<<<1, 32>>>(gates, imp, thr);

    // operand pre-splits (hi+lo bf16 = same total bytes as fp32 source)
    split_bf16_kernel<<<(MM*EE/4 + 255)/256, 256>>>(x, xh, xl, MM*EE/4);
    split_bf16_kernel<<<(3*EE*EE/4 + 255)/256, 256>>>(qkv_w, wh, wl, 3*EE*EE/4);
    split_bf16_kernel<<<(EE*EE/4 + 255)/256, 256>>>(out_w, owh, owl, EE*EE/4);

    // QKV projection (3-term bf16 split, m16n8k16 + ldmatrix)
    {
        dim3 g(3 * EE / 128, MM / 128);      // 24 x 32
        gemm_bf16_kernel<0><<<g, 256, SMEM_GEMM>>>(xh, xl, wh, wl, qkv_b, nullptr);
    }

    vmean_kernel<<<BB * HH, 256>>>();

    // Attention (bf16 QK 3-term + fp16 PV)
    {
        dim3 g(SS / 128, HH, BB);            // 16 x 16 x 2
        attn_tc_kernel<<<g, 256, SMEM_ATTN>>>();
    }

    // Output projection (3-term bf16 split, m16n8k16 + ldmatrix)
    {
        dim3 g(EE / 128, MM / 128);          // 8 x 32
        gemm_bf16_kernel<1><<<g, 256, SMEM_GEMM>>>(aoh, aol, owh, owl, out_b, out);
    }
}

// round 14
// speedup vs baseline: 1.8805x; 1.0212x over previous
#include <cuda_runtime.h>
#include <cuda_bf16.h>
#include <cuda_fp16.h>
#include <stdint.h>
#include <math.h>

#define BB 2
#define SS 2048
#define EE 1024
#define HH 16
#define DD 64
#define MM (BB*SS)

// Scratch (static device globals; no runtime allocation)
__device__ float g_q[BB*HH*SS*DD];      // raw fp32 q   [B,H,S,D]
__device__ float g_vpart[BB*HH][8][DD]; // vmean partials (8 s-chunks)
__device__ float g_active[HH];
// V stored fp16, s-pair interleaved: word [bh][s2][d] = (V[2*s2][d], V[2*s2+1][d])
__device__ __align__(16) __half g_vp[BB*HH*SS*DD];
// bf16 hi/lo K for attention QK
__device__ __align__(16) __nv_bfloat16 g_kh[BB*HH*SS*DD], g_kl[BB*HH*SS*DD];
// bf16 hi/lo operand arrays for bf16 mma GEMMs
__device__ __align__(16) __nv_bfloat16 g_xh[MM*EE],   g_xl[MM*EE];     // x
__device__ __align__(16) __nv_bfloat16 g_wh[3*EE*EE], g_wl[3*EE*EE];   // qkv_w
__device__ __align__(16) __nv_bfloat16 g_owh[EE*EE],  g_owl[EE*EE];    // out_w
__device__ __align__(16) __nv_bfloat16 g_aoh[MM*EE],  g_aol[MM*EE];    // attn out [B,S,H*D]

// ---------------------------------------------------------------------------
// helpers
// ---------------------------------------------------------------------------
__device__ __forceinline__ float uaf(unsigned u) { return __uint_as_float(u); }

__device__ __forceinline__ void mma_bf16(float c[4], const unsigned a[4], const unsigned b[2]) {
    asm volatile(
        "mma.sync.aligned.m16n8k16.row.col.f32.bf16.bf16.f32 "
        "{%0,%1,%2,%3}, {%4,%5,%6,%7}, {%8,%9}, {%0,%1,%2,%3};"
        : "+f"(c[0]), "+f"(c[1]), "+f"(c[2]), "+f"(c[3])
        : "r"(a[0]), "r"(a[1]), "r"(a[2]), "r"(a[3]),
          "r"(b[0]), "r"(b[1]));
}

__device__ __forceinline__ void mma_f16(float c[4], const unsigned a[4], const unsigned b[2]) {
    asm volatile(
        "mma.sync.aligned.m16n8k16.row.col.f32.f16.f16.f32 "
        "{%0,%1,%2,%3}, {%4,%5,%6,%7}, {%8,%9}, {%0,%1,%2,%3};"
        : "+f"(c[0]), "+f"(c[1]), "+f"(c[2]), "+f"(c[3])
        : "r"(a[0]), "r"(a[1]), "r"(a[2]), "r"(a[3]),
          "r"(b[0]), "r"(b[1]));
}

__device__ __forceinline__ void ldsm4(unsigned &r0, unsigned &r1, unsigned &r2,
                                      unsigned &r3, unsigned addr) {
    asm volatile("ldmatrix.sync.aligned.m8n8.x4.shared.b16 {%0,%1,%2,%3}, [%4];"
                 : "=r"(r0), "=r"(r1), "=r"(r2), "=r"(r3) : "r"(addr));
}

__device__ __forceinline__ void cp16(unsigned dst, const void* src) {
    asm volatile("cp.async.cg.shared.global [%0], [%1], 16;\n" :: "r"(dst), "l"(src));
}
__device__ __forceinline__ void cp_commit() {
    asm volatile("cp.async.commit_group;\n");
}
__device__ __forceinline__ void cp_wait1() {
    asm volatile("cp.async.wait_group 1;\n");
}

__device__ __forceinline__ unsigned bf2u(__nv_bfloat162 v) {
    return *(unsigned*)&v;
}
__device__ __forceinline__ unsigned h2u(__half2 v) {
    return *(unsigned*)&v;
}

__device__ __forceinline__ void split_one4(const float* __restrict__ src,
                                           __nv_bfloat16* __restrict__ h,
                                           __nv_bfloat16* __restrict__ l,
                                           size_t i) {
    float4 v = ((const float4*)src)[i];
    __nv_bfloat162 h01 = __floats2bfloat162_rn(v.x, v.y);
    __nv_bfloat162 h23 = __floats2bfloat162_rn(v.z, v.w);
    *(__nv_bfloat162*)(h + 4 * i)     = h01;
    *(__nv_bfloat162*)(h + 4 * i + 2) = h23;
    __nv_bfloat162 l01 = __floats2bfloat162_rn(
        v.x - __bfloat162float(h01.x), v.y - __bfloat162float(h01.y));
    __nv_bfloat162 l23 = __floats2bfloat162_rn(
        v.z - __bfloat162float(h23.x), v.w - __bfloat162float(h23.y));
    *(__nv_bfloat162*)(l + 4 * i)     = l01;
    *(__nv_bfloat162*)(l + 4 * i + 2) = l23;
}

// ---------------------------------------------------------------------------
// prep: head mask (block 0) + all three bf16 hi/lo splits in ONE launch
// ---------------------------------------------------------------------------
#define NX4 (MM*EE/4)        // 1048576
#define NW4 (3*EE*EE/4)      //  786432
#define NO4 (EE*EE/4)        //  262144
#define PREP_BLOCKS ((NX4 + NW4 + NO4) / 256)   // 8192

__global__ void prep_kernel(const float* __restrict__ x,
                            const float* __restrict__ w,
                            const float* __restrict__ ow,
                            const float* __restrict__ gates,
                            const float* __restrict__ imp,
                            const float* __restrict__ thr) {
    if (blockIdx.x == 0 && threadIdx.x < HH) {
        const int h = threadIdx.x;
        const float z  = gates[h] * imp[h];
        const float gs = 1.0f / (1.0f + expf(-z));
        g_active[h] = (gs > thr[0]) ? 1.0f : 0.0f;
    }
    const int i = blockIdx.x * 256 + threadIdx.x;
    if (i < NX4) {
        split_one4(x, g_xh, g_xl, i);
    } else if (i < NX4 + NW4) {
        split_one4(w, g_wh, g_wl, i - NX4);
    } else {
        split_one4(ow, g_owh, g_owl, i - NX4 - NW4);
    }
}

// ---------------------------------------------------------------------------
// vmean partials: grid (BB*HH, 8); each block sums 128 s2-rows of fp16 VP
// ---------------------------------------------------------------------------
__global__ void vpart_kernel() {
    const int bh = blockIdx.x;
    if (g_active[bh & (HH - 1)] == 0.0f) return;
    const int chunk = blockIdx.y;         // 0..7
    const int d   = threadIdx.x & 63;
    const int sub = threadIdx.x >> 6;     // 0..3, 32 s2-rows each
    const __half2* vp = (const __half2*)g_vp + (size_t)bh * (SS / 2) * DD;
    const int s2b = chunk * 128 + sub * 32;
    float sum = 0.f;
    for (int s2 = s2b; s2 < s2b + 32; s2++) {
        float2 f = __half22float2(vp[(size_t)s2 * DD + d]);
        sum += f.x + f.y;
    }
    __shared__ float red[256];
    red[threadIdx.x] = sum;
    __syncthreads();
    if (sub == 0)
        g_vpart[bh][chunk][d] = red[d] + red[64 + d] + red[128 + d] + red[192 + d];
}

// ---------------------------------------------------------------------------
// 3-term bf16-split GEMM on mma.sync.m16n8k16, ldmatrix fragment loads.
// MODE 0: qkv scatter epilogue. MODE 1: row-major write.
// ---------------------------------------------------------------------------
#define GSTR  20
#define GARR  (128 * GSTR)
#define GSTG  (4 * GARR)
#define SMEM_GEMM (2 * GSTG * 4)    // 81920 B

template <int MODE>
__global__ void __launch_bounds__(256, 2) gemm_bf16_kernel(
    const __nv_bfloat16* __restrict__ Ahg, const __nv_bfloat16* __restrict__ Alg,
    const __nv_bfloat16* __restrict__ Bhg, const __nv_bfloat16* __restrict__ Blg,
    const float* __restrict__ bias, float* __restrict__ Y) {
    extern __shared__ unsigned gsm[];

    const int m0 = blockIdx.y * 128;
    const int n0 = blockIdx.x * 128;

    if (MODE == 0) {
        const int hA = (n0 & 1023) >> 6;
        if (g_active[hA] == 0.0f && g_active[hA + 1] == 0.0f) return;
    }

    const int tid  = threadIdx.x;
    const int lane = tid & 31;
    const int warp = tid >> 5;
    const int wm = (warp >> 2) * 64;
    const int wn = (warp & 3) * 32;
    const int grp = lane >> 2;
    const int tig = lane & 3;

    const int grow = tid >> 1;
    const int gkw  = (tid & 1) * 8;
    const __nv_bfloat16* Aph = Ahg + (size_t)(m0 + grow) * EE + gkw * 2;
    const __nv_bfloat16* Apl = Alg + (size_t)(m0 + grow) * EE + gkw * 2;
    const __nv_bfloat16* Bph = Bhg + (size_t)(n0 + grow) * EE + gkw * 2;
    const __nv_bfloat16* Bpl = Blg + (size_t)(n0 + grow) * EE + gkw * 2;

    const unsigned gb = (unsigned)__cvta_generic_to_shared(gsm);
    const int seg = lane >> 3, lr8 = lane & 7;
    const int arow = wm + (seg & 1) * 8 + lr8;
    const int acol = (seg >> 1) * 4;
    const int brow = wn + (seg >> 1) * 8 + lr8;
    const int bcol = (seg & 1) * 4;

    float acc[4][4][4];
#pragma unroll
    for (int i = 0; i < 4; i++)
#pragma unroll
        for (int j = 0; j < 4; j++)
#pragma unroll
            for (int r = 0; r < 4; r++) acc[i][j][r] = 0.f;

    auto store_stage = [&](int st, const uint4 p[8]) {
        unsigned* base = gsm + st * GSTG + grow * GSTR + gkw;
        *(uint4*)(base)                = p[0];
        *(uint4*)(base + 4)            = p[1];
        *(uint4*)(base + GARR)         = p[2];
        *(uint4*)(base + GARR + 4)     = p[3];
        *(uint4*)(base + 2 * GARR)     = p[4];
        *(uint4*)(base + 2 * GARR + 4) = p[5];
        *(uint4*)(base + 3 * GARR)     = p[6];
        *(uint4*)(base + 3 * GARR + 4) = p[7];
    };
    auto load_tile = [&](int kt, uint4 p[8]) {
        const size_t o = (size_t)kt * 32;
        p[0] = *(const uint4*)(Aph + o);  p[1] = *(const uint4*)(Aph + o + 8);
        p[2] = *(const uint4*)(Apl + o);  p[3] = *(const uint4*)(Apl + o + 8);
        p[4] = *(const uint4*)(Bph + o);  p[5] = *(const uint4*)(Bph + o + 8);
        p[6] = *(const uint4*)(Bpl + o);  p[7] = *(const uint4*)(Bpl + o + 8);
    };

    {
        uint4 p[8];
        load_tile(0, p);
        store_stage(0, p);
    }
    __syncthreads();

    const int NT = EE / 32;
    for (int kt = 0; kt < NT; kt++) {
        uint4 p[8];
        if (kt + 1 < NT) load_tile(kt + 1, p);

        const unsigned stb = gb + ((kt & 1) * GSTG) * 4;

#pragma unroll
        for (int ks = 0; ks < 2; ks++) {
            const int kw = ks * 8;
            unsigned bh[4][2], bl[4][2];
#pragma unroll
            for (int np = 0; np < 2; np++) {
                const unsigned addr =
                    stb + (2 * GARR + (brow + np * 16) * GSTR + kw + bcol) * 4;
                ldsm4(bh[2*np][0], bh[2*np][1], bh[2*np+1][0], bh[2*np+1][1], addr);
                ldsm4(bl[2*np][0], bl[2*np][1], bl[2*np+1][0], bl[2*np+1][1],
                      addr + GARR * 4);
            }
#pragma unroll
            for (int mi = 0; mi < 4; mi++) {
                unsigned ah[4], al[4];
                const unsigned addr =
                    stb + ((arow + mi * 16) * GSTR + kw + acol) * 4;
                ldsm4(ah[0], ah[1], ah[2], ah[3], addr);
                ldsm4(al[0], al[1], al[2], al[3], addr + GARR * 4);
#pragma unroll
                for (int ni = 0; ni < 4; ni++) {
                    mma_bf16(acc[mi][ni], ah, bh[ni]);
                    mma_bf16(acc[mi][ni], al, bh[ni]);
                    mma_bf16(acc[mi][ni], ah, bl[ni]);
                }
            }
        }

        if (kt + 1 < NT) store_stage((kt + 1) & 1, p);
        __syncthreads();
    }

    // epilogue
#pragma unroll
    for (int mi = 0; mi < 4; mi++) {
        const int rbase = m0 + wm + mi * 16 + grp;
#pragma unroll
        for (int ni = 0; ni < 4; ni++) {
            const int j = n0 + wn + ni * 8 + 2 * tig;
            const float b0 = bias[j], b1 = bias[j + 1];
#pragma unroll
            for (int rh = 0; rh < 2; rh++) {
                const int m = rbase + rh * 8;
                const float v0 = acc[mi][ni][rh * 2 + 0] + b0;
                const float v1 = acc[mi][ni][rh * 2 + 1] + b1;
                if (MODE == 1) {
                    float2 o; o.x = v0; o.y = v1;
                    *(float2*)(Y + (size_t)m * EE + j) = o;
                } else {
                    const int cc  = j >> 10;
                    const int rem = j & 1023;
                    const int h = rem >> 6, d = rem & 63;
                    const int bI = m >> 11;
                    const int s  = m & (SS - 1);
                    const size_t off = (((size_t)(bI * HH + h)) * SS + s) * DD + d;
                    if (cc == 0) {
                        float2 o; o.x = v0; o.y = v1;       // q raw
                        *(float2*)(g_q + off) = o;
                    } else if (cc == 1) {
                        __nv_bfloat162 kh = __floats2bfloat162_rn(v0, v1);
                        __nv_bfloat162 kl = __floats2bfloat162_rn(
                            v0 - __bfloat162float(kh.x), v1 - __bfloat162float(kh.y));
                        *(__nv_bfloat162*)(g_kh + off) = kh;
                        *(__nv_bfloat162*)(g_kl + off) = kl;
                    } else {
                        const float am = g_active[h];
                        const int s2 = s >> 1, so = s & 1;
                        __half* vp = g_vp + (size_t)(bI * HH + h) * SS * DD
                                   + (size_t)s2 * (2 * DD) + 2 * d + so;
                        vp[0] = __float2half_rn(v0 * am);
                        vp[2] = __float2half_rn(v1 * am);
                    }
                }
            }
        }
    }
}

// ---------------------------------------------------------------------------
// Tensor-core flash attention, v8:
//  - QK bf16 3-term (ldmatrix), PV fp16 (register-P k-pair), as validated
//  - vmean final reduction folded into preamble (from g_vpart)
// ---------------------------------------------------------------------------
#define KSTRW 36
#define TKHW  (64 * KSTRW)
#define VPSTR 72
#define TVPW  (32 * VPSTR)
#define BUFW  (2 * TKHW + TVPW)        // 6912 words
#define NSTG  3
#define SMEM_ATTN ((NSTG * BUFW + 64) * 4)   // 83200 B

__global__ void __launch_bounds__(256, 2) attn_tc_kernel() {
    extern __shared__ float sh[];

    const int tid  = threadIdx.x;
    const int lane = tid & 31;
    const int warp = tid >> 5;
    const int g8   = lane >> 2;
    const int tig  = lane & 3;
    const int wr   = warp * 16;

    const int b = blockIdx.z, h = blockIdx.y;
    const int q0 = blockIdx.x * 128;
    const size_t bh = (size_t)(b * HH + h) * SS * DD;

    if (g_active[h] == 0.0f) {
        const uint4 z = {0u, 0u, 0u, 0u};
        for (int i = tid; i < 128 * 8; i += 256) {
            const int r = i >> 3, c = (i & 7) * 8;
            const size_t off = ((size_t)(b * SS + q0 + r) * HH + h) * DD + c;
            *(uint4*)(g_aoh + off) = z;
            *(uint4*)(g_aol + off) = z;
        }
        return;
    }

    const unsigned sbase = (unsigned)__cvta_generic_to_shared(sh);
    float* vsm = sh + NSTG * BUFW;    // 64-float vmean

    // fold vmean partials (first loop barrier publishes it)
    if (tid < 64) {
        float s = 0.f;
#pragma unroll
        for (int j = 0; j < 8; j++) s += g_vpart[b * HH + h][j][tid];
        vsm[tid] = s * (1.0f / SS);
    }

    // ldmatrix lane mapping for K fragments
    const int seg = lane >> 3, lr8 = lane & 7;
    const int krow = (seg >> 1) * 8 + lr8;
    const int kcol = (seg & 1) * 4;

    // Q bf16 hi/lo fragments (32 regs)
    unsigned qh[4][4], ql[4][4];
#pragma unroll
    for (int ks = 0; ks < 4; ks++) {
        const int r0 = q0 + wr + g8;
        const int k0 = ks * 16 + 2 * tig;
        const float* qr0 = g_q + bh + (size_t)r0 * DD;
        const float* qr1 = g_q + bh + (size_t)(r0 + 8) * DD;
        float a0 = qr0[k0],     a1 = qr0[k0 + 1];
        float b0 = qr1[k0],     b1 = qr1[k0 + 1];
        float c0 = qr0[k0 + 8], c1 = qr0[k0 + 9];
        float d0 = qr1[k0 + 8], d1 = qr1[k0 + 9];
        __nv_bfloat162 ha = __floats2bfloat162_rn(a0, a1);
        __nv_bfloat162 hb = __floats2bfloat162_rn(b0, b1);
        __nv_bfloat162 hc = __floats2bfloat162_rn(c0, c1);
        __nv_bfloat162 hd = __floats2bfloat162_rn(d0, d1);
        qh[ks][0] = bf2u(ha); qh[ks][1] = bf2u(hb);
        qh[ks][2] = bf2u(hc); qh[ks][3] = bf2u(hd);
        ql[ks][0] = bf2u(__floats2bfloat162_rn(a0 - __bfloat162float(ha.x),
                                               a1 - __bfloat162float(ha.y)));
        ql[ks][1] = bf2u(__floats2bfloat162_rn(b0 - __bfloat162float(hb.x),
                                               b1 - __bfloat162float(hb.y)));
        ql[ks][2] = bf2u(__floats2bfloat162_rn(c0 - __bfloat162float(hc.x),
                                               c1 - __bfloat162float(hc.y)));
        ql[ks][3] = bf2u(__floats2bfloat162_rn(d0 - __bfloat162float(hd.x),
                                               d1 - __bfloat162float(hd.y)));
    }

    float o[8][4];
#pragma unroll
    for (int i = 0; i < 8; i++)
#pragma unroll
        for (int j = 0; j < 4; j++) o[i][j] = 0.f;
    float m0 = -1e30f, m1 = -1e30f, l0 = 0.f, l1 = 0.f;

    const unsigned* vpw = (const unsigned*)g_vp + (size_t)(b * HH + h) * (SS / 2) * DD;

    auto issue_tile = [&](int kvt, int st) {
        const int row = tid >> 2;
        const int t4  = tid & 3;
        const __nv_bfloat16* khp = g_kh + bh + (size_t)(kvt * 64 + row) * DD + t4 * 16;
        const __nv_bfloat16* klp = g_kl + bh + (size_t)(kvt * 64 + row) * DD + t4 * 16;
        const unsigned khd = sbase + (st * BUFW + row * KSTRW + t4 * 8) * 4;
        const unsigned kld = khd + TKHW * 4;
        cp16(khd,      khp);
        cp16(khd + 16, khp + 8);
        cp16(kld,      klp);
        cp16(kld + 16, klp + 8);
        const int vrow = tid >> 3;
        const int vcol = (tid & 7) * 8;
        const unsigned* vg = vpw + (size_t)(kvt * 32 + vrow) * DD + vcol;
        const unsigned vd = sbase + (st * BUFW + 2 * TKHW + vrow * VPSTR + vcol) * 4;
        cp16(vd,      vg);
        cp16(vd + 16, vg + 4);
    };

    issue_tile(0, 0); cp_commit();
    issue_tile(1, 1); cp_commit();

    const int NTILE = SS / 64;
    int stage = 0;
    for (int t = 0; t < NTILE; t++) {
        cp_wait1();
        __syncthreads();

        if (t + 2 < NTILE) {
            int st2 = stage + 2; if (st2 >= NSTG) st2 -= NSTG;
            issue_tile(t + 2, st2);
        }
        cp_commit();

        const unsigned stb = sbase + (stage * BUFW) * 4;
        const unsigned* VPu = (const unsigned*)(sh + stage * BUFW + 2 * TKHW);

        // ---- QK: bf16 3-term, ldmatrix K fragments ----
        float c[8][4];
#pragma unroll
        for (int i = 0; i < 8; i++)
#pragma unroll
            for (int j = 0; j < 4; j++) c[i][j] = 0.f;
#pragma unroll
        for (int ks = 0; ks < 4; ks++) {
            const int kw = ks * 8;
#pragma unroll
            for (int ntp = 0; ntp < 4; ntp++) {
                unsigned kh0[2], kh1[2], kl0[2], kl1[2];
                const unsigned addr =
                    stb + ((krow + ntp * 16) * KSTRW + kw + kcol) * 4;
                ldsm4(kh0[0], kh0[1], kh1[0], kh1[1], addr);
                ldsm4(kl0[0], kl0[1], kl1[0], kl1[1], addr + TKHW * 4);
                mma_bf16(c[2*ntp],     qh[ks], kh0);
                mma_bf16(c[2*ntp],     ql[ks], kh0);
                mma_bf16(c[2*ntp],     qh[ks], kl0);
                mma_bf16(c[2*ntp + 1], qh[ks], kh1);
                mma_bf16(c[2*ntp + 1], ql[ks], kh1);
                mma_bf16(c[2*ntp + 1], qh[ks], kl1);
            }
        }

        // ---- online softmax; P packed to fp16 pairs ----
        float mx0 = c[0][0], mx1 = c[0][2];
#pragma unroll
        for (int nt = 0; nt < 8; nt++) {
            mx0 = fmaxf(mx0, fmaxf(c[nt][0], c[nt][1]));
            mx1 = fmaxf(mx1, fmaxf(c[nt][2], c[nt][3]));
        }
        mx0 = fmaxf(mx0, __shfl_xor_sync(0xffffffffu, mx0, 1));
        mx0 = fmaxf(mx0, __shfl_xor_sync(0xffffffffu, mx0, 2));
        mx1 = fmaxf(mx1, __shfl_xor_sync(0xffffffffu, mx1, 1));
        mx1 = fmaxf(mx1, __shfl_xor_sync(0xffffffffu, mx1, 2));
        const float mn0 = fmaxf(m0, mx0);
        const float mn1 = fmaxf(m1, mx1);
        const float sc0 = __expf(m0 - mn0);
        const float sc1 = __expf(m1 - mn1);
        m0 = mn0; m1 = mn1;
#pragma unroll
        for (int dt = 0; dt < 8; dt++) {
            o[dt][0] *= sc0; o[dt][1] *= sc0;
            o[dt][2] *= sc1; o[dt][3] *= sc1;
        }
        unsigned hp[8][2];
        float s0 = 0.f, s1 = 0.f;
#pragma unroll
        for (int nt = 0; nt < 8; nt++) {
            const float p00 = __expf(c[nt][0] - m0);
            const float p01 = __expf(c[nt][1] - m0);
            const float p10 = __expf(c[nt][2] - m1);
            const float p11 = __expf(c[nt][3] - m1);
            __half2 w0 = __floats2half2_rn(p00, p01);
            __half2 w1 = __floats2half2_rn(p10, p11);
            hp[nt][0] = h2u(w0);
            hp[nt][1] = h2u(w1);
            float2 f0 = __half22float2(w0);
            float2 f1 = __half22float2(w1);
            s0 += f0.x + f0.y;
            s1 += f1.x + f1.y;
        }
        s0 += __shfl_xor_sync(0xffffffffu, s0, 1);
        s0 += __shfl_xor_sync(0xffffffffu, s0, 2);
        s1 += __shfl_xor_sync(0xffffffffu, s1, 1);
        s1 += __shfl_xor_sync(0xffffffffu, s1, 2);
        l0 = l0 * sc0 + s0;
        l1 = l1 * sc1 + s1;

        // ---- PV: fp16 m16n8k16; A-frag = own packed P registers ----
#pragma unroll
        for (int ks = 0; ks < 4; ks++) {
            unsigned aa[4] = {hp[2*ks][0], hp[2*ks][1],
                              hp[2*ks + 1][0], hp[2*ks + 1][1]};
            const int r0 = (8 * ks + tig) * VPSTR;
#pragma unroll
            for (int dt = 0; dt < 8; dt++) {
                unsigned bb[2];
                bb[0] = VPu[r0 + dt * 8 + g8];
                bb[1] = VPu[r0 + 4 * VPSTR + dt * 8 + g8];
                mma_f16(o[dt], aa, bb);
            }
        }

        stage = (stage + 1 == NSTG) ? 0 : stage + 1;
    }

    // epilogue: normalize, add vmean (from smem), emit bf16 hi/lo
    const float inv0 = 1.0f / l0;
    const float inv1 = 1.0f / l1;
    const int r0 = q0 + wr + g8;
    const size_t ob0 = ((size_t)(b * SS + r0) * HH + h) * DD;
    const size_t ob1 = ((size_t)(b * SS + r0 + 8) * HH + h) * DD;
#pragma unroll
    for (int dt = 0; dt < 8; dt++) {
        const int col = dt * 8 + 2 * tig;
        const float v0 = vsm[col], v1 = vsm[col + 1];
        const float f00 = o[dt][0] * inv0 + v0, f01 = o[dt][1] * inv0 + v1;
        const float f10 = o[dt][2] * inv1 + v0, f11 = o[dt][3] * inv1 + v1;
        __nv_bfloat162 h0 = __floats2bfloat162_rn(f00, f01);
        __nv_bfloat162 h1 = __floats2bfloat162_rn(f10, f11);
        __nv_bfloat162 lo0 = __floats2bfloat162_rn(
            f00 - __bfloat162float(h0.x), f01 - __bfloat162float(h0.y));
        __nv_bfloat162 lo1 = __floats2bfloat162_rn(
            f10 - __bfloat162float(h1.x), f11 - __bfloat162float(h1.y));
        *(__nv_bfloat162*)(g_aoh + ob0 + col) = h0;
        *(__nv_bfloat162*)(g_aol + ob0 + col) = lo0;
        *(__nv_bfloat162*)(g_aoh + ob1 + col) = h1;
        *(__nv_bfloat162*)(g_aol + ob1 + col) = lo1;
    }
}

// ---------------------------------------------------------------------------
extern "C" void kernel_launch(void* const* d_in, const int* in_sizes, int n_in,
                              void* d_out, int out_size) {
    const float* x      = (const float*)d_in[0];
    const float* qkv_w  = (const float*)d_in[1];
    const float* qkv_b  = (const float*)d_in[2];
    const float* out_w  = (const float*)d_in[3];
    const float* out_b  = (const float*)d_in[4];
    const float* gates  = (const float*)d_in[5];
    const float* imp    = (const float*)d_in[6];
    const float* thr    = (const float*)d_in[7];
    float* out = (float*)d_out;

    static bool attr_set = false;
    if (!attr_set) {
        cudaFuncSetAttribute(attn_tc_kernel,
                             cudaFuncAttributeMaxDynamicSharedMemorySize, SMEM_ATTN);
        cudaFuncSetAttribute(gemm_bf16_kernel<0>,
                             cudaFuncAttributeMaxDynamicSharedMemorySize, SMEM_GEMM);
        cudaFuncSetAttribute(gemm_bf16_kernel<1>,
                             cudaFuncAttributeMaxDynamicSharedMemorySize, SMEM_GEMM);
        attr_set = true;
    }

    __nv_bfloat16 *xh, *xl, *wh, *wl, *owh, *owl, *aoh, *aol;
    cudaGetSymbolAddress((void**)&xh,  g_xh);
    cudaGetSymbolAddress((void**)&xl,  g_xl);
    cudaGetSymbolAddress((void**)&wh,  g_wh);
    cudaGetSymbolAddress((void**)&wl,  g_wl);
    cudaGetSymbolAddress((void**)&owh, g_owh);
    cudaGetSymbolAddress((void**)&owl, g_owl);
    cudaGetSymbolAddress((void**)&aoh, g_aoh);
    cudaGetSymbolAddress((void**)&aol, g_aol);

    // fused mask + splits
    prep_kernel<<<PREP_BLOCKS, 256>>>(x, qkv_w, out_w, gates, imp, thr);

    // QKV projection (3-term bf16 split, m16n8k16 + ldmatrix)
    {
        dim3 g(3 * EE / 128, MM / 128);      // 24 x 32
        gemm_bf16_kernel<0><<<g, 256, SMEM_GEMM>>>(xh, xl, wh, wl, qkv_b, nullptr);
    }

    // vmean partials (full-chip parallel, deterministic)
    {
        dim3 g(BB * HH, 8);
        vpart_kernel<<<g, 256>>>();
    }

    // Attention (bf16 QK 3-term + fp16 PV; folds vmean reduction)
    {
        dim3 g(SS / 128, HH, BB);            // 16 x 16 x 2
        attn_tc_kernel<<<g, 256, SMEM_ATTN>>>();
    }

    // Output projection (3-term bf16 split, m16n8k16 + ldmatrix)
    {
        dim3 g(EE / 128, MM / 128);          // 8 x 32
        gemm_bf16_kernel<1><<<g, 256, SMEM_GEMM>>>(aoh, aol, owh, owl, out_b, out);
    }
}

// round 15
// speedup vs baseline: 2.1190x; 1.1268x over previous
#include <cuda_runtime.h>
#include <cuda_bf16.h>
#include <cuda_fp16.h>
#include <stdint.h>
#include <math.h>

#define BB 2
#define SS 2048
#define EE 1024
#define HH 16
#define DD 64
#define MM (BB*SS)

// Scratch (static device globals; no runtime allocation)
__device__ float g_q[BB*HH*SS*DD];      // raw fp32 q   [B,H,S,D]
__device__ float g_vpart[BB*HH][8][DD]; // vmean partials (8 s-chunks)
__device__ float g_active[HH];
// V stored fp16, s-pair interleaved: word [bh][s2][d] = (V[2*s2][d], V[2*s2+1][d])
__device__ __align__(16) __half g_vp[BB*HH*SS*DD];
// bf16 hi/lo K for attention QK
__device__ __align__(16) __nv_bfloat16 g_kh[BB*HH*SS*DD], g_kl[BB*HH*SS*DD];
// bf16 hi/lo operand arrays for bf16 mma GEMMs
__device__ __align__(16) __nv_bfloat16 g_xh[MM*EE],   g_xl[MM*EE];     // x
__device__ __align__(16) __nv_bfloat16 g_wh[3*EE*EE], g_wl[3*EE*EE];   // qkv_w
__device__ __align__(16) __nv_bfloat16 g_owh[EE*EE],  g_owl[EE*EE];    // out_w
__device__ __align__(16) __nv_bfloat16 g_aoh[MM*EE],  g_aol[MM*EE];    // attn out [B,S,H*D]

// ---------------------------------------------------------------------------
// helpers
// ---------------------------------------------------------------------------
__device__ __forceinline__ float uaf(unsigned u) { return __uint_as_float(u); }

__device__ __forceinline__ void mma_bf16(float c[4], const unsigned a[4], const unsigned b[2]) {
    asm volatile(
        "mma.sync.aligned.m16n8k16.row.col.f32.bf16.bf16.f32 "
        "{%0,%1,%2,%3}, {%4,%5,%6,%7}, {%8,%9}, {%0,%1,%2,%3};"
        : "+f"(c[0]), "+f"(c[1]), "+f"(c[2]), "+f"(c[3])
        : "r"(a[0]), "r"(a[1]), "r"(a[2]), "r"(a[3]),
          "r"(b[0]), "r"(b[1]));
}

__device__ __forceinline__ void mma_f16(float c[4], const unsigned a[4], const unsigned b[2]) {
    asm volatile(
        "mma.sync.aligned.m16n8k16.row.col.f32.f16.f16.f32 "
        "{%0,%1,%2,%3}, {%4,%5,%6,%7}, {%8,%9}, {%0,%1,%2,%3};"
        : "+f"(c[0]), "+f"(c[1]), "+f"(c[2]), "+f"(c[3])
        : "r"(a[0]), "r"(a[1]), "r"(a[2]), "r"(a[3]),
          "r"(b[0]), "r"(b[1]));
}

__device__ __forceinline__ void ldsm4(unsigned &r0, unsigned &r1, unsigned &r2,
                                      unsigned &r3, unsigned addr) {
    asm volatile("ldmatrix.sync.aligned.m8n8.x4.shared.b16 {%0,%1,%2,%3}, [%4];"
                 : "=r"(r0), "=r"(r1), "=r"(r2), "=r"(r3) : "r"(addr));
}

__device__ __forceinline__ void cp16(unsigned dst, const void* src) {
    asm volatile("cp.async.cg.shared.global [%0], [%1], 16;\n" :: "r"(dst), "l"(src));
}
__device__ __forceinline__ void cp_commit() {
    asm volatile("cp.async.commit_group;\n");
}
__device__ __forceinline__ void cp_wait1() {
    asm volatile("cp.async.wait_group 1;\n");
}
__device__ __forceinline__ void cp_wait0() {
    asm volatile("cp.async.wait_group 0;\n");
}

__device__ __forceinline__ unsigned bf2u(__nv_bfloat162 v) {
    return *(unsigned*)&v;
}
__device__ __forceinline__ unsigned h2u(__half2 v) {
    return *(unsigned*)&v;
}

__device__ __forceinline__ void split_one4(const float* __restrict__ src,
                                           __nv_bfloat16* __restrict__ h,
                                           __nv_bfloat16* __restrict__ l,
                                           size_t i) {
    float4 v = ((const float4*)src)[i];
    __nv_bfloat162 h01 = __floats2bfloat162_rn(v.x, v.y);
    __nv_bfloat162 h23 = __floats2bfloat162_rn(v.z, v.w);
    *(__nv_bfloat162*)(h + 4 * i)     = h01;
    *(__nv_bfloat162*)(h + 4 * i + 2) = h23;
    __nv_bfloat162 l01 = __floats2bfloat162_rn(
        v.x - __bfloat162float(h01.x), v.y - __bfloat162float(h01.y));
    __nv_bfloat162 l23 = __floats2bfloat162_rn(
        v.z - __bfloat162float(h23.x), v.w - __bfloat162float(h23.y));
    *(__nv_bfloat162*)(l + 4 * i)     = l01;
    *(__nv_bfloat162*)(l + 4 * i + 2) = l23;
}

// ---------------------------------------------------------------------------
// prep: head mask (block 0) + all three bf16 hi/lo splits in ONE launch
// ---------------------------------------------------------------------------
#define NX4 (MM*EE/4)        // 1048576
#define NW4 (3*EE*EE/4)      //  786432
#define NO4 (EE*EE/4)        //  262144
#define PREP_BLOCKS ((NX4 + NW4 + NO4) / 256)   // 8192

__global__ void prep_kernel(const float* __restrict__ x,
                            const float* __restrict__ w,
                            const float* __restrict__ ow,
                            const float* __restrict__ gates,
                            const float* __restrict__ imp,
                            const float* __restrict__ thr) {
    if (blockIdx.x == 0 && threadIdx.x < HH) {
        const int h = threadIdx.x;
        const float z  = gates[h] * imp[h];
        const float gs = 1.0f / (1.0f + expf(-z));
        g_active[h] = (gs > thr[0]) ? 1.0f : 0.0f;
    }
    const int i = blockIdx.x * 256 + threadIdx.x;
    if (i < NX4) {
        split_one4(x, g_xh, g_xl, i);
    } else if (i < NX4 + NW4) {
        split_one4(w, g_wh, g_wl, i - NX4);
    } else {
        split_one4(ow, g_owh, g_owl, i - NX4 - NW4);
    }
}

// ---------------------------------------------------------------------------
// vmean partials: grid (BB*HH, 8); each block sums 128 s2-rows of fp16 VP
// ---------------------------------------------------------------------------
__global__ void vpart_kernel() {
    const int bh = blockIdx.x;
    if (g_active[bh & (HH - 1)] == 0.0f) return;
    const int chunk = blockIdx.y;         // 0..7
    const int d   = threadIdx.x & 63;
    const int sub = threadIdx.x >> 6;     // 0..3, 32 s2-rows each
    const __half2* vp = (const __half2*)g_vp + (size_t)bh * (SS / 2) * DD;
    const int s2b = chunk * 128 + sub * 32;
    float sum = 0.f;
    for (int s2 = s2b; s2 < s2b + 32; s2++) {
        float2 f = __half22float2(vp[(size_t)s2 * DD + d]);
        sum += f.x + f.y;
    }
    __shared__ float red[256];
    red[threadIdx.x] = sum;
    __syncthreads();
    if (sub == 0)
        g_vpart[bh][chunk][d] = red[d] + red[64 + d] + red[128 + d] + red[192 + d];
}

// ---------------------------------------------------------------------------
// 3-term bf16-split GEMM on mma.sync.m16n8k16, ldmatrix frags, cp.async staging.
// MODE 0: qkv scatter epilogue. MODE 1: row-major write.
// ---------------------------------------------------------------------------
#define GSTR  20
#define GARR  (128 * GSTR)
#define GSTG  (4 * GARR)
#define SMEM_GEMM (2 * GSTG * 4)    // 81920 B

template <int MODE>
__global__ void __launch_bounds__(256, 2) gemm_bf16_kernel(
    const __nv_bfloat16* __restrict__ Ahg, const __nv_bfloat16* __restrict__ Alg,
    const __nv_bfloat16* __restrict__ Bhg, const __nv_bfloat16* __restrict__ Blg,
    const float* __restrict__ bias, float* __restrict__ Y) {
    extern __shared__ unsigned gsm[];

    const int m0 = blockIdx.y * 128;
    const int n0 = blockIdx.x * 128;

    if (MODE == 0) {
        const int hA = (n0 & 1023) >> 6;
        if (g_active[hA] == 0.0f && g_active[hA + 1] == 0.0f) return;
    }

    const int tid  = threadIdx.x;
    const int lane = tid & 31;
    const int warp = tid >> 5;
    const int wm = (warp >> 2) * 64;
    const int wn = (warp & 3) * 32;
    const int grp = lane >> 2;
    const int tig = lane & 3;

    const int grow = tid >> 1;
    const int gkw  = (tid & 1) * 8;
    const __nv_bfloat16* Aph = Ahg + (size_t)(m0 + grow) * EE + gkw * 2;
    const __nv_bfloat16* Apl = Alg + (size_t)(m0 + grow) * EE + gkw * 2;
    const __nv_bfloat16* Bph = Bhg + (size_t)(n0 + grow) * EE + gkw * 2;
    const __nv_bfloat16* Bpl = Blg + (size_t)(n0 + grow) * EE + gkw * 2;

    const unsigned gb = (unsigned)__cvta_generic_to_shared(gsm);
    const int seg = lane >> 3, lr8 = lane & 7;
    const int arow = wm + (seg & 1) * 8 + lr8;
    const int acol = (seg >> 1) * 4;
    const int brow = wn + (seg >> 1) * 8 + lr8;
    const int bcol = (seg & 1) * 4;

    float acc[4][4][4];
#pragma unroll
    for (int i = 0; i < 4; i++)
#pragma unroll
        for (int j = 0; j < 4; j++)
#pragma unroll
            for (int r = 0; r < 4; r++) acc[i][j][r] = 0.f;

    // cp.async staging: 8 x 16B per thread per tile
    auto issue_tile = [&](int kt, int st) {
        const size_t o = (size_t)kt * 32;       // bf16 elements
        const unsigned base = gb + (st * GSTG + grow * GSTR + gkw) * 4;
        cp16(base,                    Aph + o);
        cp16(base + 16,               Aph + o + 8);
        cp16(base + GARR * 4,         Apl + o);
        cp16(base + GARR * 4 + 16,    Apl + o + 8);
        cp16(base + 2 * GARR * 4,     Bph + o);
        cp16(base + 2 * GARR * 4 + 16, Bph + o + 8);
        cp16(base + 3 * GARR * 4,     Bpl + o);
        cp16(base + 3 * GARR * 4 + 16, Bpl + o + 8);
    };

    issue_tile(0, 0);
    cp_commit();

    const int NT = EE / 32;
    for (int kt = 0; kt < NT; kt++) {
        cp_wait0();          // tile kt resident (only group outstanding)
        __syncthreads();     // all warps see kt; all warps done with kt-1's stage

        if (kt + 1 < NT) issue_tile(kt + 1, (kt + 1) & 1);  // overlaps compute
        cp_commit();

        const unsigned stb = gb + ((kt & 1) * GSTG) * 4;

#pragma unroll
        for (int ks = 0; ks < 2; ks++) {
            const int kw = ks * 8;
            unsigned bh[4][2], bl[4][2];
#pragma unroll
            for (int np = 0; np < 2; np++) {
                const unsigned addr =
                    stb + (2 * GARR + (brow + np * 16) * GSTR + kw + bcol) * 4;
                ldsm4(bh[2*np][0], bh[2*np][1], bh[2*np+1][0], bh[2*np+1][1], addr);
                ldsm4(bl[2*np][0], bl[2*np][1], bl[2*np+1][0], bl[2*np+1][1],
                      addr + GARR * 4);
            }
#pragma unroll
            for (int mi = 0; mi < 4; mi++) {
                unsigned ah[4], al[4];
                const unsigned addr =
                    stb + ((arow + mi * 16) * GSTR + kw + acol) * 4;
                ldsm4(ah[0], ah[1], ah[2], ah[3], addr);
                ldsm4(al[0], al[1], al[2], al[3], addr + GARR * 4);
#pragma unroll
                for (int ni = 0; ni < 4; ni++) {
                    mma_bf16(acc[mi][ni], ah, bh[ni]);
                    mma_bf16(acc[mi][ni], al, bh[ni]);
                    mma_bf16(acc[mi][ni], ah, bl[ni]);
                }
            }
        }
    }

    // epilogue
#pragma unroll
    for (int mi = 0; mi < 4; mi++) {
        const int rbase = m0 + wm + mi * 16 + grp;
#pragma unroll
        for (int ni = 0; ni < 4; ni++) {
            const int j = n0 + wn + ni * 8 + 2 * tig;
            const float b0 = bias[j], b1 = bias[j + 1];
#pragma unroll
            for (int rh = 0; rh < 2; rh++) {
                const int m = rbase + rh * 8;
                const float v0 = acc[mi][ni][rh * 2 + 0] + b0;
                const float v1 = acc[mi][ni][rh * 2 + 1] + b1;
                if (MODE == 1) {
                    float2 o; o.x = v0; o.y = v1;
                    *(float2*)(Y + (size_t)m * EE + j) = o;
                } else {
                    const int cc  = j >> 10;
                    const int rem = j & 1023;
                    const int h = rem >> 6, d = rem & 63;
                    const int bI = m >> 11;
                    const int s  = m & (SS - 1);
                    const size_t off = (((size_t)(bI * HH + h)) * SS + s) * DD + d;
                    if (cc == 0) {
                        float2 o; o.x = v0; o.y = v1;       // q raw
                        *(float2*)(g_q + off) = o;
                    } else if (cc == 1) {
                        __nv_bfloat162 kh = __floats2bfloat162_rn(v0, v1);
                        __nv_bfloat162 kl = __floats2bfloat162_rn(
                            v0 - __bfloat162float(kh.x), v1 - __bfloat162float(kh.y));
                        *(__nv_bfloat162*)(g_kh + off) = kh;
                        *(__nv_bfloat162*)(g_kl + off) = kl;
                    } else {
                        const float am = g_active[h];
                        const int s2 = s >> 1, so = s & 1;
                        __half* vp = g_vp + (size_t)(bI * HH + h) * SS * DD
                                   + (size_t)s2 * (2 * DD) + 2 * d + so;
                        vp[0] = __float2half_rn(v0 * am);
                        vp[2] = __float2half_rn(v1 * am);
                    }
                }
            }
        }
    }
}

// ---------------------------------------------------------------------------
// Tensor-core flash attention, v8 (validated): QK bf16 3-term (ldmatrix),
// PV fp16 (register-P k-pair), vmean folded, 3-stage cp.async ring.
// ---------------------------------------------------------------------------
#define KSTRW 36
#define TKHW  (64 * KSTRW)
#define VPSTR 72
#define TVPW  (32 * VPSTR)
#define BUFW  (2 * TKHW + TVPW)        // 6912 words
#define NSTG  3
#define SMEM_ATTN ((NSTG * BUFW + 64) * 4)   // 83200 B

__global__ void __launch_bounds__(256, 2) attn_tc_kernel() {
    extern __shared__ float sh[];

    const int tid  = threadIdx.x;
    const int lane = tid & 31;
    const int warp = tid >> 5;
    const int g8   = lane >> 2;
    const int tig  = lane & 3;
    const int wr   = warp * 16;

    const int b = blockIdx.z, h = blockIdx.y;
    const int q0 = blockIdx.x * 128;
    const size_t bh = (size_t)(b * HH + h) * SS * DD;

    if (g_active[h] == 0.0f) {
        const uint4 z = {0u, 0u, 0u, 0u};
        for (int i = tid; i < 128 * 8; i += 256) {
            const int r = i >> 3, c = (i & 7) * 8;
            const size_t off = ((size_t)(b * SS + q0 + r) * HH + h) * DD + c;
            *(uint4*)(g_aoh + off) = z;
            *(uint4*)(g_aol + off) = z;
        }
        return;
    }

    const unsigned sbase = (unsigned)__cvta_generic_to_shared(sh);
    float* vsm = sh + NSTG * BUFW;    // 64-float vmean

    if (tid < 64) {
        float s = 0.f;
#pragma unroll
        for (int j = 0; j < 8; j++) s += g_vpart[b * HH + h][j][tid];
        vsm[tid] = s * (1.0f / SS);
    }

    const int seg = lane >> 3, lr8 = lane & 7;
    const int krow = (seg >> 1) * 8 + lr8;
    const int kcol = (seg & 1) * 4;

    unsigned qh[4][4], ql[4][4];
#pragma unroll
    for (int ks = 0; ks < 4; ks++) {
        const int r0 = q0 + wr + g8;
        const int k0 = ks * 16 + 2 * tig;
        const float* qr0 = g_q + bh + (size_t)r0 * DD;
        const float* qr1 = g_q + bh + (size_t)(r0 + 8) * DD;
        float a0 = qr0[k0],     a1 = qr0[k0 + 1];
        float b0 = qr1[k0],     b1 = qr1[k0 + 1];
        float c0 = qr0[k0 + 8], c1 = qr0[k0 + 9];
        float d0 = qr1[k0 + 8], d1 = qr1[k0 + 9];
        __nv_bfloat162 ha = __floats2bfloat162_rn(a0, a1);
        __nv_bfloat162 hb = __floats2bfloat162_rn(b0, b1);
        __nv_bfloat162 hc = __floats2bfloat162_rn(c0, c1);
        __nv_bfloat162 hd = __floats2bfloat162_rn(d0, d1);
        qh[ks][0] = bf2u(ha); qh[ks][1] = bf2u(hb);
        qh[ks][2] = bf2u(hc); qh[ks][3] = bf2u(hd);
        ql[ks][0] = bf2u(__floats2bfloat162_rn(a0 - __bfloat162float(ha.x),
                                               a1 - __bfloat162float(ha.y)));
        ql[ks][1] = bf2u(__floats2bfloat162_rn(b0 - __bfloat162float(hb.x),
                                               b1 - __bfloat162float(hb.y)));
        ql[ks][2] = bf2u(__floats2bfloat162_rn(c0 - __bfloat162float(hc.x),
                                               c1 - __bfloat162float(hc.y)));
        ql[ks][3] = bf2u(__floats2bfloat162_rn(d0 - __bfloat162float(hd.x),
                                               d1 - __bfloat162float(hd.y)));
    }

    float o[8][4];
#pragma unroll
    for (int i = 0; i < 8; i++)
#pragma unroll
        for (int j = 0; j < 4; j++) o[i][j] = 0.f;
    float m0 = -1e30f, m1 = -1e30f, l0 = 0.f, l1 = 0.f;

    const unsigned* vpw = (const unsigned*)g_vp + (size_t)(b * HH + h) * (SS / 2) * DD;

    auto issue_tile = [&](int kvt, int st) {
        const int row = tid >> 2;
        const int t4  = tid & 3;
        const __nv_bfloat16* khp = g_kh + bh + (size_t)(kvt * 64 + row) * DD + t4 * 16;
        const __nv_bfloat16* klp = g_kl + bh + (size_t)(kvt * 64 + row) * DD + t4 * 16;
        const unsigned khd = sbase + (st * BUFW + row * KSTRW + t4 * 8) * 4;
        const unsigned kld = khd + TKHW * 4;
        cp16(khd,      khp);
        cp16(khd + 16, khp + 8);
        cp16(kld,      klp);
        cp16(kld + 16, klp + 8);
        const int vrow = tid >> 3;
        const int vcol = (tid & 7) * 8;
        const unsigned* vg = vpw + (size_t)(kvt * 32 + vrow) * DD + vcol;
        const unsigned vd = sbase + (st * BUFW + 2 * TKHW + vrow * VPSTR + vcol) * 4;
        cp16(vd,      vg);
        cp16(vd + 16, vg + 4);
    };

    issue_tile(0, 0); cp_commit();
    issue_tile(1, 1); cp_commit();

    const int NTILE = SS / 64;
    int stage = 0;
    for (int t = 0; t < NTILE; t++) {
        cp_wait1();
        __syncthreads();

        if (t + 2 < NTILE) {
            int st2 = stage + 2; if (st2 >= NSTG) st2 -= NSTG;
            issue_tile(t + 2, st2);
        }
        cp_commit();

        const unsigned stb = sbase + (stage * BUFW) * 4;
        const unsigned* VPu = (const unsigned*)(sh + stage * BUFW + 2 * TKHW);

        float c[8][4];
#pragma unroll
        for (int i = 0; i < 8; i++)
#pragma unroll
            for (int j = 0; j < 4; j++) c[i][j] = 0.f;
#pragma unroll
        for (int ks = 0; ks < 4; ks++) {
            const int kw = ks * 8;
#pragma unroll
            for (int ntp = 0; ntp < 4; ntp++) {
                unsigned kh0[2], kh1[2], kl0[2], kl1[2];
                const unsigned addr =
                    stb + ((krow + ntp * 16) * KSTRW + kw + kcol) * 4;
                ldsm4(kh0[0], kh0[1], kh1[0], kh1[1], addr);
                ldsm4(kl0[0], kl0[1], kl1[0], kl1[1], addr + TKHW * 4);
                mma_bf16(c[2*ntp],     qh[ks], kh0);
                mma_bf16(c[2*ntp],     ql[ks], kh0);
                mma_bf16(c[2*ntp],     qh[ks], kl0);
                mma_bf16(c[2*ntp + 1], qh[ks], kh1);
                mma_bf16(c[2*ntp + 1], ql[ks], kh1);
                mma_bf16(c[2*ntp + 1], qh[ks], kl1);
            }
        }

        float mx0 = c[0][0], mx1 = c[0][2];
#pragma unroll
        for (int nt = 0; nt < 8; nt++) {
            mx0 = fmaxf(mx0, fmaxf(c[nt][0], c[nt][1]));
            mx1 = fmaxf(mx1, fmaxf(c[nt][2], c[nt][3]));
        }
        mx0 = fmaxf(mx0, __shfl_xor_sync(0xffffffffu, mx0, 1));
        mx0 = fmaxf(mx0, __shfl_xor_sync(0xffffffffu, mx0, 2));
        mx1 = fmaxf(mx1, __shfl_xor_sync(0xffffffffu, mx1, 1));
        mx1 = fmaxf(mx1, __shfl_xor_sync(0xffffffffu, mx1, 2));
        const float mn0 = fmaxf(m0, mx0);
        const float mn1 = fmaxf(m1, mx1);
        const float sc0 = __expf(m0 - mn0);
        const float sc1 = __expf(m1 - mn1);
        m0 = mn0; m1 = mn1;
#pragma unroll
        for (int dt = 0; dt < 8; dt++) {
            o[dt][0] *= sc0; o[dt][1] *= sc0;
            o[dt][2] *= sc1; o[dt][3] *= sc1;
        }
        unsigned hp[8][2];
        float s0 = 0.f, s1 = 0.f;
#pragma unroll
        for (int nt = 0; nt < 8; nt++) {
            const float p00 = __expf(c[nt][0] - m0);
            const float p01 = __expf(c[nt][1] - m0);
            const float p10 = __expf(c[nt][2] - m1);
            const float p11 = __expf(c[nt][3] - m1);
            __half2 w0 = __floats2half2_rn(p00, p01);
            __half2 w1 = __floats2half2_rn(p10, p11);
            hp[nt][0] = h2u(w0);
            hp[nt][1] = h2u(w1);
            float2 f0 = __half22float2(w0);
            float2 f1 = __half22float2(w1);
            s0 += f0.x + f0.y;
            s1 += f1.x + f1.y;
        }
        s0 += __shfl_xor_sync(0xffffffffu, s0, 1);
        s0 += __shfl_xor_sync(0xffffffffu, s0, 2);
        s1 += __shfl_xor_sync(0xffffffffu, s1, 1);
        s1 += __shfl_xor_sync(0xffffffffu, s1, 2);
        l0 = l0 * sc0 + s0;
        l1 = l1 * sc1 + s1;

#pragma unroll
        for (int ks = 0; ks < 4; ks++) {
            unsigned aa[4] = {hp[2*ks][0], hp[2*ks][1],
                              hp[2*ks + 1][0], hp[2*ks + 1][1]};
            const int r0 = (8 * ks + tig) * VPSTR;
#pragma unroll
            for (int dt = 0; dt < 8; dt++) {
                unsigned bb[2];
                bb[0] = VPu[r0 + dt * 8 + g8];
                bb[1] = VPu[r0 + 4 * VPSTR + dt * 8 + g8];
                mma_f16(o[dt], aa, bb);
            }
        }

        stage = (stage + 1 == NSTG) ? 0 : stage + 1;
    }

    const float inv0 = 1.0f / l0;
    const float inv1 = 1.0f / l1;
    const int r0 = q0 + wr + g8;
    const size_t ob0 = ((size_t)(b * SS + r0) * HH + h) * DD;
    const size_t ob1 = ((size_t)(b * SS + r0 + 8) * HH + h) * DD;
#pragma unroll
    for (int dt = 0; dt < 8; dt++) {
        const int col = dt * 8 + 2 * tig;
        const float v0 = vsm[col], v1 = vsm[col + 1];
        const float f00 = o[dt][0] * inv0 + v0, f01 = o[dt][1] * inv0 + v1;
        const float f10 = o[dt][2] * inv1 + v0, f11 = o[dt][3] * inv1 + v1;
        __nv_bfloat162 h0 = __floats2bfloat162_rn(f00, f01);
        __nv_bfloat162 h1 = __floats2bfloat162_rn(f10, f11);
        __nv_bfloat162 lo0 = __floats2bfloat162_rn(
            f00 - __bfloat162float(h0.x), f01 - __bfloat162float(h0.y));
        __nv_bfloat162 lo1 = __floats2bfloat162_rn(
            f10 - __bfloat162float(h1.x), f11 - __bfloat162float(h1.y));
        *(__nv_bfloat162*)(g_aoh + ob0 + col) = h0;
        *(__nv_bfloat162*)(g_aol + ob0 + col) = lo0;
        *(__nv_bfloat162*)(g_aoh + ob1 + col) = h1;
        *(__nv_bfloat162*)(g_aol + ob1 + col) = lo1;
    }
}

// ---------------------------------------------------------------------------
extern "C" void kernel_launch(void* const* d_in, const int* in_sizes, int n_in,
                              void* d_out, int out_size) {
    const float* x      = (const float*)d_in[0];
    const float* qkv_w  = (const float*)d_in[1];
    const float* qkv_b  = (const float*)d_in[2];
    const float* out_w  = (const float*)d_in[3];
    const float* out_b  = (const float*)d_in[4];
    const float* gates  = (const float*)d_in[5];
    const float* imp    = (const float*)d_in[6];
    const float* thr    = (const float*)d_in[7];
    float* out = (float*)d_out;

    static bool attr_set = false;
    if (!attr_set) {
        cudaFuncSetAttribute(attn_tc_kernel,
                             cudaFuncAttributeMaxDynamicSharedMemorySize, SMEM_ATTN);
        cudaFuncSetAttribute(gemm_bf16_kernel<0>,
                             cudaFuncAttributeMaxDynamicSharedMemorySize, SMEM_GEMM);
        cudaFuncSetAttribute(gemm_bf16_kernel<1>,
                             cudaFuncAttributeMaxDynamicSharedMemorySize, SMEM_GEMM);
        attr_set = true;
    }

    __nv_bfloat16 *xh, *xl, *wh, *wl, *owh, *owl, *aoh, *aol;
    cudaGetSymbolAddress((void**)&xh,  g_xh);
    cudaGetSymbolAddress((void**)&xl,  g_xl);
    cudaGetSymbolAddress((void**)&wh,  g_wh);
    cudaGetSymbolAddress((void**)&wl,  g_wl);
    cudaGetSymbolAddress((void**)&owh, g_owh);
    cudaGetSymbolAddress((void**)&owl, g_owl);
    cudaGetSymbolAddress((void**)&aoh, g_aoh);
    cudaGetSymbolAddress((void**)&aol, g_aol);

    // fused mask + splits
    prep_kernel<<<PREP_BLOCKS, 256>>>(x, qkv_w, out_w, gates, imp, thr);

    // QKV projection (3-term bf16 split, m16n8k16 + ldmatrix + cp.async)
    {
        dim3 g(3 * EE / 128, MM / 128);      // 24 x 32
        gemm_bf16_kernel<0><<<g, 256, SMEM_GEMM>>>(xh, xl, wh, wl, qkv_b, nullptr);
    }

    // vmean partials
    {
        dim3 g(BB * HH, 8);
        vpart_kernel<<<g, 256>>>();
    }

    // Attention (bf16 QK 3-term + fp16 PV; folds vmean reduction)
    {
        dim3 g(SS / 128, HH, BB);            // 16 x 16 x 2
        attn_tc_kernel<<<g, 256, SMEM_ATTN>>>();
    }

    // Output projection (3-term bf16 split, m16n8k16 + ldmatrix + cp.async)
    {
        dim3 g(EE / 128, MM / 128);          // 8 x 32
        gemm_bf16_kernel<1><<<g, 256, SMEM_GEMM>>>(aoh, aol, owh, owl, out_b, out);
    }
}

// round 16
// speedup vs baseline: 2.1530x; 1.0161x over previous
#include <cuda_runtime.h>
#include <cuda_bf16.h>
#include <cuda_fp16.h>
#include <stdint.h>
#include <math.h>

#define BB 2
#define SS 2048
#define EE 1024
#define HH 16
#define DD 64
#define MM (BB*SS)
#define LOG2E 1.4426950408889634f

// Scratch (static device globals; no runtime allocation)
__device__ float g_q[BB*HH*SS*DD];      // raw fp32 q   [B,H,S,D]
__device__ float g_vmean[BB*HH*DD];
__device__ float g_active[HH];
// V stored fp16 TRANSPOSED d-major: word [bh][d][s2] = (V[2*s2][d], V[2*s2+1][d])
__device__ __align__(16) __half g_vpt[BB*HH*SS*DD];
// bf16 hi/lo K for attention QK
__device__ __align__(16) __nv_bfloat16 g_kh[BB*HH*SS*DD], g_kl[BB*HH*SS*DD];
// bf16 hi/lo operand arrays for bf16 mma GEMMs
__device__ __align__(16) __nv_bfloat16 g_xh[MM*EE],   g_xl[MM*EE];     // x
__device__ __align__(16) __nv_bfloat16 g_wh[3*EE*EE], g_wl[3*EE*EE];   // qkv_w
__device__ __align__(16) __nv_bfloat16 g_owh[EE*EE],  g_owl[EE*EE];    // out_w
__device__ __align__(16) __nv_bfloat16 g_aoh[MM*EE],  g_aol[MM*EE];    // attn out [B,S,H*D]

// ---------------------------------------------------------------------------
// helpers
// ---------------------------------------------------------------------------
__device__ __forceinline__ float uaf(unsigned u) { return __uint_as_float(u); }

__device__ __forceinline__ void mma_bf16(float c[4], const unsigned a[4], const unsigned b[2]) {
    asm volatile(
        "mma.sync.aligned.m16n8k16.row.col.f32.bf16.bf16.f32 "
        "{%0,%1,%2,%3}, {%4,%5,%6,%7}, {%8,%9}, {%0,%1,%2,%3};"
        : "+f"(c[0]), "+f"(c[1]), "+f"(c[2]), "+f"(c[3])
        : "r"(a[0]), "r"(a[1]), "r"(a[2]), "r"(a[3]),
          "r"(b[0]), "r"(b[1]));
}

__device__ __forceinline__ void mma_f16(float c[4], const unsigned a[4], const unsigned b[2]) {
    asm volatile(
        "mma.sync.aligned.m16n8k16.row.col.f32.f16.f16.f32 "
        "{%0,%1,%2,%3}, {%4,%5,%6,%7}, {%8,%9}, {%0,%1,%2,%3};"
        : "+f"(c[0]), "+f"(c[1]), "+f"(c[2]), "+f"(c[3])
        : "r"(a[0]), "r"(a[1]), "r"(a[2]), "r"(a[3]),
          "r"(b[0]), "r"(b[1]));
}

__device__ __forceinline__ void ldsm4(unsigned &r0, unsigned &r1, unsigned &r2,
                                      unsigned &r3, unsigned addr) {
    asm volatile("ldmatrix.sync.aligned.m8n8.x4.shared.b16 {%0,%1,%2,%3}, [%4];"
                 : "=r"(r0), "=r"(r1), "=r"(r2), "=r"(r3) : "r"(addr));
}

__device__ __forceinline__ void cp16(unsigned dst, const void* src) {
    asm volatile("cp.async.cg.shared.global [%0], [%1], 16;\n" :: "r"(dst), "l"(src));
}
__device__ __forceinline__ void cp_commit() {
    asm volatile("cp.async.commit_group;\n");
}
__device__ __forceinline__ void cp_wait1() {
    asm volatile("cp.async.wait_group 1;\n");
}
__device__ __forceinline__ void cp_wait0() {
    asm volatile("cp.async.wait_group 0;\n");
}

__device__ __forceinline__ unsigned bf2u(__nv_bfloat162 v) {
    return *(unsigned*)&v;
}
__device__ __forceinline__ unsigned h2u(__half2 v) {
    return *(unsigned*)&v;
}

__device__ __forceinline__ void split_one4(const float* __restrict__ src,
                                           __nv_bfloat16* __restrict__ h,
                                           __nv_bfloat16* __restrict__ l,
                                           size_t i) {
    float4 v = ((const float4*)src)[i];
    __nv_bfloat162 h01 = __floats2bfloat162_rn(v.x, v.y);
    __nv_bfloat162 h23 = __floats2bfloat162_rn(v.z, v.w);
    *(__nv_bfloat162*)(h + 4 * i)     = h01;
    *(__nv_bfloat162*)(h + 4 * i + 2) = h23;
    __nv_bfloat162 l01 = __floats2bfloat162_rn(
        v.x - __bfloat162float(h01.x), v.y - __bfloat162float(h01.y));
    __nv_bfloat162 l23 = __floats2bfloat162_rn(
        v.z - __bfloat162float(h23.x), v.w - __bfloat162float(h23.y));
    *(__nv_bfloat162*)(l + 4 * i)     = l01;
    *(__nv_bfloat162*)(l + 4 * i + 2) = l23;
}

// ---------------------------------------------------------------------------
// prep: head mask (block 0) + all three bf16 hi/lo splits in ONE launch
// ---------------------------------------------------------------------------
#define NX4 (MM*EE/4)
#define NW4 (3*EE*EE/4)
#define NO4 (EE*EE/4)
#define PREP_BLOCKS ((NX4 + NW4 + NO4) / 256)   // 8192

__global__ void prep_kernel(const float* __restrict__ x,
                            const float* __restrict__ w,
                            const float* __restrict__ ow,
                            const float* __restrict__ gates,
                            const float* __restrict__ imp,
                            const float* __restrict__ thr) {
    if (blockIdx.x == 0 && threadIdx.x < HH) {
        const int h = threadIdx.x;
        const float z  = gates[h] * imp[h];
        const float gs = 1.0f / (1.0f + expf(-z));
        g_active[h] = (gs > thr[0]) ? 1.0f : 0.0f;
    }
    const int i = blockIdx.x * 256 + threadIdx.x;
    if (i < NX4) {
        split_one4(x, g_xh, g_xl, i);
    } else if (i < NX4 + NW4) {
        split_one4(w, g_wh, g_wl, i - NX4);
    } else {
        split_one4(ow, g_owh, g_owl, i - NX4 - NW4);
    }
}

// ---------------------------------------------------------------------------
// vmean: grid (BB*HH, 8); block = 8 warps, warp w owns d-row dg*8+w.
// Coalesced scan of the d-major VPt row; warp-reduce; writes g_vmean.
// ---------------------------------------------------------------------------
__global__ void vmean_kernel() {
    const int bh = blockIdx.x;
    if (g_active[bh & (HH - 1)] == 0.0f) return;
    const int d    = blockIdx.y * 8 + (threadIdx.x >> 5);
    const int lane = threadIdx.x & 31;
    const __half2* row = (const __half2*)g_vpt + ((size_t)bh * DD + d) * (SS / 2);
    float sum = 0.f;
    for (int s2 = lane; s2 < SS / 2; s2 += 32) {
        float2 f = __half22float2(row[s2]);
        sum += f.x + f.y;
    }
#pragma unroll
    for (int o = 16; o > 0; o >>= 1)
        sum += __shfl_xor_sync(0xffffffffu, sum, o);
    if (lane == 0)
        g_vmean[bh * DD + d] = sum * (1.0f / SS);
}

// ---------------------------------------------------------------------------
// 3-term bf16-split GEMM on mma.sync.m16n8k16, ldmatrix frags, cp.async staging.
// MODE 0: qkv scatter epilogue (V transposed d-major fp16). MODE 1: row-major.
// ---------------------------------------------------------------------------
#define GSTR  20
#define GARR  (128 * GSTR)
#define GSTG  (4 * GARR)
#define SMEM_GEMM (2 * GSTG * 4)    // 81920 B

template <int MODE>
__global__ void __launch_bounds__(256, 2) gemm_bf16_kernel(
    const __nv_bfloat16* __restrict__ Ahg, const __nv_bfloat16* __restrict__ Alg,
    const __nv_bfloat16* __restrict__ Bhg, const __nv_bfloat16* __restrict__ Blg,
    const float* __restrict__ bias, float* __restrict__ Y) {
    extern __shared__ unsigned gsm[];

    const int m0 = blockIdx.y * 128;
    const int n0 = blockIdx.x * 128;

    if (MODE == 0) {
        const int hA = (n0 & 1023) >> 6;
        if (g_active[hA] == 0.0f && g_active[hA + 1] == 0.0f) return;
    }

    const int tid  = threadIdx.x;
    const int lane = tid & 31;
    const int warp = tid >> 5;
    const int wm = (warp >> 2) * 64;
    const int wn = (warp & 3) * 32;
    const int grp = lane >> 2;
    const int tig = lane & 3;

    const int grow = tid >> 1;
    const int gkw  = (tid & 1) * 8;
    const __nv_bfloat16* Aph = Ahg + (size_t)(m0 + grow) * EE + gkw * 2;
    const __nv_bfloat16* Apl = Alg + (size_t)(m0 + grow) * EE + gkw * 2;
    const __nv_bfloat16* Bph = Bhg + (size_t)(n0 + grow) * EE + gkw * 2;
    const __nv_bfloat16* Bpl = Blg + (size_t)(n0 + grow) * EE + gkw * 2;

    const unsigned gb = (unsigned)__cvta_generic_to_shared(gsm);
    const int seg = lane >> 3, lr8 = lane & 7;
    const int arow = wm + (seg & 1) * 8 + lr8;
    const int acol = (seg >> 1) * 4;
    const int brow = wn + (seg >> 1) * 8 + lr8;
    const int bcol = (seg & 1) * 4;

    float acc[4][4][4];
#pragma unroll
    for (int i = 0; i < 4; i++)
#pragma unroll
        for (int j = 0; j < 4; j++)
#pragma unroll
            for (int r = 0; r < 4; r++) acc[i][j][r] = 0.f;

    auto issue_tile = [&](int kt, int st) {
        const size_t o = (size_t)kt * 32;
        const unsigned base = gb + (st * GSTG + grow * GSTR + gkw) * 4;
        cp16(base,                     Aph + o);
        cp16(base + 16,                Aph + o + 8);
        cp16(base + GARR * 4,          Apl + o);
        cp16(base + GARR * 4 + 16,     Apl + o + 8);
        cp16(base + 2 * GARR * 4,      Bph + o);
        cp16(base + 2 * GARR * 4 + 16, Bph + o + 8);
        cp16(base + 3 * GARR * 4,      Bpl + o);
        cp16(base + 3 * GARR * 4 + 16, Bpl + o + 8);
    };

    issue_tile(0, 0);
    cp_commit();

    const int NT = EE / 32;
    for (int kt = 0; kt < NT; kt++) {
        cp_wait0();
        __syncthreads();

        if (kt + 1 < NT) issue_tile(kt + 1, (kt + 1) & 1);
        cp_commit();

        const unsigned stb = gb + ((kt & 1) * GSTG) * 4;

#pragma unroll
        for (int ks = 0; ks < 2; ks++) {
            const int kw = ks * 8;
            unsigned bh[4][2], bl[4][2];
#pragma unroll
            for (int np = 0; np < 2; np++) {
                const unsigned addr =
                    stb + (2 * GARR + (brow + np * 16) * GSTR + kw + bcol) * 4;
                ldsm4(bh[2*np][0], bh[2*np][1], bh[2*np+1][0], bh[2*np+1][1], addr);
                ldsm4(bl[2*np][0], bl[2*np][1], bl[2*np+1][0], bl[2*np+1][1],
                      addr + GARR * 4);
            }
#pragma unroll
            for (int mi = 0; mi < 4; mi++) {
                unsigned ah[4], al[4];
                const unsigned addr =
                    stb + ((arow + mi * 16) * GSTR + kw + acol) * 4;
                ldsm4(ah[0], ah[1], ah[2], ah[3], addr);
                ldsm4(al[0], al[1], al[2], al[3], addr + GARR * 4);
#pragma unroll
                for (int ni = 0; ni < 4; ni++) {
                    mma_bf16(acc[mi][ni], ah, bh[ni]);
                    mma_bf16(acc[mi][ni], al, bh[ni]);
                    mma_bf16(acc[mi][ni], ah, bl[ni]);
                }
            }
        }
    }

    // epilogue
#pragma unroll
    for (int mi = 0; mi < 4; mi++) {
        const int rbase = m0 + wm + mi * 16 + grp;
#pragma unroll
        for (int ni = 0; ni < 4; ni++) {
            const int j = n0 + wn + ni * 8 + 2 * tig;
            const float b0 = bias[j], b1 = bias[j + 1];
#pragma unroll
            for (int rh = 0; rh < 2; rh++) {
                const int m = rbase + rh * 8;
                const float v0 = acc[mi][ni][rh * 2 + 0] + b0;
                const float v1 = acc[mi][ni][rh * 2 + 1] + b1;
                if (MODE == 1) {
                    float2 o; o.x = v0; o.y = v1;
                    *(float2*)(Y + (size_t)m * EE + j) = o;
                } else {
                    const int cc  = j >> 10;
                    const int rem = j & 1023;
                    const int h = rem >> 6, d = rem & 63;
                    const int bI = m >> 11;
                    const int s  = m & (SS - 1);
                    const size_t off = (((size_t)(bI * HH + h)) * SS + s) * DD + d;
                    if (cc == 0) {
                        float2 o; o.x = v0; o.y = v1;       // q raw
                        *(float2*)(g_q + off) = o;
                    } else if (cc == 1) {
                        __nv_bfloat162 kh = __floats2bfloat162_rn(v0, v1);
                        __nv_bfloat162 kl = __floats2bfloat162_rn(
                            v0 - __bfloat162float(kh.x), v1 - __bfloat162float(kh.y));
                        *(__nv_bfloat162*)(g_kh + off) = kh;
                        *(__nv_bfloat162*)(g_kl + off) = kl;
                    } else {
                        // v masked, fp16, transposed d-major s-pair layout:
                        // half at [bh][d][s>>1] slot (s&1); d-row stride = SS halves
                        const float am = g_active[h];
                        __half* base = g_vpt
                            + (((size_t)(bI * HH + h) * DD + d) * (SS / 2)
                               + (s >> 1)) * 2 + (s & 1);
                        base[0]  = __float2half_rn(v0 * am);
                        base[SS] = __float2half_rn(v1 * am);   // d+1 row
                    }
                }
            }
        }
    }
}

// ---------------------------------------------------------------------------
// Tensor-core flash attention, v9:
//  - QK bf16 3-term (ldmatrix), scores in log2 domain (log2e folded into Q)
//  - PV fp16: A-frag = own packed P regs; B-frag via ldmatrix on transposed VPt
//  - 3-stage cp.async ring, 1 barrier/tile, 2 CTAs/SM
// ---------------------------------------------------------------------------
#define KSTRW  36
#define TKHW   (64 * KSTRW)
#define VPTSTR 36                       // words per VPt d-row (32 + 4 pad)
#define TVPTW  (64 * VPTSTR)            // words per VPt tile (64 d-rows)
#define BUFW   (2 * TKHW + TVPTW)       // 6912 words
#define NSTG   3
#define SMEM_ATTN ((NSTG * BUFW + 64) * 4)   // 83200 B

__global__ void __launch_bounds__(256, 2) attn_tc_kernel() {
    extern __shared__ float sh[];

    const int tid  = threadIdx.x;
    const int lane = tid & 31;
    const int warp = tid >> 5;
    const int g8   = lane >> 2;
    const int tig  = lane & 3;
    const int wr   = warp * 16;

    const int b = blockIdx.z, h = blockIdx.y;
    const int q0 = blockIdx.x * 128;
    const size_t bh = (size_t)(b * HH + h) * SS * DD;

    if (g_active[h] == 0.0f) {
        const uint4 z = {0u, 0u, 0u, 0u};
        for (int i = tid; i < 128 * 8; i += 256) {
            const int r = i >> 3, c = (i & 7) * 8;
            const size_t off = ((size_t)(b * SS + q0 + r) * HH + h) * DD + c;
            *(uint4*)(g_aoh + off) = z;
            *(uint4*)(g_aol + off) = z;
        }
        return;
    }

    const unsigned sbase = (unsigned)__cvta_generic_to_shared(sh);
    float* vsm = sh + NSTG * BUFW;

    if (tid < 64)
        vsm[tid] = g_vmean[(b * HH + h) * DD + tid];

    const int seg = lane >> 3, lr8 = lane & 7;
    const int krow = (seg >> 1) * 8 + lr8;
    const int kcol = (seg & 1) * 4;

    // Q bf16 hi/lo fragments of (q * log2e)  -> scores in log2 domain
    unsigned qh[4][4], ql[4][4];
#pragma unroll
    for (int ks = 0; ks < 4; ks++) {
        const int r0 = q0 + wr + g8;
        const int k0 = ks * 16 + 2 * tig;
        const float* qr0 = g_q + bh + (size_t)r0 * DD;
        const float* qr1 = g_q + bh + (size_t)(r0 + 8) * DD;
        float a0 = qr0[k0]     * LOG2E, a1 = qr0[k0 + 1] * LOG2E;
        float b0 = qr1[k0]     * LOG2E, b1 = qr1[k0 + 1] * LOG2E;
        float c0 = qr0[k0 + 8] * LOG2E, c1 = qr0[k0 + 9] * LOG2E;
        float d0 = qr1[k0 + 8] * LOG2E, d1 = qr1[k0 + 9] * LOG2E;
        __nv_bfloat162 ha = __floats2bfloat162_rn(a0, a1);
        __nv_bfloat162 hb = __floats2bfloat162_rn(b0, b1);
        __nv_bfloat162 hc = __floats2bfloat162_rn(c0, c1);
        __nv_bfloat162 hd = __floats2bfloat162_rn(d0, d1);
        qh[ks][0] = bf2u(ha); qh[ks][1] = bf2u(hb);
        qh[ks][2] = bf2u(hc); qh[ks][3] = bf2u(hd);
        ql[ks][0] = bf2u(__floats2bfloat162_rn(a0 - __bfloat162float(ha.x),
                                               a1 - __bfloat162float(ha.y)));
        ql[ks][1] = bf2u(__floats2bfloat162_rn(b0 - __bfloat162float(hb.x),
                                               b1 - __bfloat162float(hb.y)));
        ql[ks][2] = bf2u(__floats2bfloat162_rn(c0 - __bfloat162float(hc.x),
                                               c1 - __bfloat162float(hc.y)));
        ql[ks][3] = bf2u(__floats2bfloat162_rn(d0 - __bfloat162float(hd.x),
                                               d1 - __bfloat162float(hd.y)));
    }

    float o[8][4];
#pragma unroll
    for (int i = 0; i < 8; i++)
#pragma unroll
        for (int j = 0; j < 4; j++) o[i][j] = 0.f;
    float m0 = -1e30f, m1 = -1e30f, l0 = 0.f, l1 = 0.f;

    // VPt word base for this (b,h): d-rows of SS/2 words
    const unsigned* vptw = (const unsigned*)g_vpt + (size_t)(b * HH + h) * DD * (SS / 2);

    auto issue_tile = [&](int kvt, int st) {
        const int row = tid >> 2;       // 0..63
        const int t4  = tid & 3;
        // K tiles (row = s within tile)
        const __nv_bfloat16* khp = g_kh + bh + (size_t)(kvt * 64 + row) * DD + t4 * 16;
        const __nv_bfloat16* klp = g_kl + bh + (size_t)(kvt * 64 + row) * DD + t4 * 16;
        const unsigned khd = sbase + (st * BUFW + row * KSTRW + t4 * 8) * 4;
        const unsigned kld = khd + TKHW * 4;
        cp16(khd,      khp);
        cp16(khd + 16, khp + 8);
        cp16(kld,      klp);
        cp16(kld + 16, klp + 8);
        // VPt tile (row = d), 32 words per row for this kv tile
        const int qw = t4 * 8;
        const unsigned* vg = vptw + (size_t)row * (SS / 2) + kvt * 32 + qw;
        const unsigned vd = sbase + (st * BUFW + 2 * TKHW + row * VPTSTR + qw) * 4;
        cp16(vd,      vg);
        cp16(vd + 16, vg + 4);
    };

    issue_tile(0, 0); cp_commit();
    issue_tile(1, 1); cp_commit();

    const int NTILE = SS / 64;
    int stage = 0;
    for (int t = 0; t < NTILE; t++) {
        cp_wait1();
        __syncthreads();

        if (t + 2 < NTILE) {
            int st2 = stage + 2; if (st2 >= NSTG) st2 -= NSTG;
            issue_tile(t + 2, st2);
        }
        cp_commit();

        const unsigned stb = sbase + (stage * BUFW) * 4;
        const unsigned vtb = stb + (2 * TKHW) * 4;

        // ---- QK: bf16 3-term, ldmatrix K fragments (log2 domain) ----
        float c[8][4];
#pragma unroll
        for (int i = 0; i < 8; i++)
#pragma unroll
            for (int j = 0; j < 4; j++) c[i][j] = 0.f;
#pragma unroll
        for (int ks = 0; ks < 4; ks++) {
            const int kw = ks * 8;
#pragma unroll
            for (int ntp = 0; ntp < 4; ntp++) {
                unsigned kh0[2], kh1[2], kl0[2], kl1[2];
                const unsigned addr =
                    stb + ((krow + ntp * 16) * KSTRW + kw + kcol) * 4;
                ldsm4(kh0[0], kh0[1], kh1[0], kh1[1], addr);
                ldsm4(kl0[0], kl0[1], kl1[0], kl1[1], addr + TKHW * 4);
                mma_bf16(c[2*ntp],     qh[ks], kh0);
                mma_bf16(c[2*ntp],     ql[ks], kh0);
                mma_bf16(c[2*ntp],     qh[ks], kl0);
                mma_bf16(c[2*ntp + 1], qh[ks], kh1);
                mma_bf16(c[2*ntp + 1], ql[ks], kh1);
                mma_bf16(c[2*ntp + 1], qh[ks], kl1);
            }
        }

        // ---- online softmax in log2 domain; P packed to fp16 pairs ----
        float mx0 = c[0][0], mx1 = c[0][2];
#pragma unroll
        for (int nt = 0; nt < 8; nt++) {
            mx0 = fmaxf(mx0, fmaxf(c[nt][0], c[nt][1]));
            mx1 = fmaxf(mx1, fmaxf(c[nt][2], c[nt][3]));
        }
        mx0 = fmaxf(mx0, __shfl_xor_sync(0xffffffffu, mx0, 1));
        mx0 = fmaxf(mx0, __shfl_xor_sync(0xffffffffu, mx0, 2));
        mx1 = fmaxf(mx1, __shfl_xor_sync(0xffffffffu, mx1, 1));
        mx1 = fmaxf(mx1, __shfl_xor_sync(0xffffffffu, mx1, 2));
        const float mn0 = fmaxf(m0, mx0);
        const float mn1 = fmaxf(m1, mx1);
        const float sc0 = exp2f(m0 - mn0);
        const float sc1 = exp2f(m1 - mn1);
        m0 = mn0; m1 = mn1;
#pragma unroll
        for (int dt = 0; dt < 8; dt++) {
            o[dt][0] *= sc0; o[dt][1] *= sc0;
            o[dt][2] *= sc1; o[dt][3] *= sc1;
        }
        unsigned hp[8][2];
        float s0 = 0.f, s1 = 0.f;
#pragma unroll
        for (int nt = 0; nt < 8; nt++) {
            const float p00 = exp2f(c[nt][0] - m0);
            const float p01 = exp2f(c[nt][1] - m0);
            const float p10 = exp2f(c[nt][2] - m1);
            const float p11 = exp2f(c[nt][3] - m1);
            __half2 w0 = __floats2half2_rn(p00, p01);
            __half2 w1 = __floats2half2_rn(p10, p11);
            hp[nt][0] = h2u(w0);
            hp[nt][1] = h2u(w1);
            float2 f0 = __half22float2(w0);
            float2 f1 = __half22float2(w1);
            s0 += f0.x + f0.y;
            s1 += f1.x + f1.y;
        }
        s0 += __shfl_xor_sync(0xffffffffu, s0, 1);
        s0 += __shfl_xor_sync(0xffffffffu, s0, 2);
        s1 += __shfl_xor_sync(0xffffffffu, s1, 1);
        s1 += __shfl_xor_sync(0xffffffffu, s1, 2);
        l0 = l0 * sc0 + s0;
        l1 = l1 * sc1 + s1;

        // ---- PV: fp16 m16n8k16; B-frags via ldmatrix on transposed VPt ----
        // matrices = dt values: lane l addr -> VPt row dtp*32 + l, word col 8ks (+4)
#pragma unroll
        for (int ks = 0; ks < 4; ks++) {
            unsigned aa[4] = {hp[2*ks][0], hp[2*ks][1],
                              hp[2*ks + 1][0], hp[2*ks + 1][1]};
#pragma unroll
            for (int dtp = 0; dtp < 2; dtp++) {
                const unsigned a0 = vtb + ((dtp * 32 + lane) * VPTSTR + 8 * ks) * 4;
                unsigned b00, b01, b02, b03, b10, b11, b12, b13;
                ldsm4(b00, b01, b02, b03, a0);
                ldsm4(b10, b11, b12, b13, a0 + 16);
                unsigned bb0[2] = {b00, b10};
                unsigned bb1[2] = {b01, b11};
                unsigned bb2[2] = {b02, b12};
                unsigned bb3[2] = {b03, b13};
                mma_f16(o[dtp * 4 + 0], aa, bb0);
                mma_f16(o[dtp * 4 + 1], aa, bb1);
                mma_f16(o[dtp * 4 + 2], aa, bb2);
                mma_f16(o[dtp * 4 + 3], aa, bb3);
            }
        }

        stage = (stage + 1 == NSTG) ? 0 : stage + 1;
    }

    // epilogue: normalize, add vmean (from smem), emit bf16 hi/lo
    const float inv0 = 1.0f / l0;
    const float inv1 = 1.0f / l1;
    const int r0 = q0 + wr + g8;
    const size_t ob0 = ((size_t)(b * SS + r0) * HH + h) * DD;
    const size_t ob1 = ((size_t)(b * SS + r0 + 8) * HH + h) * DD;
#pragma unroll
    for (int dt = 0; dt < 8; dt++) {
        const int col = dt * 8 + 2 * tig;
        const float v0 = vsm[col], v1 = vsm[col + 1];
        const float f00 = o[dt][0] * inv0 + v0, f01 = o[dt][1] * inv0 + v1;
        const float f10 = o[dt][2] * inv1 + v0, f11 = o[dt][3] * inv1 + v1;
        __nv_bfloat162 h0 = __floats2bfloat162_rn(f00, f01);
        __nv_bfloat162 h1 = __floats2bfloat162_rn(f10, f11);
        __nv_bfloat162 lo0 = __floats2bfloat162_rn(
            f00 - __bfloat162float(h0.x), f01 - __bfloat162float(h0.y));
        __nv_bfloat162 lo1 = __floats2bfloat162_rn(
            f10 - __bfloat162float(h1.x), f11 - __bfloat162float(h1.y));
        *(__nv_bfloat162*)(g_aoh + ob0 + col) = h0;
        *(__nv_bfloat162*)(g_aol + ob0 + col) = lo0;
        *(__nv_bfloat162*)(g_aoh + ob1 + col) = h1;
        *(__nv_bfloat162*)(g_aol + ob1 + col) = lo1;
    }
}

// ---------------------------------------------------------------------------
extern "C" void kernel_launch(void* const* d_in, const int* in_sizes, int n_in,
                              void* d_out, int out_size) {
    const float* x      = (const float*)d_in[0];
    const float* qkv_w  = (const float*)d_in[1];
    const float* qkv_b  = (const float*)d_in[2];
    const float* out_w  = (const float*)d_in[3];
    const float* out_b  = (const float*)d_in[4];
    const float* gates  = (const float*)d_in[5];
    const float* imp    = (const float*)d_in[6];
    const float* thr    = (const float*)d_in[7];
    float* out = (float*)d_out;

    static bool attr_set = false;
    if (!attr_set) {
        cudaFuncSetAttribute(attn_tc_kernel,
                             cudaFuncAttributeMaxDynamicSharedMemorySize, SMEM_ATTN);
        cudaFuncSetAttribute(gemm_bf16_kernel<0>,
                             cudaFuncAttributeMaxDynamicSharedMemorySize, SMEM_GEMM);
        cudaFuncSetAttribute(gemm_bf16_kernel<1>,
                             cudaFuncAttributeMaxDynamicSharedMemorySize, SMEM_GEMM);
        attr_set = true;
    }

    __nv_bfloat16 *xh, *xl, *wh, *wl, *owh, *owl, *aoh, *aol;
    cudaGetSymbolAddress((void**)&xh,  g_xh);
    cudaGetSymbolAddress((void**)&xl,  g_xl);
    cudaGetSymbolAddress((void**)&wh,  g_wh);
    cudaGetSymbolAddress((void**)&wl,  g_wl);
    cudaGetSymbolAddress((void**)&owh, g_owh);
    cudaGetSymbolAddress((void**)&owl, g_owl);
    cudaGetSymbolAddress((void**)&aoh, g_aoh);
    cudaGetSymbolAddress((void**)&aol, g_aol);

    // fused mask + splits
    prep_kernel<<<PREP_BLOCKS, 256>>>(x, qkv_w, out_w, gates, imp, thr);

    // QKV projection
    {
        dim3 g(3 * EE / 128, MM / 128);      // 24 x 32
        gemm_bf16_kernel<0><<<g, 256, SMEM_GEMM>>>(xh, xl, wh, wl, qkv_b, nullptr);
    }

    // vmean (coalesced d-row scan, deterministic)
    {
        dim3 g(BB * HH, 8);
        vmean_kernel<<<g, 256>>>();
    }

    // Attention (bf16 QK 3-term + fp16 PV via ldmatrix, exp2 softmax)
    {
        dim3 g(SS / 128, HH, BB);            // 16 x 16 x 2
        attn_tc_kernel<<<g, 256, SMEM_ATTN>>>();
    }

    // Output projection
    {
        dim3 g(EE / 128, MM / 128);          // 8 x 32
        gemm_bf16_kernel<1><<<g, 256, SMEM_GEMM>>>(aoh, aol, owh, owl, out_b, out);
    }
}